// round 1
// baseline (speedup 1.0000x reference)
#include <cuda_runtime.h>
#include <math.h>

#define S  2048
#define H  1024
#define NH 16
#define DH 64
#define FF 4096
#define NLAYERS 6

#define SZ_SH (S*H)   // 2,097,152 == NH*S*DH too

// ---------------- scratch (no allocations allowed) ----------------
__device__ float g_x[SZ_SH];
__device__ float g_att[SZ_SH];
__device__ float g_tmp[SZ_SH];
__device__ float g_res[SZ_SH];
__device__ float g_xf[SZ_SH];
__device__ float g_q[SZ_SH];
__device__ float g_k[SZ_SH];
__device__ float g_v[SZ_SH];
__device__ float g_suf[SZ_SH];
__device__ float g_m[NH*DH*DH];
__device__ float g_h1[S*FF];

__device__ __forceinline__ float gelu_exact(float x) {
    return 0.5f * x * (1.0f + erff(x * 0.70710678118654752f));
}

// ---------------- embedding: x = emb[tok] + pos ----------------
__global__ void embed_kernel(const int* __restrict__ tok,
                             const float* __restrict__ emb,
                             const float* __restrict__ pos,
                             float* __restrict__ x) {
    int i = blockIdx.x * 256 + threadIdx.x;      // 0 .. S*H-1
    int s = i >> 10;
    int h = i & 1023;
    x[i] = emb[(long)tok[s] * H + h] + pos[i];
}

// ---------------- generic SGEMM: C = act(A@B + bias) ----------------
// A [M,K] rm, B [K,N] rm, C [M,N]. M multiple of 128; K multiple of 8.
// N guarded (LM head N=50257). BM=BN=128, BK=8, 256 thr, 8x8 micro.
template<int ACT>
__global__ __launch_bounds__(256)
void sgemm128(const float* __restrict__ A, const float* __restrict__ B,
              const float* __restrict__ bias, float* __restrict__ C,
              int N, int K) {
    const int bm = blockIdx.y * 128;
    const int bn = blockIdx.x * 128;
    __shared__ float As[8][128];
    __shared__ float Bs[8][128];
    const int tid  = threadIdx.x;
    const int rowA = tid >> 1;
    const int colA = (tid & 1) * 4;
    const int rowB = tid >> 5;
    const int colB = (tid & 31) * 4;
    const int tr   = tid >> 4;
    const int tc   = tid & 15;

    float acc[8][8] = {};
    const float* Ap = A + (long)(bm + rowA) * K;

    for (int k0 = 0; k0 < K; k0 += 8) {
        float4 a4 = *(const float4*)(Ap + k0 + colA);
        As[colA + 0][rowA] = a4.x;
        As[colA + 1][rowA] = a4.y;
        As[colA + 2][rowA] = a4.z;
        As[colA + 3][rowA] = a4.w;
        #pragma unroll
        for (int i = 0; i < 4; i++) {
            int c = bn + colB + i;
            Bs[rowB][colB + i] = (c < N) ? B[(long)(k0 + rowB) * N + c] : 0.f;
        }
        __syncthreads();
        #pragma unroll
        for (int kk = 0; kk < 8; kk++) {
            float4 ax = *(const float4*)&As[kk][tr * 8];
            float4 ay = *(const float4*)&As[kk][tr * 8 + 4];
            float4 bx = *(const float4*)&Bs[kk][tc * 8];
            float4 by = *(const float4*)&Bs[kk][tc * 8 + 4];
            float ar[8] = {ax.x, ax.y, ax.z, ax.w, ay.x, ay.y, ay.z, ay.w};
            float br[8] = {bx.x, bx.y, bx.z, bx.w, by.x, by.y, by.z, by.w};
            #pragma unroll
            for (int i = 0; i < 8; i++)
                #pragma unroll
                for (int j = 0; j < 8; j++)
                    acc[i][j] = fmaf(ar[i], br[j], acc[i][j]);
        }
        __syncthreads();
    }
    #pragma unroll
    for (int i = 0; i < 8; i++) {
        long r = bm + tr * 8 + i;
        #pragma unroll
        for (int j = 0; j < 8; j++) {
            int c = bn + tc * 8 + j;
            if (c < N) {
                float val = acc[i][j] + bias[c];
                if (ACT == 1) val = gelu_exact(val);
                C[r * N + c] = val;
            }
        }
    }
}

// ---------------- per-head QKV GEMM ----------------
// A [S,H], W layer slice [NH,H,DH], out [NH,S,DH].  BM=128,BN=64,BK=8.
__global__ __launch_bounds__(256)
void qkv_gemm(const float* __restrict__ A, const float* __restrict__ W,
              float* __restrict__ out) {
    const int head = blockIdx.y;
    const int bm   = blockIdx.x * 128;
    const float* B = W + (long)head * H * DH;
    float* C       = out + (long)head * S * DH;
    __shared__ float As[8][128];
    __shared__ float Bs[8][64];
    const int tid  = threadIdx.x;
    const int rowA = tid >> 1;
    const int colA = (tid & 1) * 4;
    const int rowB = tid >> 5;
    const int colB = (tid & 31) * 2;
    const int tr   = tid >> 4;
    const int tc   = tid & 15;

    float acc[8][4] = {};
    const float* Ap = A + (long)(bm + rowA) * H;

    for (int k0 = 0; k0 < H; k0 += 8) {
        float4 a4 = *(const float4*)(Ap + k0 + colA);
        As[colA + 0][rowA] = a4.x;
        As[colA + 1][rowA] = a4.y;
        As[colA + 2][rowA] = a4.z;
        As[colA + 3][rowA] = a4.w;
        float2 b2 = *(const float2*)(B + (long)(k0 + rowB) * DH + colB);
        Bs[rowB][colB]     = b2.x;
        Bs[rowB][colB + 1] = b2.y;
        __syncthreads();
        #pragma unroll
        for (int kk = 0; kk < 8; kk++) {
            float4 ax = *(const float4*)&As[kk][tr * 8];
            float4 ay = *(const float4*)&As[kk][tr * 8 + 4];
            float4 bx = *(const float4*)&Bs[kk][tc * 4];
            float ar[8] = {ax.x, ax.y, ax.z, ax.w, ay.x, ay.y, ay.z, ay.w};
            float br[4] = {bx.x, bx.y, bx.z, bx.w};
            #pragma unroll
            for (int i = 0; i < 8; i++)
                #pragma unroll
                for (int j = 0; j < 4; j++)
                    acc[i][j] = fmaf(ar[i], br[j], acc[i][j]);
        }
        __syncthreads();
    }
    #pragma unroll
    for (int i = 0; i < 8; i++)
        #pragma unroll
        for (int j = 0; j < 4; j++)
            C[(long)(bm + tr * 8 + i) * DH + tc * 4 + j] = acc[i][j];
}

// ---------------- M = K^T V per head (64x64, reduce over S) ----------------
__global__ __launch_bounds__(256)
void ktv_kernel(const float* __restrict__ k, const float* __restrict__ v,
                float* __restrict__ m) {
    const int head = blockIdx.x;
    __shared__ float Ks[64][65];
    __shared__ float Vs[64][65];
    const int tid = threadIdx.x;
    const int tr  = tid >> 4;
    const int tc  = tid & 15;
    float acc[4][4] = {};

    for (int t0 = 0; t0 < S; t0 += 64) {
        for (int i = tid; i < 4096; i += 256) {
            int r = i >> 6, c = i & 63;
            long idx = ((long)head * S + t0 + r) * DH + c;
            Ks[r][c] = k[idx];
            Vs[r][c] = v[idx];
        }
        __syncthreads();
        #pragma unroll 4
        for (int t = 0; t < 64; t++) {
            float a[4], b[4];
            #pragma unroll
            for (int i = 0; i < 4; i++) a[i] = Ks[t][tr * 4 + i];
            #pragma unroll
            for (int j = 0; j < 4; j++) b[j] = Vs[t][tc * 4 + j];
            #pragma unroll
            for (int i = 0; i < 4; i++)
                #pragma unroll
                for (int j = 0; j < 4; j++)
                    acc[i][j] = fmaf(a[i], b[j], acc[i][j]);
        }
        __syncthreads();
    }
    #pragma unroll
    for (int i = 0; i < 4; i++)
        #pragma unroll
        for (int j = 0; j < 4; j++)
            m[(long)head * 4096 + (tr * 4 + i) * 64 + tc * 4 + j] = acc[i][j];
}

// ---------------- suffix sums of V: suf[n,s,d] = sum_{t>s} v[n,t,d] ----------------
__global__ void suffix_kernel(const float* __restrict__ v, float* __restrict__ suf) {
    const int head = blockIdx.x;
    const int d    = threadIdx.x;   // 64 threads
    float run = 0.f;
    for (int t = S - 1; t >= 0; --t) {
        long idx = ((long)head * S + t) * DH + d;
        suf[idx] = run;
        run += v[idx];
    }
}

// ---------------- attn = scale*(Q@M) - 1e9*suf, concat heads ----------------
__global__ __launch_bounds__(256)
void attn_combine(const float* __restrict__ q, const float* __restrict__ m,
                  const float* __restrict__ suf, float* __restrict__ att) {
    const int head = blockIdx.y;
    const int s0   = blockIdx.x * 64;
    __shared__ float Qs[64][65];
    __shared__ float Ms[64][65];
    const int tid = threadIdx.x;
    for (int i = tid; i < 4096; i += 256) {
        int r = i >> 6, c = i & 63;
        Qs[r][c] = q[((long)head * S + s0 + r) * DH + c];
        Ms[r][c] = m[(long)head * 4096 + i];
    }
    __syncthreads();
    const int tr = tid >> 4;
    const int tc = tid & 15;
    float acc[4][4] = {};
    #pragma unroll 4
    for (int hp = 0; hp < 64; hp++) {
        float a[4], b[4];
        #pragma unroll
        for (int i = 0; i < 4; i++) a[i] = Qs[tr * 4 + i][hp];
        #pragma unroll
        for (int j = 0; j < 4; j++) b[j] = Ms[hp][tc * 4 + j];
        #pragma unroll
        for (int i = 0; i < 4; i++)
            #pragma unroll
            for (int j = 0; j < 4; j++)
                acc[i][j] = fmaf(a[i], b[j], acc[i][j]);
    }
    #pragma unroll
    for (int i = 0; i < 4; i++) {
        int s = s0 + tr * 4 + i;
        #pragma unroll
        for (int j = 0; j < 4; j++) {
            int d = tc * 4 + j;
            att[(long)s * H + head * DH + d] =
                0.125f * acc[i][j] - 1e9f * suf[((long)head * S + s) * DH + d];
        }
    }
}

// ---------------- LayerNorm (+ optional residual add) ----------------
template<bool ADD>
__global__ __launch_bounds__(256)
void ln_kernel(const float* __restrict__ t, const float* __restrict__ xin,
               const float* __restrict__ g, const float* __restrict__ b,
               float* __restrict__ out) {
    const int row = blockIdx.x;
    const int tid = threadIdx.x;
    const float* trow = t + (long)row * H;
    __shared__ float red[256];
    __shared__ float stat[2];

    float s = 0.f;
    for (int h = tid; h < H; h += 256) s += trow[h];
    red[tid] = s; __syncthreads();
    for (int off = 128; off > 0; off >>= 1) {
        if (tid < off) red[tid] += red[tid + off];
        __syncthreads();
    }
    if (tid == 0) stat[0] = red[0] * (1.0f / H);
    __syncthreads();
    float mean = stat[0];

    float vs = 0.f;
    for (int h = tid; h < H; h += 256) { float d = trow[h] - mean; vs += d * d; }
    red[tid] = vs; __syncthreads();
    for (int off = 128; off > 0; off >>= 1) {
        if (tid < off) red[tid] += red[tid + off];
        __syncthreads();
    }
    if (tid == 0) stat[1] = rsqrtf(red[0] * (1.0f / H) + 1e-5f);
    __syncthreads();
    float rstd = stat[1];

    for (int h = tid; h < H; h += 256) {
        float val = (trow[h] - mean) * rstd * g[h] + b[h];
        if (ADD) val += xin[(long)row * H + h];
        out[(long)row * H + h] = val;
    }
}

// ---------------- launch ----------------
extern "C" void kernel_launch(void* const* d_in, const int* in_sizes, int n_in,
                              void* d_out, int out_size) {
    const int*   tokens = (const int*)  d_in[0];
    const float* emb    = (const float*)d_in[1];
    const float* pos    = (const float*)d_in[2];
    const float* Wq     = (const float*)d_in[3];
    const float* Wk     = (const float*)d_in[4];
    const float* Wv     = (const float*)d_in[5];
    const float* Wp     = (const float*)d_in[6];
    const float* bp     = (const float*)d_in[7];
    const float* W1     = (const float*)d_in[8];
    const float* b1     = (const float*)d_in[9];
    const float* W2     = (const float*)d_in[10];
    const float* b2     = (const float*)d_in[11];
    const float* ln_g   = (const float*)d_in[12];
    const float* ln_b   = (const float*)d_in[13];
    const float* Wlm    = (const float*)d_in[14];
    const float* blm    = (const float*)d_in[15];
    float* out = (float*)d_out;
    const int Vv = in_sizes[15];   // vocab size from blm (50257)

    float *x, *att, *tmp, *res, *xf, *q, *k, *v, *suf, *m, *h1;
    cudaGetSymbolAddress((void**)&x,   g_x);
    cudaGetSymbolAddress((void**)&att, g_att);
    cudaGetSymbolAddress((void**)&tmp, g_tmp);
    cudaGetSymbolAddress((void**)&res, g_res);
    cudaGetSymbolAddress((void**)&xf,  g_xf);
    cudaGetSymbolAddress((void**)&q,   g_q);
    cudaGetSymbolAddress((void**)&k,   g_k);
    cudaGetSymbolAddress((void**)&v,   g_v);
    cudaGetSymbolAddress((void**)&suf, g_suf);
    cudaGetSymbolAddress((void**)&m,   g_m);
    cudaGetSymbolAddress((void**)&h1,  g_h1);

    embed_kernel<<<(S * H) / 256, 256>>>(tokens, emb, pos, x);

    for (int l = 0; l < NLAYERS; l++) {
        const float* Wql = Wq + (long)l * NH * H * DH;
        const float* Wkl = Wk + (long)l * NH * H * DH;
        const float* Wvl = Wv + (long)l * NH * H * DH;

        qkv_gemm<<<dim3(S / 128, NH), 256>>>(x, Wql, q);
        qkv_gemm<<<dim3(S / 128, NH), 256>>>(x, Wkl, k);
        qkv_gemm<<<dim3(S / 128, NH), 256>>>(x, Wvl, v);

        ktv_kernel<<<NH, 256>>>(k, v, m);
        suffix_kernel<<<NH, 64>>>(v, suf);
        attn_combine<<<dim3(S / 64, NH), 256>>>(q, m, suf, att);

        // proj: tmp = att @ Wp[l] + bp[l]
        sgemm128<0><<<dim3(H / 128, S / 128), 256>>>(att, Wp + (long)l * H * H,
                                                     bp + (long)l * H, tmp, H, H);
        // res = x + LN(tmp)
        ln_kernel<true><<<S, 256>>>(tmp, x, ln_g, ln_b, res);

        // h1 = gelu(res @ W1[l] + b1[l])
        sgemm128<1><<<dim3(FF / 128, S / 128), 256>>>(res, W1 + (long)l * H * FF,
                                                      b1 + (long)l * FF, h1, FF, H);
        // tmp = h1 @ W2[l] + b2[l]
        sgemm128<0><<<dim3(H / 128, S / 128), 256>>>(h1, W2 + (long)l * FF * H,
                                                     b2 + (long)l * H, tmp, H, FF);
        // x = res + LN(tmp)
        ln_kernel<true><<<S, 256>>>(tmp, res, ln_g, ln_b, x);
    }

    // final LN then LM head
    ln_kernel<false><<<S, 256>>>(x, nullptr, ln_g, ln_b, xf);
    sgemm128<0><<<dim3((Vv + 127) / 128, S / 128), 256>>>(xf, Wlm, blm, out, Vv, H);
}

// round 3
// speedup vs baseline: 2.3944x; 2.3944x over previous
#include <cuda_runtime.h>
#include <cuda_bf16.h>
#include <math.h>
#include <stdint.h>

#define S  2048
#define H  1024
#define NH 16
#define DH 64
#define FF 4096
#define NLAYERS 6
#define VPAD 50432     // 50257 padded to multiple of 128

#define SZ_SH (S*H)

// ---------------- device scratch (zero-initialized at module load) ----------------
__device__ __align__(16) float g_x[SZ_SH];
__device__ __align__(16) float g_att[SZ_SH];
__device__ __align__(16) float g_tmp[SZ_SH];
__device__ __align__(16) float g_res[SZ_SH];
__device__ __align__(16) float g_xf[SZ_SH];
__device__ __align__(16) float g_q[SZ_SH];
__device__ __align__(16) float g_k[SZ_SH];
__device__ __align__(16) float g_v[SZ_SH];
__device__ __align__(16) float g_suf[SZ_SH];
__device__ __align__(16) float g_m[NH*DH*DH];
__device__ __align__(16) float g_h1[S*FF];
__device__ __align__(16) float g_part[16*1024];
__device__ __align__(16) float g_zb[8192];          // zero bias (never written)

// activation hi/lo (max 2048x4096)
__device__ __align__(128) __nv_bfloat16 g_ahi[S*FF];
__device__ __align__(128) __nv_bfloat16 g_alo[S*FF];

// weight hi/lo, K-major transposed [N,K]
__device__ __align__(128) __nv_bfloat16 g_btq_hi[NLAYERS*H*H];
__device__ __align__(128) __nv_bfloat16 g_btq_lo[NLAYERS*H*H];
__device__ __align__(128) __nv_bfloat16 g_btk_hi[NLAYERS*H*H];
__device__ __align__(128) __nv_bfloat16 g_btk_lo[NLAYERS*H*H];
__device__ __align__(128) __nv_bfloat16 g_btv_hi[NLAYERS*H*H];
__device__ __align__(128) __nv_bfloat16 g_btv_lo[NLAYERS*H*H];
__device__ __align__(128) __nv_bfloat16 g_btp_hi[NLAYERS*H*H];
__device__ __align__(128) __nv_bfloat16 g_btp_lo[NLAYERS*H*H];
__device__ __align__(128) __nv_bfloat16 g_bt1_hi[NLAYERS*H*FF];
__device__ __align__(128) __nv_bfloat16 g_bt1_lo[NLAYERS*H*FF];
__device__ __align__(128) __nv_bfloat16 g_bt2_hi[NLAYERS*H*FF];
__device__ __align__(128) __nv_bfloat16 g_bt2_lo[NLAYERS*H*FF];
__device__ __align__(128) __nv_bfloat16 g_btlm_hi[VPAD*H];   // pad rows stay zero
__device__ __align__(128) __nv_bfloat16 g_btlm_lo[VPAD*H];

// ---------------- PTX helpers ----------------
__device__ __forceinline__ uint32_t smem_u32(const void* p) {
    uint32_t a;
    asm("{ .reg .u64 t; cvta.to.shared.u64 t, %1; cvt.u32.u64 %0, t; }" : "=r"(a) : "l"(p));
    return a;
}
__device__ __forceinline__ void cp16(uint32_t dst, const void* src) {
    asm volatile("cp.async.cg.shared.global [%0], [%1], 16;" :: "r"(dst), "l"(src));
}
__device__ __forceinline__ void cp_commit() { asm volatile("cp.async.commit_group;" ::: "memory"); }
template<int N> __device__ __forceinline__ void cp_wait() {
    asm volatile("cp.async.wait_group %0;" :: "n"(N) : "memory");
}
__device__ __forceinline__ void ldsm4(uint32_t& r0, uint32_t& r1, uint32_t& r2, uint32_t& r3,
                                      uint32_t addr) {
    asm volatile("ldmatrix.sync.aligned.m8n8.x4.shared.b16 {%0,%1,%2,%3}, [%4];"
                 : "=r"(r0), "=r"(r1), "=r"(r2), "=r"(r3) : "r"(addr));
}
__device__ __forceinline__ void mma16816(float& d0, float& d1, float& d2, float& d3,
                                         uint32_t a0, uint32_t a1, uint32_t a2, uint32_t a3,
                                         uint32_t b0, uint32_t b1) {
    asm volatile("mma.sync.aligned.m16n8k16.row.col.f32.bf16.bf16.f32 "
                 "{%0,%1,%2,%3}, {%4,%5,%6,%7}, {%8,%9}, {%0,%1,%2,%3};"
                 : "+f"(d0), "+f"(d1), "+f"(d2), "+f"(d3)
                 : "r"(a0), "r"(a1), "r"(a2), "r"(a3), "r"(b0), "r"(b1));
}

__device__ __forceinline__ float gelu_exact(float x) {
    return 0.5f * x * (1.0f + erff(x * 0.70710678118654752f));
}

// ---------------- HMMA GEMM: C[M,N] = act(A[M,K] @ Bt[N,K]^T + bias) ----------------
// bf16x3: hi*hi + lo*hi + hi*lo, fp32 accumulate.
// Tiles: CTA 128x128, BK=32, 8 warps (2x4) of 64x32 warp tiles.
// SMEM stage: 4 tiles (Ahi, Alo, Bhi, Blo), each 128 rows x (64B data + 16B pad).
#define ROWB 80
#define T_AHI 0
#define T_ALO 10240
#define T_BHI 20480
#define T_BLO 30720
#define STAGE_BYTES 40960
#define GEMM_SMEM (2*STAGE_BYTES)

template<int ACT>
__global__ __launch_bounds__(256)
void gemm_hmma(const __nv_bfloat16* __restrict__ Ahi, const __nv_bfloat16* __restrict__ Alo,
               const __nv_bfloat16* __restrict__ Bhi, const __nv_bfloat16* __restrict__ Blo,
               const float* __restrict__ bias, float* __restrict__ C, int N, int K) {
    extern __shared__ char smem[];
    const uint32_t sb = smem_u32(smem);
    const int tid  = threadIdx.x;
    const int wid  = tid >> 5;
    const int lane = tid & 31;
    const int wrow = wid & 1;          // 0..1 -> 64-row slab
    const int wcol = wid >> 1;         // 0..3 -> 32-col slab
    const int bm = blockIdx.y << 7;
    const long bn = (long)blockIdx.x << 7;
    const int nc = K >> 5;

    // cp.async mapping: 2 reps x (row = t>>2, chunk = t&3)
    const int r0t = tid >> 2, c0t = tid & 3;
    const int r1t = (tid + 256) >> 2, c1t = tid & 3;

    #define LOAD_STAGE(kc, s) do {                                                     \
        uint32_t st_ = sb + (s) * STAGE_BYTES;                                          \
        {                                                                               \
            size_t ga = ((size_t)(bm + r0t) * K + (kc) * 32 + c0t * 8) * 2;             \
            size_t gb = ((size_t)(bn + r0t) * K + (kc) * 32 + c0t * 8) * 2;             \
            uint32_t so = r0t * ROWB + c0t * 16;                                        \
            cp16(st_ + T_AHI + so, (const char*)Ahi + ga);                              \
            cp16(st_ + T_ALO + so, (const char*)Alo + ga);                              \
            cp16(st_ + T_BHI + so, (const char*)Bhi + gb);                              \
            cp16(st_ + T_BLO + so, (const char*)Blo + gb);                              \
        }                                                                               \
        {                                                                               \
            size_t ga = ((size_t)(bm + r1t) * K + (kc) * 32 + c1t * 8) * 2;             \
            size_t gb = ((size_t)(bn + r1t) * K + (kc) * 32 + c1t * 8) * 2;             \
            uint32_t so = r1t * ROWB + c1t * 16;                                        \
            cp16(st_ + T_AHI + so, (const char*)Ahi + ga);                              \
            cp16(st_ + T_ALO + so, (const char*)Alo + ga);                              \
            cp16(st_ + T_BHI + so, (const char*)Bhi + gb);                              \
            cp16(st_ + T_BLO + so, (const char*)Blo + gb);                              \
        }                                                                               \
        cp_commit();                                                                    \
    } while (0)

    LOAD_STAGE(0, 0);
    LOAD_STAGE(1, 1);

    // ldmatrix per-lane address offsets
    const int lane8 = lane & 7, sub = lane >> 3;
    // A 16x16 tile (mi, ks): m = wrow*64 + mi*16 + (sub&1)*8 + lane8; k = ks*16 + (sub>>1)*8
    const uint32_t aoff = (uint32_t)(wrow * 64 + (sub & 1) * 8 + lane8) * ROWB + (sub >> 1) * 16;
    // B n8 x k32 group (nj): n = wcol*32 + nj*8 + lane8; k = sub*8
    const uint32_t boff = (uint32_t)(wcol * 32 + lane8) * ROWB + sub * 16;

    float acc[4][4][4];
    #pragma unroll
    for (int i = 0; i < 4; i++)
        #pragma unroll
        for (int j = 0; j < 4; j++)
            #pragma unroll
            for (int e = 0; e < 4; e++) acc[i][j][e] = 0.f;

    for (int it = 0; it < nc; it++) {
        if (it == nc - 1) cp_wait<0>(); else cp_wait<1>();
        __syncthreads();
        const uint32_t st = sb + (it & 1) * STAGE_BYTES;

        uint32_t bh[4][4], bl[4][4];
        #pragma unroll
        for (int nj = 0; nj < 4; nj++) {
            ldsm4(bh[nj][0], bh[nj][1], bh[nj][2], bh[nj][3], st + T_BHI + boff + nj * (8 * ROWB));
            ldsm4(bl[nj][0], bl[nj][1], bl[nj][2], bl[nj][3], st + T_BLO + boff + nj * (8 * ROWB));
        }
        #pragma unroll
        for (int ks = 0; ks < 2; ks++) {
            uint32_t a[4][4];
            #pragma unroll
            for (int mi = 0; mi < 4; mi++)
                ldsm4(a[mi][0], a[mi][1], a[mi][2], a[mi][3],
                      st + T_AHI + aoff + mi * (16 * ROWB) + ks * 32);
            #pragma unroll
            for (int mi = 0; mi < 4; mi++)
                #pragma unroll
                for (int nj = 0; nj < 4; nj++)
                    mma16816(acc[mi][nj][0], acc[mi][nj][1], acc[mi][nj][2], acc[mi][nj][3],
                             a[mi][0], a[mi][1], a[mi][2], a[mi][3],
                             bh[nj][ks * 2], bh[nj][ks * 2 + 1]);
            #pragma unroll
            for (int mi = 0; mi < 4; mi++)
                #pragma unroll
                for (int nj = 0; nj < 4; nj++)
                    mma16816(acc[mi][nj][0], acc[mi][nj][1], acc[mi][nj][2], acc[mi][nj][3],
                             a[mi][0], a[mi][1], a[mi][2], a[mi][3],
                             bl[nj][ks * 2], bl[nj][ks * 2 + 1]);
            #pragma unroll
            for (int mi = 0; mi < 4; mi++)
                ldsm4(a[mi][0], a[mi][1], a[mi][2], a[mi][3],
                      st + T_ALO + aoff + mi * (16 * ROWB) + ks * 32);
            #pragma unroll
            for (int mi = 0; mi < 4; mi++)
                #pragma unroll
                for (int nj = 0; nj < 4; nj++)
                    mma16816(acc[mi][nj][0], acc[mi][nj][1], acc[mi][nj][2], acc[mi][nj][3],
                             a[mi][0], a[mi][1], a[mi][2], a[mi][3],
                             bh[nj][ks * 2], bh[nj][ks * 2 + 1]);
        }
        __syncthreads();
        if (it + 2 < nc) LOAD_STAGE(it + 2, it & 1);
    }

    // epilogue
    const int gr = lane >> 2;
    const int gc = (lane & 3) * 2;
    #pragma unroll
    for (int mi = 0; mi < 4; mi++) {
        size_t row0 = (size_t)(bm + wrow * 64 + mi * 16 + gr) * N;
        size_t row1 = row0 + (size_t)8 * N;
        #pragma unroll
        for (int nj = 0; nj < 4; nj++) {
            long c = bn + wcol * 32 + nj * 8 + gc;
            if (c < N) {
                float bsv = bias[c];
                float v0 = acc[mi][nj][0] + bsv;
                float v2 = acc[mi][nj][2] + bsv;
                if (ACT == 1) { v0 = gelu_exact(v0); v2 = gelu_exact(v2); }
                C[row0 + c] = v0;
                C[row1 + c] = v2;
            }
            if (c + 1 < N) {
                float bsv = bias[c + 1];
                float v1 = acc[mi][nj][1] + bsv;
                float v3 = acc[mi][nj][3] + bsv;
                if (ACT == 1) { v1 = gelu_exact(v1); v3 = gelu_exact(v3); }
                C[row0 + c + 1] = v1;
                C[row1 + c + 1] = v3;
            }
        }
    }
    #undef LOAD_STAGE
}

// ---------------- weight transpose + bf16 split: src[R,C] -> out[C,R] hi/lo ----------------
__global__ void transpose_split(const float* __restrict__ src,
                                __nv_bfloat16* __restrict__ hi, __nv_bfloat16* __restrict__ lo,
                                int R, int C) {
    __shared__ float t[32][33];
    size_t mb = (size_t)blockIdx.z * R * C;
    int c0 = blockIdx.x * 32, r0 = blockIdx.y * 32;
    for (int k = threadIdx.y; k < 32; k += 8) {
        int c = c0 + threadIdx.x;
        t[k][threadIdx.x] = (c < C) ? src[mb + (size_t)(r0 + k) * C + c] : 0.f;
    }
    __syncthreads();
    for (int k = threadIdx.y; k < 32; k += 8) {
        int oc = c0 + k;
        if (oc < C) {
            float v = t[threadIdx.x][k];
            __nv_bfloat16 h = __float2bfloat16(v);
            size_t o = mb + (size_t)oc * R + r0 + threadIdx.x;
            hi[o] = h;
            lo[o] = __float2bfloat16(v - __bfloat162float(h));
        }
    }
}

// ---------------- activation split ----------------
__global__ void split_act(const float* __restrict__ x, __nv_bfloat16* __restrict__ hi,
                          __nv_bfloat16* __restrict__ lo, int n) {
    int i = blockIdx.x * 256 + threadIdx.x;
    if (i < n) {
        float v = x[i];
        __nv_bfloat16 h = __float2bfloat16(v);
        hi[i] = h;
        lo[i] = __float2bfloat16(v - __bfloat162float(h));
    }
}

// ---------------- embedding ----------------
__global__ void embed_kernel(const int* __restrict__ tok, const float* __restrict__ emb,
                             const float* __restrict__ pos, float* __restrict__ x) {
    int i = blockIdx.x * 256 + threadIdx.x;
    int s = i >> 10, h = i & 1023;
    x[i] = emb[(long)tok[s] * H + h] + pos[i];
}

// ---------------- M = K^T V per head; k,v layout [S, NH*DH] ----------------
__global__ __launch_bounds__(256)
void ktv_kernel(const float* __restrict__ k, const float* __restrict__ v, float* __restrict__ m) {
    const int head = blockIdx.x;
    __shared__ float Ks[64][65];
    __shared__ float Vs[64][65];
    const int tid = threadIdx.x;
    const int tr = tid >> 4, tc = tid & 15;
    float acc[4][4] = {};
    for (int t0 = 0; t0 < S; t0 += 64) {
        for (int i = tid; i < 4096; i += 256) {
            int r = i >> 6, c = i & 63;
            size_t idx = (size_t)(t0 + r) * H + head * DH + c;
            Ks[r][c] = k[idx];
            Vs[r][c] = v[idx];
        }
        __syncthreads();
        #pragma unroll 4
        for (int t = 0; t < 64; t++) {
            float a[4], b[4];
            #pragma unroll
            for (int i = 0; i < 4; i++) a[i] = Ks[t][tr * 4 + i];
            #pragma unroll
            for (int j = 0; j < 4; j++) b[j] = Vs[t][tc * 4 + j];
            #pragma unroll
            for (int i = 0; i < 4; i++)
                #pragma unroll
                for (int j = 0; j < 4; j++)
                    acc[i][j] = fmaf(a[i], b[j], acc[i][j]);
        }
        __syncthreads();
    }
    #pragma unroll
    for (int i = 0; i < 4; i++)
        #pragma unroll
        for (int j = 0; j < 4; j++)
            m[(long)head * 4096 + (tr * 4 + i) * 64 + tc * 4 + j] = acc[i][j];
}

// ---------------- parallel suffix sum over S for each of 1024 cols ----------------
__global__ void suf_partial(const float* __restrict__ v, float* __restrict__ part) {
    int col = blockIdx.y * 256 + threadIdx.x;
    int seg = blockIdx.x;
    float s = 0.f;
    for (int t = seg * 128; t < seg * 128 + 128; t++) s += v[(size_t)t * H + col];
    part[seg * H + col] = s;
}
__global__ void suf_apply(const float* __restrict__ v, const float* __restrict__ part,
                          float* __restrict__ suf) {
    int col = blockIdx.y * 256 + threadIdx.x;
    int seg = blockIdx.x;
    float run = 0.f;
    for (int s2 = seg + 1; s2 < 16; s2++) run += part[s2 * H + col];
    for (int t = seg * 128 + 127; t >= seg * 128; t--) {
        size_t idx = (size_t)t * H + col;
        suf[idx] = run;
        run += v[idx];
    }
}

// ---------------- attn = scale*(Q@M) - 1e9*suf ; q,suf layout [S, NH*DH] ----------------
__global__ __launch_bounds__(256)
void attn_combine(const float* __restrict__ q, const float* __restrict__ m,
                  const float* __restrict__ suf, float* __restrict__ att) {
    const int head = blockIdx.y;
    const int s0 = blockIdx.x * 64;
    __shared__ float Qs[64][65];
    __shared__ float Ms[64][65];
    const int tid = threadIdx.x;
    for (int i = tid; i < 4096; i += 256) {
        int r = i >> 6, c = i & 63;
        Qs[r][c] = q[(size_t)(s0 + r) * H + head * DH + c];
        Ms[r][c] = m[(long)head * 4096 + i];
    }
    __syncthreads();
    const int tr = tid >> 4, tc = tid & 15;
    float acc[4][4] = {};
    #pragma unroll 4
    for (int hp = 0; hp < 64; hp++) {
        float a[4], b[4];
        #pragma unroll
        for (int i = 0; i < 4; i++) a[i] = Qs[tr * 4 + i][hp];
        #pragma unroll
        for (int j = 0; j < 4; j++) b[j] = Ms[hp][tc * 4 + j];
        #pragma unroll
        for (int i = 0; i < 4; i++)
            #pragma unroll
            for (int j = 0; j < 4; j++)
                acc[i][j] = fmaf(a[i], b[j], acc[i][j]);
    }
    #pragma unroll
    for (int i = 0; i < 4; i++) {
        int s = s0 + tr * 4 + i;
        #pragma unroll
        for (int j = 0; j < 4; j++) {
            int d = tc * 4 + j;
            att[(size_t)s * H + head * DH + d] =
                0.125f * acc[i][j] - 1e9f * suf[(size_t)s * H + head * DH + d];
        }
    }
}

// ---------------- LayerNorm (+ optional residual add) ----------------
template<bool ADD>
__global__ __launch_bounds__(256)
void ln_kernel(const float* __restrict__ t, const float* __restrict__ xin,
               const float* __restrict__ g, const float* __restrict__ b,
               float* __restrict__ out) {
    const int row = blockIdx.x;
    const int tid = threadIdx.x;
    const float* trow = t + (long)row * H;
    __shared__ float red[256];
    __shared__ float stat[2];

    float s = 0.f;
    for (int h = tid; h < H; h += 256) s += trow[h];
    red[tid] = s; __syncthreads();
    for (int off = 128; off > 0; off >>= 1) {
        if (tid < off) red[tid] += red[tid + off];
        __syncthreads();
    }
    if (tid == 0) stat[0] = red[0] * (1.0f / H);
    __syncthreads();
    float mean = stat[0];

    float vs = 0.f;
    for (int h = tid; h < H; h += 256) { float d = trow[h] - mean; vs += d * d; }
    red[tid] = vs; __syncthreads();
    for (int off = 128; off > 0; off >>= 1) {
        if (tid < off) red[tid] += red[tid + off];
        __syncthreads();
    }
    if (tid == 0) stat[1] = rsqrtf(red[0] * (1.0f / H) + 1e-5f);
    __syncthreads();
    float rstd = stat[1];

    for (int h = tid; h < H; h += 256) {
        float val = (trow[h] - mean) * rstd * g[h] + b[h];
        if (ADD) val += xin[(long)row * H + h];
        out[(long)row * H + h] = val;
    }
}

// ---------------- launch ----------------
extern "C" void kernel_launch(void* const* d_in, const int* in_sizes, int n_in,
                              void* d_out, int out_size) {
    const int*   tokens = (const int*)  d_in[0];
    const float* emb    = (const float*)d_in[1];
    const float* pos    = (const float*)d_in[2];
    const float* Wq     = (const float*)d_in[3];
    const float* Wk     = (const float*)d_in[4];
    const float* Wv     = (const float*)d_in[5];
    const float* Wp     = (const float*)d_in[6];
    const float* bp     = (const float*)d_in[7];
    const float* W1     = (const float*)d_in[8];
    const float* b1     = (const float*)d_in[9];
    const float* W2     = (const float*)d_in[10];
    const float* b2     = (const float*)d_in[11];
    const float* ln_g   = (const float*)d_in[12];
    const float* ln_b   = (const float*)d_in[13];
    const float* Wlm    = (const float*)d_in[14];
    const float* blm    = (const float*)d_in[15];
    float* out = (float*)d_out;
    const int Vv = in_sizes[15];

    float *x, *att, *tmp, *res, *xf, *q, *k, *v, *suf, *m, *h1, *part, *zb;
    __nv_bfloat16 *ahi, *alo;
    __nv_bfloat16 *btq_hi, *btq_lo, *btk_hi, *btk_lo, *btv_hi, *btv_lo, *btp_hi, *btp_lo;
    __nv_bfloat16 *bt1_hi, *bt1_lo, *bt2_hi, *bt2_lo, *btlm_hi, *btlm_lo;
    cudaGetSymbolAddress((void**)&x, g_x);       cudaGetSymbolAddress((void**)&att, g_att);
    cudaGetSymbolAddress((void**)&tmp, g_tmp);   cudaGetSymbolAddress((void**)&res, g_res);
    cudaGetSymbolAddress((void**)&xf, g_xf);     cudaGetSymbolAddress((void**)&q, g_q);
    cudaGetSymbolAddress((void**)&k, g_k);       cudaGetSymbolAddress((void**)&v, g_v);
    cudaGetSymbolAddress((void**)&suf, g_suf);   cudaGetSymbolAddress((void**)&m, g_m);
    cudaGetSymbolAddress((void**)&h1, g_h1);     cudaGetSymbolAddress((void**)&part, g_part);
    cudaGetSymbolAddress((void**)&zb, g_zb);
    cudaGetSymbolAddress((void**)&ahi, g_ahi);   cudaGetSymbolAddress((void**)&alo, g_alo);
    cudaGetSymbolAddress((void**)&btq_hi, g_btq_hi); cudaGetSymbolAddress((void**)&btq_lo, g_btq_lo);
    cudaGetSymbolAddress((void**)&btk_hi, g_btk_hi); cudaGetSymbolAddress((void**)&btk_lo, g_btk_lo);
    cudaGetSymbolAddress((void**)&btv_hi, g_btv_hi); cudaGetSymbolAddress((void**)&btv_lo, g_btv_lo);
    cudaGetSymbolAddress((void**)&btp_hi, g_btp_hi); cudaGetSymbolAddress((void**)&btp_lo, g_btp_lo);
    cudaGetSymbolAddress((void**)&bt1_hi, g_bt1_hi); cudaGetSymbolAddress((void**)&bt1_lo, g_bt1_lo);
    cudaGetSymbolAddress((void**)&bt2_hi, g_bt2_hi); cudaGetSymbolAddress((void**)&bt2_lo, g_bt2_lo);
    cudaGetSymbolAddress((void**)&btlm_hi, g_btlm_hi); cudaGetSymbolAddress((void**)&btlm_lo, g_btlm_lo);

    cudaFuncSetAttribute(gemm_hmma<0>, cudaFuncAttributeMaxDynamicSharedMemorySize, GEMM_SMEM);
    cudaFuncSetAttribute(gemm_hmma<1>, cudaFuncAttributeMaxDynamicSharedMemorySize, GEMM_SMEM);

    dim3 tb(32, 8);
    // weight conversion (part of each replay)
    transpose_split<<<dim3(2, 32, NLAYERS*NH), tb>>>(Wq, btq_hi, btq_lo, H, DH);
    transpose_split<<<dim3(2, 32, NLAYERS*NH), tb>>>(Wk, btk_hi, btk_lo, H, DH);
    transpose_split<<<dim3(2, 32, NLAYERS*NH), tb>>>(Wv, btv_hi, btv_lo, H, DH);
    transpose_split<<<dim3(32, 32, NLAYERS), tb>>>(Wp, btp_hi, btp_lo, H, H);
    transpose_split<<<dim3(128, 32, NLAYERS), tb>>>(W1, bt1_hi, bt1_lo, H, FF);
    transpose_split<<<dim3(32, 128, NLAYERS), tb>>>(W2, bt2_hi, bt2_lo, FF, H);
    transpose_split<<<dim3((Vv + 31) / 32, 32, 1), tb>>>(Wlm, btlm_hi, btlm_lo, H, Vv);

    embed_kernel<<<(S * H) / 256, 256>>>(tokens, emb, pos, x);

    for (int l = 0; l < NLAYERS; l++) {
        size_t oH = (size_t)l * H * H;
        size_t oF = (size_t)l * H * FF;

        split_act<<<(S * H) / 256, 256>>>(x, ahi, alo, S * H);
        gemm_hmma<0><<<dim3(8, 16), 256, GEMM_SMEM>>>(ahi, alo, btq_hi + oH, btq_lo + oH, zb, q, H, H);
        gemm_hmma<0><<<dim3(8, 16), 256, GEMM_SMEM>>>(ahi, alo, btk_hi + oH, btk_lo + oH, zb, k, H, H);
        gemm_hmma<0><<<dim3(8, 16), 256, GEMM_SMEM>>>(ahi, alo, btv_hi + oH, btv_lo + oH, zb, v, H, H);

        ktv_kernel<<<NH, 256>>>(k, v, m);
        suf_partial<<<dim3(16, 4), 256>>>(v, part);
        suf_apply<<<dim3(16, 4), 256>>>(v, part, suf);
        attn_combine<<<dim3(S / 64, NH), 256>>>(q, m, suf, att);

        split_act<<<(S * H) / 256, 256>>>(att, ahi, alo, S * H);
        gemm_hmma<0><<<dim3(8, 16), 256, GEMM_SMEM>>>(ahi, alo, btp_hi + oH, btp_lo + oH,
                                                      bp + (size_t)l * H, tmp, H, H);
        ln_kernel<true><<<S, 256>>>(tmp, x, ln_g, ln_b, res);

        split_act<<<(S * H) / 256, 256>>>(res, ahi, alo, S * H);
        gemm_hmma<1><<<dim3(32, 16), 256, GEMM_SMEM>>>(ahi, alo, bt1_hi + oF, bt1_lo + oF,
                                                       b1 + (size_t)l * FF, h1, FF, H);
        split_act<<<(S * FF) / 256, 256>>>(h1, ahi, alo, S * FF);
        gemm_hmma<0><<<dim3(8, 16), 256, GEMM_SMEM>>>(ahi, alo, bt2_hi + oF, bt2_lo + oF,
                                                      b2 + (size_t)l * H, tmp, H, FF);
        ln_kernel<true><<<S, 256>>>(tmp, res, ln_g, ln_b, x);
    }

    ln_kernel<false><<<S, 256>>>(x, nullptr, ln_g, ln_b, xf);
    split_act<<<(S * H) / 256, 256>>>(xf, ahi, alo, S * H);
    gemm_hmma<0><<<dim3(VPAD / 128, 16), 256, GEMM_SMEM>>>(ahi, alo, btlm_hi, btlm_lo,
                                                           blm, out, Vv, H);
}

// round 4
// speedup vs baseline: 2.9687x; 1.2399x over previous
#include <cuda_runtime.h>
#include <cuda_bf16.h>
#include <math.h>
#include <stdint.h>

#define S  2048
#define H  1024
#define NH 16
#define DH 64
#define FF 4096
#define NLAYERS 6
#define VPAD 50432     // 50257 padded to multiple of 128

#define SZ_SH (S*H)

// ---------------- device scratch ----------------
__device__ __align__(16) float g_x[SZ_SH];
__device__ __align__(16) float g_tmp[SZ_SH];
__device__ __align__(16) float g_res[SZ_SH];
__device__ __align__(16) float g_qkv[S*3072];
__device__ __align__(16) float g_suf[SZ_SH];
__device__ __align__(16) float g_m[4*NH*DH*DH];     // split-K partials
__device__ __align__(16) float g_part[16*1024];
__device__ __align__(16) float g_zb[8192];          // zero bias (never written)

// activation hi/lo
__device__ __align__(128) __nv_bfloat16 g_ahi[S*FF];
__device__ __align__(128) __nv_bfloat16 g_alo[S*FF];
__device__ __align__(128) __nv_bfloat16 g_bhi[S*FF];
__device__ __align__(128) __nv_bfloat16 g_blo[S*FF];

// weight hi/lo, K-major transposed [N,K]
__device__ __align__(128) __nv_bfloat16 g_btqkv_hi[NLAYERS*3072*H];
__device__ __align__(128) __nv_bfloat16 g_btqkv_lo[NLAYERS*3072*H];
__device__ __align__(128) __nv_bfloat16 g_btp_hi[NLAYERS*H*H];
__device__ __align__(128) __nv_bfloat16 g_btp_lo[NLAYERS*H*H];
__device__ __align__(128) __nv_bfloat16 g_bt1_hi[NLAYERS*H*FF];
__device__ __align__(128) __nv_bfloat16 g_bt1_lo[NLAYERS*H*FF];
__device__ __align__(128) __nv_bfloat16 g_bt2_hi[NLAYERS*H*FF];
__device__ __align__(128) __nv_bfloat16 g_bt2_lo[NLAYERS*H*FF];
__device__ __align__(128) __nv_bfloat16 g_btlm_hi[VPAD*H];   // pad rows stay zero
__device__ __align__(128) __nv_bfloat16 g_btlm_lo[VPAD*H];

// ---------------- PTX helpers ----------------
__device__ __forceinline__ uint32_t smem_u32(const void* p) {
    uint32_t a;
    asm("{ .reg .u64 t; cvta.to.shared.u64 t, %1; cvt.u32.u64 %0, t; }" : "=r"(a) : "l"(p));
    return a;
}
__device__ __forceinline__ void cp16(uint32_t dst, const void* src) {
    asm volatile("cp.async.cg.shared.global [%0], [%1], 16;" :: "r"(dst), "l"(src));
}
__device__ __forceinline__ void cp_commit() { asm volatile("cp.async.commit_group;" ::: "memory"); }
template<int N> __device__ __forceinline__ void cp_wait() {
    asm volatile("cp.async.wait_group %0;" :: "n"(N) : "memory");
}
__device__ __forceinline__ void ldsm4(uint32_t& r0, uint32_t& r1, uint32_t& r2, uint32_t& r3,
                                      uint32_t addr) {
    asm volatile("ldmatrix.sync.aligned.m8n8.x4.shared.b16 {%0,%1,%2,%3}, [%4];"
                 : "=r"(r0), "=r"(r1), "=r"(r2), "=r"(r3) : "r"(addr));
}
__device__ __forceinline__ void mma16816(float& d0, float& d1, float& d2, float& d3,
                                         uint32_t a0, uint32_t a1, uint32_t a2, uint32_t a3,
                                         uint32_t b0, uint32_t b1) {
    asm volatile("mma.sync.aligned.m16n8k16.row.col.f32.bf16.bf16.f32 "
                 "{%0,%1,%2,%3}, {%4,%5,%6,%7}, {%8,%9}, {%0,%1,%2,%3};"
                 : "+f"(d0), "+f"(d1), "+f"(d2), "+f"(d3)
                 : "r"(a0), "r"(a1), "r"(a2), "r"(a3), "r"(b0), "r"(b1));
}

__device__ __forceinline__ float gelu_exact(float x) {
    return 0.5f * x * (1.0f + erff(x * 0.70710678118654752f));
}

// pack 4 floats into bf16 hi/lo pairs (8B each)
__device__ __forceinline__ void split4(float o0, float o1, float o2, float o3,
                                       uint2& hv, uint2& lv) {
    __nv_bfloat162 h01 = __floats2bfloat162_rn(o0, o1);
    __nv_bfloat162 h23 = __floats2bfloat162_rn(o2, o3);
    float e0 = o0 - __bfloat162float(h01.x), e1 = o1 - __bfloat162float(h01.y);
    float e2 = o2 - __bfloat162float(h23.x), e3 = o3 - __bfloat162float(h23.y);
    __nv_bfloat162 l01 = __floats2bfloat162_rn(e0, e1);
    __nv_bfloat162 l23 = __floats2bfloat162_rn(e2, e3);
    hv = make_uint2(*(uint32_t*)&h01, *(uint32_t*)&h23);
    lv = make_uint2(*(uint32_t*)&l01, *(uint32_t*)&l23);
}

// ---------------- HMMA GEMM ----------------
// bf16x3: hi*hi + lo*hi + hi*lo, fp32 accumulate.
// CTA 128x128, BK=32, 8 warps (2x4) of 64x32 warp tiles, 3-stage cp.async pipeline.
// MODE 0: fp32 C (+bias, N-guarded). MODE 1: bf16 hi/lo out (+bias/act, N mult of 128).
#define ROWB 80
#define T_AHI 0
#define T_ALO 10240
#define T_BHI 20480
#define T_BLO 30720
#define STAGE_BYTES 40960
#define GEMM_SMEM (3*STAGE_BYTES)

template<int ACT, int MODE>
__global__ __launch_bounds__(256)
void gemm_hmma(const __nv_bfloat16* __restrict__ Ahi, const __nv_bfloat16* __restrict__ Alo,
               const __nv_bfloat16* __restrict__ Bhi, const __nv_bfloat16* __restrict__ Blo,
               const float* __restrict__ bias, float* __restrict__ C,
               __nv_bfloat16* __restrict__ Chi, __nv_bfloat16* __restrict__ Clo,
               int N, int K) {
    extern __shared__ char smem[];
    const uint32_t sb = smem_u32(smem);
    const int tid  = threadIdx.x;
    const int wid  = tid >> 5;
    const int lane = tid & 31;
    const int wrow = wid & 1;
    const int wcol = wid >> 1;
    const int bm = blockIdx.y << 7;
    const long bn = (long)blockIdx.x << 7;
    const int nc = K >> 5;

    const int r0t = tid >> 2, c0t = tid & 3;
    const int r1t = (tid + 256) >> 2, c1t = tid & 3;

    #define LOAD_STAGE(kc, s) do {                                                     \
        uint32_t st_ = sb + (s) * STAGE_BYTES;                                          \
        {                                                                               \
            size_t ga = ((size_t)(bm + r0t) * K + (kc) * 32 + c0t * 8) * 2;             \
            size_t gb = ((size_t)(bn + r0t) * K + (kc) * 32 + c0t * 8) * 2;             \
            uint32_t so = r0t * ROWB + c0t * 16;                                        \
            cp16(st_ + T_AHI + so, (const char*)Ahi + ga);                              \
            cp16(st_ + T_ALO + so, (const char*)Alo + ga);                              \
            cp16(st_ + T_BHI + so, (const char*)Bhi + gb);                              \
            cp16(st_ + T_BLO + so, (const char*)Blo + gb);                              \
        }                                                                               \
        {                                                                               \
            size_t ga = ((size_t)(bm + r1t) * K + (kc) * 32 + c1t * 8) * 2;             \
            size_t gb = ((size_t)(bn + r1t) * K + (kc) * 32 + c1t * 8) * 2;             \
            uint32_t so = r1t * ROWB + c1t * 16;                                        \
            cp16(st_ + T_AHI + so, (const char*)Ahi + ga);                              \
            cp16(st_ + T_ALO + so, (const char*)Alo + ga);                              \
            cp16(st_ + T_BHI + so, (const char*)Bhi + gb);                              \
            cp16(st_ + T_BLO + so, (const char*)Blo + gb);                              \
        }                                                                               \
    } while (0)

    LOAD_STAGE(0, 0); cp_commit();
    LOAD_STAGE(1, 1); cp_commit();

    const int lane8 = lane & 7, sub = lane >> 3;
    const uint32_t aoff = (uint32_t)(wrow * 64 + (sub & 1) * 8 + lane8) * ROWB + (sub >> 1) * 16;
    const uint32_t boff = (uint32_t)(wcol * 32 + lane8) * ROWB + sub * 16;

    float acc[4][4][4];
    #pragma unroll
    for (int i = 0; i < 4; i++)
        #pragma unroll
        for (int j = 0; j < 4; j++)
            #pragma unroll
            for (int e = 0; e < 4; e++) acc[i][j][e] = 0.f;

    int slot = 0;
    for (int it = 0; it < nc; it++) {
        cp_wait<1>();
        __syncthreads();
        if (it + 2 < nc) {
            int ns = slot + 2; if (ns >= 3) ns -= 3;
            LOAD_STAGE(it + 2, ns);
        }
        cp_commit();
        const uint32_t st = sb + slot * STAGE_BYTES;

        uint32_t bh[4][4], bl[4][4];
        #pragma unroll
        for (int nj = 0; nj < 4; nj++) {
            ldsm4(bh[nj][0], bh[nj][1], bh[nj][2], bh[nj][3], st + T_BHI + boff + nj * (8 * ROWB));
            ldsm4(bl[nj][0], bl[nj][1], bl[nj][2], bl[nj][3], st + T_BLO + boff + nj * (8 * ROWB));
        }
        #pragma unroll
        for (int ks = 0; ks < 2; ks++) {
            uint32_t a[4][4];
            #pragma unroll
            for (int mi = 0; mi < 4; mi++)
                ldsm4(a[mi][0], a[mi][1], a[mi][2], a[mi][3],
                      st + T_AHI + aoff + mi * (16 * ROWB) + ks * 32);
            #pragma unroll
            for (int mi = 0; mi < 4; mi++)
                #pragma unroll
                for (int nj = 0; nj < 4; nj++)
                    mma16816(acc[mi][nj][0], acc[mi][nj][1], acc[mi][nj][2], acc[mi][nj][3],
                             a[mi][0], a[mi][1], a[mi][2], a[mi][3],
                             bh[nj][ks * 2], bh[nj][ks * 2 + 1]);
            #pragma unroll
            for (int mi = 0; mi < 4; mi++)
                #pragma unroll
                for (int nj = 0; nj < 4; nj++)
                    mma16816(acc[mi][nj][0], acc[mi][nj][1], acc[mi][nj][2], acc[mi][nj][3],
                             a[mi][0], a[mi][1], a[mi][2], a[mi][3],
                             bl[nj][ks * 2], bl[nj][ks * 2 + 1]);
            #pragma unroll
            for (int mi = 0; mi < 4; mi++)
                ldsm4(a[mi][0], a[mi][1], a[mi][2], a[mi][3],
                      st + T_ALO + aoff + mi * (16 * ROWB) + ks * 32);
            #pragma unroll
            for (int mi = 0; mi < 4; mi++)
                #pragma unroll
                for (int nj = 0; nj < 4; nj++)
                    mma16816(acc[mi][nj][0], acc[mi][nj][1], acc[mi][nj][2], acc[mi][nj][3],
                             a[mi][0], a[mi][1], a[mi][2], a[mi][3],
                             bh[nj][ks * 2], bh[nj][ks * 2 + 1]);
        }
        if (++slot == 3) slot = 0;
    }

    // epilogue
    const int gr = lane >> 2;
    const int gc = (lane & 3) * 2;
    #pragma unroll
    for (int mi = 0; mi < 4; mi++) {
        size_t row0 = (size_t)(bm + wrow * 64 + mi * 16 + gr) * N;
        size_t row1 = row0 + (size_t)8 * N;
        #pragma unroll
        for (int nj = 0; nj < 4; nj++) {
            long c = bn + wcol * 32 + nj * 8 + gc;
            if (MODE == 0) {
                if (c < N) {
                    float bsv = bias[c];
                    float v0 = acc[mi][nj][0] + bsv;
                    float v2 = acc[mi][nj][2] + bsv;
                    if (ACT == 1) { v0 = gelu_exact(v0); v2 = gelu_exact(v2); }
                    C[row0 + c] = v0;
                    C[row1 + c] = v2;
                }
                if (c + 1 < N) {
                    float bsv = bias[c + 1];
                    float v1 = acc[mi][nj][1] + bsv;
                    float v3 = acc[mi][nj][3] + bsv;
                    if (ACT == 1) { v1 = gelu_exact(v1); v3 = gelu_exact(v3); }
                    C[row0 + c + 1] = v1;
                    C[row1 + c + 1] = v3;
                }
            } else {
                float b0 = bias[c], b1 = bias[c + 1];
                float v0 = acc[mi][nj][0] + b0, v1 = acc[mi][nj][1] + b1;
                float v2 = acc[mi][nj][2] + b0, v3 = acc[mi][nj][3] + b1;
                if (ACT == 1) {
                    v0 = gelu_exact(v0); v1 = gelu_exact(v1);
                    v2 = gelu_exact(v2); v3 = gelu_exact(v3);
                }
                __nv_bfloat162 hp0 = __floats2bfloat162_rn(v0, v1);
                __nv_bfloat162 hp1 = __floats2bfloat162_rn(v2, v3);
                float e0 = v0 - __bfloat162float(hp0.x), e1 = v1 - __bfloat162float(hp0.y);
                float e2 = v2 - __bfloat162float(hp1.x), e3 = v3 - __bfloat162float(hp1.y);
                __nv_bfloat162 lp0 = __floats2bfloat162_rn(e0, e1);
                __nv_bfloat162 lp1 = __floats2bfloat162_rn(e2, e3);
                *(uint32_t*)(Chi + row0 + c) = *(uint32_t*)&hp0;
                *(uint32_t*)(Clo + row0 + c) = *(uint32_t*)&lp0;
                *(uint32_t*)(Chi + row1 + c) = *(uint32_t*)&hp1;
                *(uint32_t*)(Clo + row1 + c) = *(uint32_t*)&lp1;
            }
        }
    }
    #undef LOAD_STAGE
}

// ---------------- weight transpose + split, vectorized writes ----------------
// src[R,C] per z -> out[C,R] hi/lo. Tile: 128 src rows x 32 src cols.
// QKV=1: out base interleaves q/k/v into [L,3072,1024] buffer (sel = 0/1/2).
template<int QKV>
__global__ __launch_bounds__(256)
void transpose_split(const float* __restrict__ src,
                     __nv_bfloat16* __restrict__ hi, __nv_bfloat16* __restrict__ lo,
                     int R, int C, int sel) {
    __shared__ float t[128][33];
    const int z = blockIdx.z;
    const size_t ib = (size_t)z * R * C;
    size_t ob;
    if (QKV) ob = (size_t)(z >> 4) * (3072 * 1024) + (size_t)sel * (1024 * 1024)
                + (size_t)(z & 15) * (64 * 1024);
    else     ob = ib;
    const int r0 = blockIdx.y * 128, c0 = blockIdx.x * 32;
    const int cc = threadIdx.x & 31, rb = threadIdx.x >> 5;
    const bool cok = (c0 + cc) < C;
    #pragma unroll
    for (int p = 0; p < 16; p++) {
        int rr = rb + p * 8;
        t[rr][cc] = cok ? src[ib + (size_t)(r0 + rr) * C + c0 + cc] : 0.f;
    }
    __syncthreads();
    const int oc = threadIdx.x >> 3, rq8 = threadIdx.x & 7;
    if (c0 + oc < C) {
        size_t obase = ob + (size_t)(c0 + oc) * R + r0;
        #pragma unroll
        for (int p = 0; p < 4; p++) {
            int r = (rq8 + p * 8) * 4;
            uint2 hv, lv;
            split4(t[r][oc], t[r + 1][oc], t[r + 2][oc], t[r + 3][oc], hv, lv);
            *(uint2*)(hi + obase + r) = hv;
            *(uint2*)(lo + obase + r) = lv;
        }
    }
}

// ---------------- embedding: x = emb[tok] + pos, + split ----------------
__global__ void embed_kernel(const int* __restrict__ tok, const float* __restrict__ emb,
                             const float* __restrict__ pos, float* __restrict__ x,
                             __nv_bfloat16* __restrict__ hi, __nv_bfloat16* __restrict__ lo) {
    int i4 = blockIdx.x * 256 + threadIdx.x;
    int e = i4 * 4;
    int s = e >> 10, h = e & 1023;
    float4 ev = *(const float4*)(emb + (size_t)tok[s] * H + h);
    float4 pv = *(const float4*)(pos + e);
    float o0 = ev.x + pv.x, o1 = ev.y + pv.y, o2 = ev.z + pv.z, o3 = ev.w + pv.w;
    *(float4*)(x + e) = make_float4(o0, o1, o2, o3);
    uint2 hv, lv;
    split4(o0, o1, o2, o3, hv, lv);
    *(uint2*)(hi + e) = hv;
    *(uint2*)(lo + e) = lv;
}

// ---------------- M_part = K^T V per (head, seg); qkv layout [S, 3072] ----------------
__global__ __launch_bounds__(256)
void ktv_kernel(const float* __restrict__ qkv, float* __restrict__ mp) {
    const int head = blockIdx.x & 15, seg = blockIdx.x >> 4;
    __shared__ float Ks[64][65];
    __shared__ float Vs[64][65];
    const int tid = threadIdx.x;
    const int tr = tid >> 4, tc = tid & 15;
    float acc[4][4] = {};
    for (int t0 = seg * 512; t0 < seg * 512 + 512; t0 += 64) {
        for (int i = tid; i < 4096; i += 256) {
            int r = i >> 6, c = i & 63;
            size_t base = (size_t)(t0 + r) * 3072 + head * DH + c;
            Ks[r][c] = qkv[base + 1024];
            Vs[r][c] = qkv[base + 2048];
        }
        __syncthreads();
        #pragma unroll 4
        for (int t = 0; t < 64; t++) {
            float a[4], b[4];
            #pragma unroll
            for (int i = 0; i < 4; i++) a[i] = Ks[t][tr * 4 + i];
            #pragma unroll
            for (int j = 0; j < 4; j++) b[j] = Vs[t][tc * 4 + j];
            #pragma unroll
            for (int i = 0; i < 4; i++)
                #pragma unroll
                for (int j = 0; j < 4; j++)
                    acc[i][j] = fmaf(a[i], b[j], acc[i][j]);
        }
        __syncthreads();
    }
    #pragma unroll
    for (int i = 0; i < 4; i++)
        #pragma unroll
        for (int j = 0; j < 4; j++)
            mp[(size_t)(seg * 16 + head) * 4096 + (tr * 4 + i) * 64 + tc * 4 + j] = acc[i][j];
}

// ---------------- parallel suffix sum of V over S ----------------
__global__ void suf_partial(const float* __restrict__ qkv, float* __restrict__ part) {
    int col = blockIdx.y * 256 + threadIdx.x;
    int seg = blockIdx.x;
    float s = 0.f;
    for (int t = seg * 128; t < seg * 128 + 128; t++)
        s += qkv[(size_t)t * 3072 + 2048 + col];
    part[seg * 1024 + col] = s;
}
__global__ void suf_apply(const float* __restrict__ qkv, const float* __restrict__ part,
                          float* __restrict__ suf) {
    int col = blockIdx.y * 256 + threadIdx.x;
    int seg = blockIdx.x;
    float run = 0.f;
    for (int s2 = seg + 1; s2 < 16; s2++) run += part[s2 * 1024 + col];
    for (int t = seg * 128 + 127; t >= seg * 128; t--) {
        suf[(size_t)t * 1024 + col] = run;
        run += qkv[(size_t)t * 3072 + 2048 + col];
    }
}

// ---------------- attn = scale*(Q@M) - 1e9*suf, emit hi/lo split ----------------
__global__ __launch_bounds__(256)
void attn_combine(const float* __restrict__ qkv, const float* __restrict__ mp,
                  const float* __restrict__ suf,
                  __nv_bfloat16* __restrict__ ahi, __nv_bfloat16* __restrict__ alo) {
    const int head = blockIdx.y;
    const int s0 = blockIdx.x * 64;
    __shared__ float Qs[64][65];
    __shared__ float Ms[64][65];
    const int tid = threadIdx.x;
    for (int i = tid; i < 4096; i += 256) {
        int r = i >> 6, c = i & 63;
        Qs[r][c] = qkv[(size_t)(s0 + r) * 3072 + head * DH + c];
        float mv = 0.f;
        #pragma unroll
        for (int sg = 0; sg < 4; sg++) mv += mp[(size_t)(sg * 16 + head) * 4096 + i];
        Ms[r][c] = mv;
    }
    __syncthreads();
    const int tr = tid >> 4, tc = tid & 15;
    float acc[4][4] = {};
    #pragma unroll 4
    for (int hp = 0; hp < 64; hp++) {
        float a[4], b[4];
        #pragma unroll
        for (int i = 0; i < 4; i++) a[i] = Qs[tr * 4 + i][hp];
        #pragma unroll
        for (int j = 0; j < 4; j++) b[j] = Ms[hp][tc * 4 + j];
        #pragma unroll
        for (int i = 0; i < 4; i++)
            #pragma unroll
            for (int j = 0; j < 4; j++)
                acc[i][j] = fmaf(a[i], b[j], acc[i][j]);
    }
    #pragma unroll
    for (int i = 0; i < 4; i++) {
        int s = s0 + tr * 4 + i;
        size_t sb = (size_t)s * 1024 + head * DH + tc * 4;
        float o[4];
        #pragma unroll
        for (int j = 0; j < 4; j++)
            o[j] = 0.125f * acc[i][j] - 1e9f * suf[sb + j];
        uint2 hv, lv;
        split4(o[0], o[1], o[2], o[3], hv, lv);
        *(uint2*)(ahi + sb) = hv;
        *(uint2*)(alo + sb) = lv;
    }
}

// ---------------- LayerNorm (+residual) + fused split ----------------
template<bool ADD, bool WF32>
__global__ __launch_bounds__(256)
void ln_kernel(const float* __restrict__ t, const float* __restrict__ xin,
               const float* __restrict__ g, const float* __restrict__ b,
               float* __restrict__ outf,
               __nv_bfloat16* __restrict__ hi, __nv_bfloat16* __restrict__ lo) {
    const int row = blockIdx.x;
    const int tid = threadIdx.x;
    float4 v = *(const float4*)(t + (size_t)row * H + tid * 4);
    __shared__ float red[256];
    __shared__ float stat[2];

    float s = v.x + v.y + v.z + v.w;
    red[tid] = s; __syncthreads();
    for (int o = 128; o > 0; o >>= 1) {
        if (tid < o) red[tid] += red[tid + o];
        __syncthreads();
    }
    if (tid == 0) stat[0] = red[0] * (1.0f / H);
    __syncthreads();
    float mean = stat[0];

    float dx = v.x - mean, dy = v.y - mean, dz = v.z - mean, dw = v.w - mean;
    red[tid] = dx * dx + dy * dy + dz * dz + dw * dw; __syncthreads();
    for (int o = 128; o > 0; o >>= 1) {
        if (tid < o) red[tid] += red[tid + o];
        __syncthreads();
    }
    if (tid == 0) stat[1] = rsqrtf(red[0] * (1.0f / H) + 1e-5f);
    __syncthreads();
    float rstd = stat[1];

    int h = tid * 4;
    float4 gv = *(const float4*)(g + h);
    float4 bv = *(const float4*)(b + h);
    float o0 = dx * rstd * gv.x + bv.x;
    float o1 = dy * rstd * gv.y + bv.y;
    float o2 = dz * rstd * gv.z + bv.z;
    float o3 = dw * rstd * gv.w + bv.w;
    if (ADD) {
        float4 xv = *(const float4*)(xin + (size_t)row * H + h);
        o0 += xv.x; o1 += xv.y; o2 += xv.z; o3 += xv.w;
    }
    if (WF32) *(float4*)(outf + (size_t)row * H + h) = make_float4(o0, o1, o2, o3);
    uint2 hv, lv;
    split4(o0, o1, o2, o3, hv, lv);
    *(uint2*)(hi + (size_t)row * H + h) = hv;
    *(uint2*)(lo + (size_t)row * H + h) = lv;
}

// ---------------- launch ----------------
extern "C" void kernel_launch(void* const* d_in, const int* in_sizes, int n_in,
                              void* d_out, int out_size) {
    const int*   tokens = (const int*)  d_in[0];
    const float* emb    = (const float*)d_in[1];
    const float* pos    = (const float*)d_in[2];
    const float* Wq     = (const float*)d_in[3];
    const float* Wk     = (const float*)d_in[4];
    const float* Wv     = (const float*)d_in[5];
    const float* Wp     = (const float*)d_in[6];
    const float* bp     = (const float*)d_in[7];
    const float* W1     = (const float*)d_in[8];
    const float* b1     = (const float*)d_in[9];
    const float* W2     = (const float*)d_in[10];
    const float* b2     = (const float*)d_in[11];
    const float* ln_g   = (const float*)d_in[12];
    const float* ln_b   = (const float*)d_in[13];
    const float* Wlm    = (const float*)d_in[14];
    const float* blm    = (const float*)d_in[15];
    float* out = (float*)d_out;
    const int Vv = in_sizes[15];

    float *x, *tmp, *res, *qkv, *suf, *m, *part, *zb;
    __nv_bfloat16 *ahi, *alo, *bhi, *blo;
    __nv_bfloat16 *btqkv_hi, *btqkv_lo, *btp_hi, *btp_lo;
    __nv_bfloat16 *bt1_hi, *bt1_lo, *bt2_hi, *bt2_lo, *btlm_hi, *btlm_lo;
    cudaGetSymbolAddress((void**)&x, g_x);       cudaGetSymbolAddress((void**)&tmp, g_tmp);
    cudaGetSymbolAddress((void**)&res, g_res);   cudaGetSymbolAddress((void**)&qkv, g_qkv);
    cudaGetSymbolAddress((void**)&suf, g_suf);   cudaGetSymbolAddress((void**)&m, g_m);
    cudaGetSymbolAddress((void**)&part, g_part); cudaGetSymbolAddress((void**)&zb, g_zb);
    cudaGetSymbolAddress((void**)&ahi, g_ahi);   cudaGetSymbolAddress((void**)&alo, g_alo);
    cudaGetSymbolAddress((void**)&bhi, g_bhi);   cudaGetSymbolAddress((void**)&blo, g_blo);
    cudaGetSymbolAddress((void**)&btqkv_hi, g_btqkv_hi);
    cudaGetSymbolAddress((void**)&btqkv_lo, g_btqkv_lo);
    cudaGetSymbolAddress((void**)&btp_hi, g_btp_hi); cudaGetSymbolAddress((void**)&btp_lo, g_btp_lo);
    cudaGetSymbolAddress((void**)&bt1_hi, g_bt1_hi); cudaGetSymbolAddress((void**)&bt1_lo, g_bt1_lo);
    cudaGetSymbolAddress((void**)&bt2_hi, g_bt2_hi); cudaGetSymbolAddress((void**)&bt2_lo, g_bt2_lo);
    cudaGetSymbolAddress((void**)&btlm_hi, g_btlm_hi); cudaGetSymbolAddress((void**)&btlm_lo, g_btlm_lo);

    cudaFuncSetAttribute(gemm_hmma<0,0>, cudaFuncAttributeMaxDynamicSharedMemorySize, GEMM_SMEM);
    cudaFuncSetAttribute(gemm_hmma<1,1>, cudaFuncAttributeMaxDynamicSharedMemorySize, GEMM_SMEM);

    dim3 tb(256);
    // launches 0-2: q/k/v weight transposes (layer-interleaved into combined buffer)
    transpose_split<1><<<dim3(2, 8, NLAYERS*NH), tb>>>(Wq, btqkv_hi, btqkv_lo, H, DH, 0);
    transpose_split<1><<<dim3(2, 8, NLAYERS*NH), tb>>>(Wk, btqkv_hi, btqkv_lo, H, DH, 1);
    transpose_split<1><<<dim3(2, 8, NLAYERS*NH), tb>>>(Wv, btqkv_hi, btqkv_lo, H, DH, 2);
    // launch 3: embed (+split)
    embed_kernel<<<(S * H) / 1024, 256>>>(tokens, emb, pos, x, ahi, alo);
    // launch 4: proj weights
    transpose_split<0><<<dim3(32, 8, NLAYERS), tb>>>(Wp, btp_hi, btp_lo, H, H, 0);
    // launch 5: first big GEMM (for ncu)
    gemm_hmma<0,0><<<dim3(24, 16), 256, GEMM_SMEM>>>(ahi, alo, btqkv_hi, btqkv_lo,
                                                     zb, qkv, nullptr, nullptr, 3072, H);
    // remaining weight transposes
    transpose_split<0><<<dim3(128, 8, NLAYERS), tb>>>(W1, bt1_hi, bt1_lo, H, FF, 0);
    transpose_split<0><<<dim3(32, 32, NLAYERS), tb>>>(W2, bt2_hi, bt2_lo, FF, H, 0);
    transpose_split<0><<<dim3((Vv + 31) / 32, 8, 1), tb>>>(Wlm, btlm_hi, btlm_lo, H, Vv, 0);

    for (int l = 0; l < NLAYERS; l++) {
        size_t oQ = (size_t)l * 3072 * H;
        size_t oH = (size_t)l * H * H;
        size_t oF = (size_t)l * H * FF;

        if (l > 0)
            gemm_hmma<0,0><<<dim3(24, 16), 256, GEMM_SMEM>>>(ahi, alo, btqkv_hi + oQ, btqkv_lo + oQ,
                                                             zb, qkv, nullptr, nullptr, 3072, H);
        ktv_kernel<<<64, 256>>>(qkv, m);
        suf_partial<<<dim3(16, 4), 256>>>(qkv, part);
        suf_apply<<<dim3(16, 4), 256>>>(qkv, part, suf);
        attn_combine<<<dim3(S / 64, NH), 256>>>(qkv, m, suf, ahi, alo);

        gemm_hmma<0,0><<<dim3(8, 16), 256, GEMM_SMEM>>>(ahi, alo, btp_hi + oH, btp_lo + oH,
                                                        bp + (size_t)l * H, tmp, nullptr, nullptr, H, H);
        ln_kernel<true, true><<<S, 256>>>(tmp, x, ln_g, ln_b, res, ahi, alo);

        gemm_hmma<1,1><<<dim3(32, 16), 256, GEMM_SMEM>>>(ahi, alo, bt1_hi + oF, bt1_lo + oF,
                                                         b1 + (size_t)l * FF, nullptr, bhi, blo, FF, H);
        gemm_hmma<0,0><<<dim3(8, 16), 256, GEMM_SMEM>>>(bhi, blo, bt2_hi + oF, bt2_lo + oF,
                                                        b2 + (size_t)l * H, tmp, nullptr, nullptr, H, FF);
        ln_kernel<true, true><<<S, 256>>>(tmp, res, ln_g, ln_b, x, ahi, alo);
    }

    ln_kernel<false, false><<<S, 256>>>(x, nullptr, ln_g, ln_b, nullptr, ahi, alo);
    gemm_hmma<0,0><<<dim3(VPAD / 128, 16), 256, GEMM_SMEM>>>(ahi, alo, btlm_hi, btlm_lo,
                                                             blm, out, nullptr, nullptr, Vv, H);
}

// round 5
// speedup vs baseline: 3.7174x; 1.2522x over previous
#include <cuda_runtime.h>
#include <cuda_bf16.h>
#include <cuda_fp16.h>
#include <math.h>
#include <stdint.h>

#define S  2048
#define H  1024
#define NH 16
#define DH 64
#define FF 4096
#define NLAYERS 6
#define VPAD 50432     // 50257 padded to multiple of 128

#define SZ_SH (S*H)

// ---------------- device scratch ----------------
__device__ __align__(16) float g_x[SZ_SH];
__device__ __align__(16) float g_tmp[SZ_SH];
__device__ __align__(16) float g_res[SZ_SH];
__device__ __align__(16) float g_qkv[S*3072];
__device__ __align__(16) float g_suf[SZ_SH];
__device__ __align__(16) float g_m[4*NH*DH*DH];     // split-K partials
__device__ __align__(16) float g_part[16*1024];
__device__ __align__(16) float g_zb[8192];          // zero bias (never written)

// activation hi/lo
__device__ __align__(128) __nv_bfloat16 g_ahi[S*FF];
__device__ __align__(128) __nv_bfloat16 g_alo[S*FF];
__device__ __align__(128) __nv_bfloat16 g_bhi[S*FF];
__device__ __align__(128) __nv_bfloat16 g_blo[S*FF];

// weight hi/lo, K-major transposed [N,K]
__device__ __align__(128) __nv_bfloat16 g_btqkv_hi[NLAYERS*3072*H];
__device__ __align__(128) __nv_bfloat16 g_btqkv_lo[NLAYERS*3072*H];
__device__ __align__(128) __nv_bfloat16 g_btp_hi[NLAYERS*H*H];
__device__ __align__(128) __nv_bfloat16 g_btp_lo[NLAYERS*H*H];
__device__ __align__(128) __nv_bfloat16 g_bt1_hi[NLAYERS*H*FF];
__device__ __align__(128) __nv_bfloat16 g_bt1_lo[NLAYERS*H*FF];
__device__ __align__(128) __nv_bfloat16 g_bt2_hi[NLAYERS*H*FF];
__device__ __align__(128) __nv_bfloat16 g_bt2_lo[NLAYERS*H*FF];
__device__ __align__(128) __half g_wlm_f16[VPAD*H];  // fp16 LM weights, pad rows stay zero
__device__ __align__(128) __half g_xf_f16[SZ_SH];    // fp16 final-LN activations

// ---------------- PTX helpers ----------------
__device__ __forceinline__ uint32_t smem_u32(const void* p) {
    uint32_t a;
    asm("{ .reg .u64 t; cvta.to.shared.u64 t, %1; cvt.u32.u64 %0, t; }" : "=r"(a) : "l"(p));
    return a;
}
__device__ __forceinline__ void cp16(uint32_t dst, const void* src) {
    asm volatile("cp.async.cg.shared.global [%0], [%1], 16;" :: "r"(dst), "l"(src));
}
__device__ __forceinline__ void cp_commit() { asm volatile("cp.async.commit_group;" ::: "memory"); }
template<int N> __device__ __forceinline__ void cp_wait() {
    asm volatile("cp.async.wait_group %0;" :: "n"(N) : "memory");
}
__device__ __forceinline__ void ldsm4(uint32_t& r0, uint32_t& r1, uint32_t& r2, uint32_t& r3,
                                      uint32_t addr) {
    asm volatile("ldmatrix.sync.aligned.m8n8.x4.shared.b16 {%0,%1,%2,%3}, [%4];"
                 : "=r"(r0), "=r"(r1), "=r"(r2), "=r"(r3) : "r"(addr));
}
__device__ __forceinline__ void mma16816(float& d0, float& d1, float& d2, float& d3,
                                         uint32_t a0, uint32_t a1, uint32_t a2, uint32_t a3,
                                         uint32_t b0, uint32_t b1) {
    asm volatile("mma.sync.aligned.m16n8k16.row.col.f32.bf16.bf16.f32 "
                 "{%0,%1,%2,%3}, {%4,%5,%6,%7}, {%8,%9}, {%0,%1,%2,%3};"
                 : "+f"(d0), "+f"(d1), "+f"(d2), "+f"(d3)
                 : "r"(a0), "r"(a1), "r"(a2), "r"(a3), "r"(b0), "r"(b1));
}
__device__ __forceinline__ void mma16816h(float& d0, float& d1, float& d2, float& d3,
                                          uint32_t a0, uint32_t a1, uint32_t a2, uint32_t a3,
                                          uint32_t b0, uint32_t b1) {
    asm volatile("mma.sync.aligned.m16n8k16.row.col.f32.f16.f16.f32 "
                 "{%0,%1,%2,%3}, {%4,%5,%6,%7}, {%8,%9}, {%0,%1,%2,%3};"
                 : "+f"(d0), "+f"(d1), "+f"(d2), "+f"(d3)
                 : "r"(a0), "r"(a1), "r"(a2), "r"(a3), "r"(b0), "r"(b1));
}

__device__ __forceinline__ float gelu_exact(float x) {
    return 0.5f * x * (1.0f + erff(x * 0.70710678118654752f));
}

// pack 4 floats into bf16 hi/lo pairs (8B each)
__device__ __forceinline__ void split4(float o0, float o1, float o2, float o3,
                                       uint2& hv, uint2& lv) {
    __nv_bfloat162 h01 = __floats2bfloat162_rn(o0, o1);
    __nv_bfloat162 h23 = __floats2bfloat162_rn(o2, o3);
    float e0 = o0 - __bfloat162float(h01.x), e1 = o1 - __bfloat162float(h01.y);
    float e2 = o2 - __bfloat162float(h23.x), e3 = o3 - __bfloat162float(h23.y);
    __nv_bfloat162 l01 = __floats2bfloat162_rn(e0, e1);
    __nv_bfloat162 l23 = __floats2bfloat162_rn(e2, e3);
    hv = make_uint2(*(uint32_t*)&h01, *(uint32_t*)&h23);
    lv = make_uint2(*(uint32_t*)&l01, *(uint32_t*)&l23);
}

// ---------------- HMMA GEMM (bf16x3 trunk) ----------------
#define ROWB 80
#define T_AHI 0
#define T_ALO 10240
#define T_BHI 20480
#define T_BLO 30720
#define STAGE_BYTES 40960
#define GEMM_SMEM (3*STAGE_BYTES)

template<int ACT, int MODE>
__global__ __launch_bounds__(256)
void gemm_hmma(const __nv_bfloat16* __restrict__ Ahi, const __nv_bfloat16* __restrict__ Alo,
               const __nv_bfloat16* __restrict__ Bhi, const __nv_bfloat16* __restrict__ Blo,
               const float* __restrict__ bias, float* __restrict__ C,
               __nv_bfloat16* __restrict__ Chi, __nv_bfloat16* __restrict__ Clo,
               int N, int K) {
    extern __shared__ char smem[];
    const uint32_t sb = smem_u32(smem);
    const int tid  = threadIdx.x;
    const int wid  = tid >> 5;
    const int lane = tid & 31;
    const int wrow = wid & 1;
    const int wcol = wid >> 1;
    const int bm = blockIdx.y << 7;
    const long bn = (long)blockIdx.x << 7;
    const int nc = K >> 5;

    const int r0t = tid >> 2, c0t = tid & 3;
    const int r1t = (tid + 256) >> 2, c1t = tid & 3;

    #define LOAD_STAGE(kc, s) do {                                                     \
        uint32_t st_ = sb + (s) * STAGE_BYTES;                                          \
        {                                                                               \
            size_t ga = ((size_t)(bm + r0t) * K + (kc) * 32 + c0t * 8) * 2;             \
            size_t gb = ((size_t)(bn + r0t) * K + (kc) * 32 + c0t * 8) * 2;             \
            uint32_t so = r0t * ROWB + c0t * 16;                                        \
            cp16(st_ + T_AHI + so, (const char*)Ahi + ga);                              \
            cp16(st_ + T_ALO + so, (const char*)Alo + ga);                              \
            cp16(st_ + T_BHI + so, (const char*)Bhi + gb);                              \
            cp16(st_ + T_BLO + so, (const char*)Blo + gb);                              \
        }                                                                               \
        {                                                                               \
            size_t ga = ((size_t)(bm + r1t) * K + (kc) * 32 + c1t * 8) * 2;             \
            size_t gb = ((size_t)(bn + r1t) * K + (kc) * 32 + c1t * 8) * 2;             \
            uint32_t so = r1t * ROWB + c1t * 16;                                        \
            cp16(st_ + T_AHI + so, (const char*)Ahi + ga);                              \
            cp16(st_ + T_ALO + so, (const char*)Alo + ga);                              \
            cp16(st_ + T_BHI + so, (const char*)Bhi + gb);                              \
            cp16(st_ + T_BLO + so, (const char*)Blo + gb);                              \
        }                                                                               \
    } while (0)

    LOAD_STAGE(0, 0); cp_commit();
    LOAD_STAGE(1, 1); cp_commit();

    const int lane8 = lane & 7, sub = lane >> 3;
    const uint32_t aoff = (uint32_t)(wrow * 64 + (sub & 1) * 8 + lane8) * ROWB + (sub >> 1) * 16;
    const uint32_t boff = (uint32_t)(wcol * 32 + lane8) * ROWB + sub * 16;

    float acc[4][4][4];
    #pragma unroll
    for (int i = 0; i < 4; i++)
        #pragma unroll
        for (int j = 0; j < 4; j++)
            #pragma unroll
            for (int e = 0; e < 4; e++) acc[i][j][e] = 0.f;

    int slot = 0;
    for (int it = 0; it < nc; it++) {
        cp_wait<1>();
        __syncthreads();
        if (it + 2 < nc) {
            int ns = slot + 2; if (ns >= 3) ns -= 3;
            LOAD_STAGE(it + 2, ns);
        }
        cp_commit();
        const uint32_t st = sb + slot * STAGE_BYTES;

        uint32_t bh[4][4], bl[4][4];
        #pragma unroll
        for (int nj = 0; nj < 4; nj++) {
            ldsm4(bh[nj][0], bh[nj][1], bh[nj][2], bh[nj][3], st + T_BHI + boff + nj * (8 * ROWB));
            ldsm4(bl[nj][0], bl[nj][1], bl[nj][2], bl[nj][3], st + T_BLO + boff + nj * (8 * ROWB));
        }
        #pragma unroll
        for (int ks = 0; ks < 2; ks++) {
            uint32_t a[4][4];
            #pragma unroll
            for (int mi = 0; mi < 4; mi++)
                ldsm4(a[mi][0], a[mi][1], a[mi][2], a[mi][3],
                      st + T_AHI + aoff + mi * (16 * ROWB) + ks * 32);
            #pragma unroll
            for (int mi = 0; mi < 4; mi++)
                #pragma unroll
                for (int nj = 0; nj < 4; nj++)
                    mma16816(acc[mi][nj][0], acc[mi][nj][1], acc[mi][nj][2], acc[mi][nj][3],
                             a[mi][0], a[mi][1], a[mi][2], a[mi][3],
                             bh[nj][ks * 2], bh[nj][ks * 2 + 1]);
            #pragma unroll
            for (int mi = 0; mi < 4; mi++)
                #pragma unroll
                for (int nj = 0; nj < 4; nj++)
                    mma16816(acc[mi][nj][0], acc[mi][nj][1], acc[mi][nj][2], acc[mi][nj][3],
                             a[mi][0], a[mi][1], a[mi][2], a[mi][3],
                             bl[nj][ks * 2], bl[nj][ks * 2 + 1]);
            #pragma unroll
            for (int mi = 0; mi < 4; mi++)
                ldsm4(a[mi][0], a[mi][1], a[mi][2], a[mi][3],
                      st + T_ALO + aoff + mi * (16 * ROWB) + ks * 32);
            #pragma unroll
            for (int mi = 0; mi < 4; mi++)
                #pragma unroll
                for (int nj = 0; nj < 4; nj++)
                    mma16816(acc[mi][nj][0], acc[mi][nj][1], acc[mi][nj][2], acc[mi][nj][3],
                             a[mi][0], a[mi][1], a[mi][2], a[mi][3],
                             bh[nj][ks * 2], bh[nj][ks * 2 + 1]);
        }
        if (++slot == 3) slot = 0;
    }

    // epilogue
    const int gr = lane >> 2;
    const int gc = (lane & 3) * 2;
    #pragma unroll
    for (int mi = 0; mi < 4; mi++) {
        size_t row0 = (size_t)(bm + wrow * 64 + mi * 16 + gr) * N;
        size_t row1 = row0 + (size_t)8 * N;
        #pragma unroll
        for (int nj = 0; nj < 4; nj++) {
            long c = bn + wcol * 32 + nj * 8 + gc;
            if (MODE == 0) {
                float bsv0 = bias[c], bsv1 = bias[c + 1];
                float v0 = acc[mi][nj][0] + bsv0;
                float v1 = acc[mi][nj][1] + bsv1;
                float v2 = acc[mi][nj][2] + bsv0;
                float v3 = acc[mi][nj][3] + bsv1;
                if (ACT == 1) {
                    v0 = gelu_exact(v0); v1 = gelu_exact(v1);
                    v2 = gelu_exact(v2); v3 = gelu_exact(v3);
                }
                C[row0 + c] = v0; C[row0 + c + 1] = v1;
                C[row1 + c] = v2; C[row1 + c + 1] = v3;
            } else {
                float b0 = bias[c], b1 = bias[c + 1];
                float v0 = acc[mi][nj][0] + b0, v1 = acc[mi][nj][1] + b1;
                float v2 = acc[mi][nj][2] + b0, v3 = acc[mi][nj][3] + b1;
                if (ACT == 1) {
                    v0 = gelu_exact(v0); v1 = gelu_exact(v1);
                    v2 = gelu_exact(v2); v3 = gelu_exact(v3);
                }
                __nv_bfloat162 hp0 = __floats2bfloat162_rn(v0, v1);
                __nv_bfloat162 hp1 = __floats2bfloat162_rn(v2, v3);
                float e0 = v0 - __bfloat162float(hp0.x), e1 = v1 - __bfloat162float(hp0.y);
                float e2 = v2 - __bfloat162float(hp1.x), e3 = v3 - __bfloat162float(hp1.y);
                __nv_bfloat162 lp0 = __floats2bfloat162_rn(e0, e1);
                __nv_bfloat162 lp1 = __floats2bfloat162_rn(e2, e3);
                *(uint32_t*)(Chi + row0 + c) = *(uint32_t*)&hp0;
                *(uint32_t*)(Clo + row0 + c) = *(uint32_t*)&lp0;
                *(uint32_t*)(Chi + row1 + c) = *(uint32_t*)&hp1;
                *(uint32_t*)(Clo + row1 + c) = *(uint32_t*)&lp1;
            }
        }
    }
    #undef LOAD_STAGE
}

// ---------------- fp16 single-term GEMM (LM head) ----------------
// grid.x = M tiles (fast) so co-resident CTAs share B tiles via L2.
#define F_TA 0
#define F_TB 10240
#define F_STAGE 20480
#define F16_SMEM (3*F_STAGE)

__global__ __launch_bounds__(256)
void gemm_f16(const __half* __restrict__ A, const __half* __restrict__ B,
              const float* __restrict__ bias, float* __restrict__ C, int N, int K) {
    extern __shared__ char smem[];
    const uint32_t sb = smem_u32(smem);
    const int tid  = threadIdx.x;
    const int wid  = tid >> 5;
    const int lane = tid & 31;
    const int wrow = wid & 1;
    const int wcol = wid >> 1;
    const int bm = blockIdx.x << 7;
    const long bn = (long)blockIdx.y << 7;
    const int nc = K >> 5;

    const int r0t = tid >> 2, c0t = tid & 3;
    const int r1t = (tid + 256) >> 2, c1t = tid & 3;

    #define LOAD_STAGE_F(kc, s) do {                                                   \
        uint32_t st_ = sb + (s) * F_STAGE;                                              \
        {                                                                               \
            size_t ga = ((size_t)(bm + r0t) * K + (kc) * 32 + c0t * 8) * 2;             \
            size_t gb = ((size_t)(bn + r0t) * K + (kc) * 32 + c0t * 8) * 2;             \
            uint32_t so = r0t * ROWB + c0t * 16;                                        \
            cp16(st_ + F_TA + so, (const char*)A + ga);                                 \
            cp16(st_ + F_TB + so, (const char*)B + gb);                                 \
        }                                                                               \
        {                                                                               \
            size_t ga = ((size_t)(bm + r1t) * K + (kc) * 32 + c1t * 8) * 2;             \
            size_t gb = ((size_t)(bn + r1t) * K + (kc) * 32 + c1t * 8) * 2;             \
            uint32_t so = r1t * ROWB + c1t * 16;                                        \
            cp16(st_ + F_TA + so, (const char*)A + ga);                                 \
            cp16(st_ + F_TB + so, (const char*)B + gb);                                 \
        }                                                                               \
    } while (0)

    LOAD_STAGE_F(0, 0); cp_commit();
    LOAD_STAGE_F(1, 1); cp_commit();

    const int lane8 = lane & 7, sub = lane >> 3;
    const uint32_t aoff = (uint32_t)(wrow * 64 + (sub & 1) * 8 + lane8) * ROWB + (sub >> 1) * 16;
    const uint32_t boff = (uint32_t)(wcol * 32 + lane8) * ROWB + sub * 16;

    float acc[4][4][4];
    #pragma unroll
    for (int i = 0; i < 4; i++)
        #pragma unroll
        for (int j = 0; j < 4; j++)
            #pragma unroll
            for (int e = 0; e < 4; e++) acc[i][j][e] = 0.f;

    int slot = 0;
    for (int it = 0; it < nc; it++) {
        cp_wait<1>();
        __syncthreads();
        if (it + 2 < nc) {
            int ns = slot + 2; if (ns >= 3) ns -= 3;
            LOAD_STAGE_F(it + 2, ns);
        }
        cp_commit();
        const uint32_t st = sb + slot * F_STAGE;

        uint32_t bf[4][4];
        #pragma unroll
        for (int nj = 0; nj < 4; nj++)
            ldsm4(bf[nj][0], bf[nj][1], bf[nj][2], bf[nj][3], st + F_TB + boff + nj * (8 * ROWB));
        #pragma unroll
        for (int ks = 0; ks < 2; ks++) {
            uint32_t a[4][4];
            #pragma unroll
            for (int mi = 0; mi < 4; mi++)
                ldsm4(a[mi][0], a[mi][1], a[mi][2], a[mi][3],
                      st + F_TA + aoff + mi * (16 * ROWB) + ks * 32);
            #pragma unroll
            for (int mi = 0; mi < 4; mi++)
                #pragma unroll
                for (int nj = 0; nj < 4; nj++)
                    mma16816h(acc[mi][nj][0], acc[mi][nj][1], acc[mi][nj][2], acc[mi][nj][3],
                              a[mi][0], a[mi][1], a[mi][2], a[mi][3],
                              bf[nj][ks * 2], bf[nj][ks * 2 + 1]);
        }
        if (++slot == 3) slot = 0;
    }

    const int gr = lane >> 2;
    const int gc = (lane & 3) * 2;
    #pragma unroll
    for (int mi = 0; mi < 4; mi++) {
        size_t row0 = (size_t)(bm + wrow * 64 + mi * 16 + gr) * N;
        size_t row1 = row0 + (size_t)8 * N;
        #pragma unroll
        for (int nj = 0; nj < 4; nj++) {
            long c = bn + wcol * 32 + nj * 8 + gc;
            if (c < N) {
                C[row0 + c] = acc[mi][nj][0] + bias[c];
                C[row1 + c] = acc[mi][nj][2] + bias[c];
            }
            if (c + 1 < N) {
                C[row0 + c + 1] = acc[mi][nj][1] + bias[c + 1];
                C[row1 + c + 1] = acc[mi][nj][3] + bias[c + 1];
            }
        }
    }
    #undef LOAD_STAGE_F
}

// ---------------- weight transpose + split (bf16 hi/lo) ----------------
// QKV=1: single launch handles q,k,v (z major selects source+slot)
template<int QKV>
__global__ __launch_bounds__(256)
void transpose_split(const float* __restrict__ src0, const float* __restrict__ src1,
                     const float* __restrict__ src2,
                     __nv_bfloat16* __restrict__ hi, __nv_bfloat16* __restrict__ lo,
                     int R, int C) {
    __shared__ float t[128][33];
    int z = blockIdx.z;
    const float* src = src0;
    int sel = 0;
    if (QKV) {
        sel = z / (NLAYERS * NH);
        z   = z % (NLAYERS * NH);
        src = (sel == 0) ? src0 : (sel == 1) ? src1 : src2;
    }
    const size_t ib = (size_t)z * R * C;
    size_t ob;
    if (QKV) ob = (size_t)(z >> 4) * (3072 * 1024) + (size_t)sel * (1024 * 1024)
                + (size_t)(z & 15) * (64 * 1024);
    else     ob = ib;
    const int r0 = blockIdx.y * 128, c0 = blockIdx.x * 32;
    const int cc = threadIdx.x & 31, rb = threadIdx.x >> 5;
    const bool cok = (c0 + cc) < C;
    #pragma unroll
    for (int p = 0; p < 16; p++) {
        int rr = rb + p * 8;
        t[rr][cc] = cok ? src[ib + (size_t)(r0 + rr) * C + c0 + cc] : 0.f;
    }
    __syncthreads();
    const int oc = threadIdx.x >> 3, rq8 = threadIdx.x & 7;
    if (c0 + oc < C) {
        size_t obase = ob + (size_t)(c0 + oc) * R + r0;
        #pragma unroll
        for (int p = 0; p < 4; p++) {
            int r = (rq8 + p * 8) * 4;
            uint2 hv, lv;
            split4(t[r][oc], t[r + 1][oc], t[r + 2][oc], t[r + 3][oc], hv, lv);
            *(uint2*)(hi + obase + r) = hv;
            *(uint2*)(lo + obase + r) = lv;
        }
    }
}

// ---------------- fp16 weight transpose (LM head) ----------------
__global__ __launch_bounds__(256)
void transpose_f16(const float* __restrict__ src, __half* __restrict__ out, int R, int C) {
    __shared__ float t[128][33];
    const int r0 = blockIdx.y * 128, c0 = blockIdx.x * 32;
    const int cc = threadIdx.x & 31, rb = threadIdx.x >> 5;
    const bool cok = (c0 + cc) < C;
    #pragma unroll
    for (int p = 0; p < 16; p++) {
        int rr = rb + p * 8;
        t[rr][cc] = cok ? src[(size_t)(r0 + rr) * C + c0 + cc] : 0.f;
    }
    __syncthreads();
    const int oc = threadIdx.x >> 3, rq8 = threadIdx.x & 7;
    if (c0 + oc < C) {
        size_t obase = (size_t)(c0 + oc) * R + r0;
        #pragma unroll
        for (int p = 0; p < 4; p++) {
            int r = (rq8 + p * 8) * 4;
            __half2 h0 = __floats2half2_rn(t[r][oc], t[r + 1][oc]);
            __half2 h1 = __floats2half2_rn(t[r + 2][oc], t[r + 3][oc]);
            *(uint2*)(out + obase + r) = make_uint2(*(uint32_t*)&h0, *(uint32_t*)&h1);
        }
    }
}

// ---------------- embedding: x = emb[tok] + pos, + split ----------------
__global__ void embed_kernel(const int* __restrict__ tok, const float* __restrict__ emb,
                             const float* __restrict__ pos, float* __restrict__ x,
                             __nv_bfloat16* __restrict__ hi, __nv_bfloat16* __restrict__ lo) {
    int i4 = blockIdx.x * 256 + threadIdx.x;
    int e = i4 * 4;
    int s = e >> 10, h = e & 1023;
    float4 ev = *(const float4*)(emb + (size_t)tok[s] * H + h);
    float4 pv = *(const float4*)(pos + e);
    float o0 = ev.x + pv.x, o1 = ev.y + pv.y, o2 = ev.z + pv.z, o3 = ev.w + pv.w;
    *(float4*)(x + e) = make_float4(o0, o1, o2, o3);
    uint2 hv, lv;
    split4(o0, o1, o2, o3, hv, lv);
    *(uint2*)(hi + e) = hv;
    *(uint2*)(lo + e) = lv;
}

// ---------------- M_part = K^T V per (head, seg); qkv layout [S, 3072] ----------------
__global__ __launch_bounds__(256)
void ktv_kernel(const float* __restrict__ qkv, float* __restrict__ mp) {
    const int head = blockIdx.x & 15, seg = blockIdx.x >> 4;
    __shared__ float Ks[64][65];
    __shared__ float Vs[64][65];
    const int tid = threadIdx.x;
    const int tr = tid >> 4, tc = tid & 15;
    float acc[4][4] = {};
    for (int t0 = seg * 512; t0 < seg * 512 + 512; t0 += 64) {
        for (int i = tid; i < 4096; i += 256) {
            int r = i >> 6, c = i & 63;
            size_t base = (size_t)(t0 + r) * 3072 + head * DH + c;
            Ks[r][c] = qkv[base + 1024];
            Vs[r][c] = qkv[base + 2048];
        }
        __syncthreads();
        #pragma unroll 4
        for (int t = 0; t < 64; t++) {
            float a[4], b[4];
            #pragma unroll
            for (int i = 0; i < 4; i++) a[i] = Ks[t][tr * 4 + i];
            #pragma unroll
            for (int j = 0; j < 4; j++) b[j] = Vs[t][tc * 4 + j];
            #pragma unroll
            for (int i = 0; i < 4; i++)
                #pragma unroll
                for (int j = 0; j < 4; j++)
                    acc[i][j] = fmaf(a[i], b[j], acc[i][j]);
        }
        __syncthreads();
    }
    #pragma unroll
    for (int i = 0; i < 4; i++)
        #pragma unroll
        for (int j = 0; j < 4; j++)
            mp[(size_t)(seg * 16 + head) * 4096 + (tr * 4 + i) * 64 + tc * 4 + j] = acc[i][j];
}

// ---------------- parallel suffix sum of V over S ----------------
__global__ void suf_partial(const float* __restrict__ qkv, float* __restrict__ part) {
    int col = blockIdx.y * 256 + threadIdx.x;
    int seg = blockIdx.x;
    float s = 0.f;
    for (int t = seg * 128; t < seg * 128 + 128; t++)
        s += qkv[(size_t)t * 3072 + 2048 + col];
    part[seg * 1024 + col] = s;
}
__global__ void suf_apply(const float* __restrict__ qkv, const float* __restrict__ part,
                          float* __restrict__ suf) {
    int col = blockIdx.y * 256 + threadIdx.x;
    int seg = blockIdx.x;
    float run = 0.f;
    for (int s2 = seg + 1; s2 < 16; s2++) run += part[s2 * 1024 + col];
    for (int t = seg * 128 + 127; t >= seg * 128; t--) {
        suf[(size_t)t * 1024 + col] = run;
        run += qkv[(size_t)t * 3072 + 2048 + col];
    }
}

// ---------------- attn = scale*(Q@M) - 1e9*suf, emit hi/lo split ----------------
__global__ __launch_bounds__(256)
void attn_combine(const float* __restrict__ qkv, const float* __restrict__ mp,
                  const float* __restrict__ suf,
                  __nv_bfloat16* __restrict__ ahi, __nv_bfloat16* __restrict__ alo) {
    const int head = blockIdx.y;
    const int s0 = blockIdx.x * 64;
    __shared__ float Qs[64][65];
    __shared__ float Ms[64][65];
    const int tid = threadIdx.x;
    for (int i = tid; i < 4096; i += 256) {
        int r = i >> 6, c = i & 63;
        Qs[r][c] = qkv[(size_t)(s0 + r) * 3072 + head * DH + c];
        float mv = 0.f;
        #pragma unroll
        for (int sg = 0; sg < 4; sg++) mv += mp[(size_t)(sg * 16 + head) * 4096 + i];
        Ms[r][c] = mv;
    }
    __syncthreads();
    const int tr = tid >> 4, tc = tid & 15;
    float acc[4][4] = {};
    #pragma unroll 4
    for (int hp = 0; hp < 64; hp++) {
        float a[4], b[4];
        #pragma unroll
        for (int i = 0; i < 4; i++) a[i] = Qs[tr * 4 + i][hp];
        #pragma unroll
        for (int j = 0; j < 4; j++) b[j] = Ms[hp][tc * 4 + j];
        #pragma unroll
        for (int i = 0; i < 4; i++)
            #pragma unroll
            for (int j = 0; j < 4; j++)
                acc[i][j] = fmaf(a[i], b[j], acc[i][j]);
    }
    #pragma unroll
    for (int i = 0; i < 4; i++) {
        int s = s0 + tr * 4 + i;
        size_t sb = (size_t)s * 1024 + head * DH + tc * 4;
        float o[4];
        #pragma unroll
        for (int j = 0; j < 4; j++)
            o[j] = 0.125f * acc[i][j] - 1e9f * suf[sb + j];
        uint2 hv, lv;
        split4(o[0], o[1], o[2], o[3], hv, lv);
        *(uint2*)(ahi + sb) = hv;
        *(uint2*)(alo + sb) = lv;
    }
}

// ---------------- LayerNorm (+residual) + fused split ----------------
// OUTK: 0 = bf16 hi/lo (+opt fp32), 1 = fp16 single
template<bool ADD, bool WF32, int OUTK>
__global__ __launch_bounds__(256)
void ln_kernel(const float* __restrict__ t, const float* __restrict__ xin,
               const float* __restrict__ g, const float* __restrict__ b,
               float* __restrict__ outf,
               __nv_bfloat16* __restrict__ hi, __nv_bfloat16* __restrict__ lo,
               __half* __restrict__ outh) {
    const int row = blockIdx.x;
    const int tid = threadIdx.x;
    float4 v = *(const float4*)(t + (size_t)row * H + tid * 4);
    __shared__ float red[256];
    __shared__ float stat[2];

    float s = v.x + v.y + v.z + v.w;
    red[tid] = s; __syncthreads();
    for (int o = 128; o > 0; o >>= 1) {
        if (tid < o) red[tid] += red[tid + o];
        __syncthreads();
    }
    if (tid == 0) stat[0] = red[0] * (1.0f / H);
    __syncthreads();
    float mean = stat[0];

    float dx = v.x - mean, dy = v.y - mean, dz = v.z - mean, dw = v.w - mean;
    red[tid] = dx * dx + dy * dy + dz * dz + dw * dw; __syncthreads();
    for (int o = 128; o > 0; o >>= 1) {
        if (tid < o) red[tid] += red[tid + o];
        __syncthreads();
    }
    if (tid == 0) stat[1] = rsqrtf(red[0] * (1.0f / H) + 1e-5f);
    __syncthreads();
    float rstd = stat[1];

    int h = tid * 4;
    float4 gv = *(const float4*)(g + h);
    float4 bv = *(const float4*)(b + h);
    float o0 = dx * rstd * gv.x + bv.x;
    float o1 = dy * rstd * gv.y + bv.y;
    float o2 = dz * rstd * gv.z + bv.z;
    float o3 = dw * rstd * gv.w + bv.w;
    if (ADD) {
        float4 xv = *(const float4*)(xin + (size_t)row * H + h);
        o0 += xv.x; o1 += xv.y; o2 += xv.z; o3 += xv.w;
    }
    if (WF32) *(float4*)(outf + (size_t)row * H + h) = make_float4(o0, o1, o2, o3);
    if (OUTK == 0) {
        uint2 hv, lv;
        split4(o0, o1, o2, o3, hv, lv);
        *(uint2*)(hi + (size_t)row * H + h) = hv;
        *(uint2*)(lo + (size_t)row * H + h) = lv;
    } else {
        __half2 h0 = __floats2half2_rn(o0, o1);
        __half2 h1 = __floats2half2_rn(o2, o3);
        *(uint2*)(outh + (size_t)row * H + h) = make_uint2(*(uint32_t*)&h0, *(uint32_t*)&h1);
    }
}

// ---------------- launch ----------------
extern "C" void kernel_launch(void* const* d_in, const int* in_sizes, int n_in,
                              void* d_out, int out_size) {
    const int*   tokens = (const int*)  d_in[0];
    const float* emb    = (const float*)d_in[1];
    const float* pos    = (const float*)d_in[2];
    const float* Wq     = (const float*)d_in[3];
    const float* Wk     = (const float*)d_in[4];
    const float* Wv     = (const float*)d_in[5];
    const float* Wp     = (const float*)d_in[6];
    const float* bp     = (const float*)d_in[7];
    const float* W1     = (const float*)d_in[8];
    const float* b1     = (const float*)d_in[9];
    const float* W2     = (const float*)d_in[10];
    const float* b2     = (const float*)d_in[11];
    const float* ln_g   = (const float*)d_in[12];
    const float* ln_b   = (const float*)d_in[13];
    const float* Wlm    = (const float*)d_in[14];
    const float* blm    = (const float*)d_in[15];
    float* out = (float*)d_out;
    const int Vv = in_sizes[15];

    float *x, *tmp, *res, *qkv, *suf, *m, *part, *zb;
    __nv_bfloat16 *ahi, *alo, *bhi, *blo;
    __nv_bfloat16 *btqkv_hi, *btqkv_lo, *btp_hi, *btp_lo;
    __nv_bfloat16 *bt1_hi, *bt1_lo, *bt2_hi, *bt2_lo;
    __half *wlm, *xf16;
    cudaGetSymbolAddress((void**)&x, g_x);       cudaGetSymbolAddress((void**)&tmp, g_tmp);
    cudaGetSymbolAddress((void**)&res, g_res);   cudaGetSymbolAddress((void**)&qkv, g_qkv);
    cudaGetSymbolAddress((void**)&suf, g_suf);   cudaGetSymbolAddress((void**)&m, g_m);
    cudaGetSymbolAddress((void**)&part, g_part); cudaGetSymbolAddress((void**)&zb, g_zb);
    cudaGetSymbolAddress((void**)&ahi, g_ahi);   cudaGetSymbolAddress((void**)&alo, g_alo);
    cudaGetSymbolAddress((void**)&bhi, g_bhi);   cudaGetSymbolAddress((void**)&blo, g_blo);
    cudaGetSymbolAddress((void**)&btqkv_hi, g_btqkv_hi);
    cudaGetSymbolAddress((void**)&btqkv_lo, g_btqkv_lo);
    cudaGetSymbolAddress((void**)&btp_hi, g_btp_hi); cudaGetSymbolAddress((void**)&btp_lo, g_btp_lo);
    cudaGetSymbolAddress((void**)&bt1_hi, g_bt1_hi); cudaGetSymbolAddress((void**)&bt1_lo, g_bt1_lo);
    cudaGetSymbolAddress((void**)&bt2_hi, g_bt2_hi); cudaGetSymbolAddress((void**)&bt2_lo, g_bt2_lo);
    cudaGetSymbolAddress((void**)&wlm, g_wlm_f16);   cudaGetSymbolAddress((void**)&xf16, g_xf_f16);

    cudaFuncSetAttribute(gemm_hmma<0,0>, cudaFuncAttributeMaxDynamicSharedMemorySize, GEMM_SMEM);
    cudaFuncSetAttribute(gemm_hmma<1,1>, cudaFuncAttributeMaxDynamicSharedMemorySize, GEMM_SMEM);
    cudaFuncSetAttribute(gemm_f16, cudaFuncAttributeMaxDynamicSharedMemorySize, F16_SMEM);

    dim3 tb(256);
    // idx0: embed
    embed_kernel<<<(S * H) / 1024, 256>>>(tokens, emb, pos, x, ahi, alo);
    // idx1: combined qkv weight transpose
    transpose_split<1><<<dim3(2, 8, 3 * NLAYERS * NH), tb>>>(Wq, Wk, Wv,
                                                             btqkv_hi, btqkv_lo, H, DH);
    // idx2: proj weights
    transpose_split<0><<<dim3(32, 8, NLAYERS), tb>>>(Wp, nullptr, nullptr,
                                                     btp_hi, btp_lo, H, H);
    // idx3: QKV GEMM layer 0 (profile target)
    gemm_hmma<0,0><<<dim3(24, 16), 256, GEMM_SMEM>>>(ahi, alo, btqkv_hi, btqkv_lo,
                                                     zb, qkv, nullptr, nullptr, 3072, H);
    // remaining weight transposes
    transpose_split<0><<<dim3(128, 8, NLAYERS), tb>>>(W1, nullptr, nullptr, bt1_hi, bt1_lo, H, FF);
    transpose_split<0><<<dim3(32, 32, NLAYERS), tb>>>(W2, nullptr, nullptr, bt2_hi, bt2_lo, FF, H);
    transpose_f16<<<dim3((Vv + 31) / 32, 8), tb>>>(Wlm, wlm, H, Vv);

    for (int l = 0; l < NLAYERS; l++) {
        size_t oQ = (size_t)l * 3072 * H;
        size_t oH = (size_t)l * H * H;
        size_t oF = (size_t)l * H * FF;

        if (l > 0)
            gemm_hmma<0,0><<<dim3(24, 16), 256, GEMM_SMEM>>>(ahi, alo, btqkv_hi + oQ, btqkv_lo + oQ,
                                                             zb, qkv, nullptr, nullptr, 3072, H);
        ktv_kernel<<<64, 256>>>(qkv, m);
        suf_partial<<<dim3(16, 4), 256>>>(qkv, part);
        suf_apply<<<dim3(16, 4), 256>>>(qkv, part, suf);
        attn_combine<<<dim3(S / 64, NH), 256>>>(qkv, m, suf, ahi, alo);

        gemm_hmma<0,0><<<dim3(8, 16), 256, GEMM_SMEM>>>(ahi, alo, btp_hi + oH, btp_lo + oH,
                                                        bp + (size_t)l * H, tmp, nullptr, nullptr, H, H);
        ln_kernel<true, true, 0><<<S, 256>>>(tmp, x, ln_g, ln_b, res, ahi, alo, nullptr);

        gemm_hmma<1,1><<<dim3(32, 16), 256, GEMM_SMEM>>>(ahi, alo, bt1_hi + oF, bt1_lo + oF,
                                                         b1 + (size_t)l * FF, nullptr, bhi, blo, FF, H);
        gemm_hmma<0,0><<<dim3(8, 16), 256, GEMM_SMEM>>>(bhi, blo, bt2_hi + oF, bt2_lo + oF,
                                                        b2 + (size_t)l * H, tmp, nullptr, nullptr, H, FF);
        ln_kernel<true, true, 0><<<S, 256>>>(tmp, res, ln_g, ln_b, x, ahi, alo, nullptr);
    }

    // final LN -> fp16, LM head in fp16 HMMA
    ln_kernel<false, false, 1><<<S, 256>>>(x, nullptr, ln_g, ln_b, nullptr, nullptr, nullptr, xf16);
    gemm_f16<<<dim3(16, VPAD / 128), 256, F16_SMEM>>>(xf16, wlm, blm, out, Vv, H);
}

// round 6
// speedup vs baseline: 4.4189x; 1.1887x over previous
#include <cuda_runtime.h>
#include <cuda_bf16.h>
#include <cuda_fp16.h>
#include <math.h>
#include <stdint.h>

#define S  2048
#define H  1024
#define NH 16
#define DH 64
#define FF 4096
#define NLAYERS 6
#define VPAD 50432     // 50257 padded to multiple of 128

#define SZ_SH (S*H)

// ---------------- device scratch ----------------
__device__ __align__(16) float g_x[SZ_SH];
__device__ __align__(16) float g_tmp[SZ_SH];
__device__ __align__(16) float g_res[SZ_SH];
__device__ __align__(16) float g_qkv[S*3072];
__device__ __align__(16) float g_suf[SZ_SH];
__device__ __align__(16) float g_m[4*NH*DH*DH];     // split-K partials
__device__ __align__(16) float g_part[16*1024];
__device__ __align__(16) float g_zb[8192];          // zero bias (never written)

// activation hi/lo
__device__ __align__(128) __nv_bfloat16 g_ahi[S*FF];
__device__ __align__(128) __nv_bfloat16 g_alo[S*FF];
__device__ __align__(128) __nv_bfloat16 g_bhi[S*FF];
__device__ __align__(128) __nv_bfloat16 g_blo[S*FF];

// weight hi/lo, K-major transposed [N,K]
__device__ __align__(128) __nv_bfloat16 g_btqkv_hi[NLAYERS*3072*H];
__device__ __align__(128) __nv_bfloat16 g_btqkv_lo[NLAYERS*3072*H];
__device__ __align__(128) __nv_bfloat16 g_btp_hi[NLAYERS*H*H];
__device__ __align__(128) __nv_bfloat16 g_btp_lo[NLAYERS*H*H];
__device__ __align__(128) __nv_bfloat16 g_bt1_hi[NLAYERS*H*FF];
__device__ __align__(128) __nv_bfloat16 g_bt1_lo[NLAYERS*H*FF];
__device__ __align__(128) __nv_bfloat16 g_bt2_hi[NLAYERS*H*FF];
__device__ __align__(128) __nv_bfloat16 g_bt2_lo[NLAYERS*H*FF];
__device__ __align__(128) __half g_wlm_f16[VPAD*H];  // fp16 LM weights, pad rows stay zero
__device__ __align__(128) __half g_xf_f16[SZ_SH];    // fp16 final-LN activations

// ---------------- PTX helpers ----------------
__device__ __forceinline__ uint32_t smem_u32(const void* p) {
    uint32_t a;
    asm("{ .reg .u64 t; cvta.to.shared.u64 t, %1; cvt.u32.u64 %0, t; }" : "=r"(a) : "l"(p));
    return a;
}
__device__ __forceinline__ void cp16(uint32_t dst, const void* src) {
    asm volatile("cp.async.cg.shared.global [%0], [%1], 16;" :: "r"(dst), "l"(src));
}
__device__ __forceinline__ void cp_commit() { asm volatile("cp.async.commit_group;" ::: "memory"); }
template<int N> __device__ __forceinline__ void cp_wait() {
    asm volatile("cp.async.wait_group %0;" :: "n"(N) : "memory");
}
__device__ __forceinline__ void ldsm4(uint32_t& r0, uint32_t& r1, uint32_t& r2, uint32_t& r3,
                                      uint32_t addr) {
    asm volatile("ldmatrix.sync.aligned.m8n8.x4.shared.b16 {%0,%1,%2,%3}, [%4];"
                 : "=r"(r0), "=r"(r1), "=r"(r2), "=r"(r3) : "r"(addr));
}
__device__ __forceinline__ void mma16816(float& d0, float& d1, float& d2, float& d3,
                                         uint32_t a0, uint32_t a1, uint32_t a2, uint32_t a3,
                                         uint32_t b0, uint32_t b1) {
    asm volatile("mma.sync.aligned.m16n8k16.row.col.f32.bf16.bf16.f32 "
                 "{%0,%1,%2,%3}, {%4,%5,%6,%7}, {%8,%9}, {%0,%1,%2,%3};"
                 : "+f"(d0), "+f"(d1), "+f"(d2), "+f"(d3)
                 : "r"(a0), "r"(a1), "r"(a2), "r"(a3), "r"(b0), "r"(b1));
}
__device__ __forceinline__ void mma16816h(float& d0, float& d1, float& d2, float& d3,
                                          uint32_t a0, uint32_t a1, uint32_t a2, uint32_t a3,
                                          uint32_t b0, uint32_t b1) {
    asm volatile("mma.sync.aligned.m16n8k16.row.col.f32.f16.f16.f32 "
                 "{%0,%1,%2,%3}, {%4,%5,%6,%7}, {%8,%9}, {%0,%1,%2,%3};"
                 : "+f"(d0), "+f"(d1), "+f"(d2), "+f"(d3)
                 : "r"(a0), "r"(a1), "r"(a2), "r"(a3), "r"(b0), "r"(b1));
}

__device__ __forceinline__ float gelu_exact(float x) {
    return 0.5f * x * (1.0f + erff(x * 0.70710678118654752f));
}

// swizzled 64B-row offset: row r (0..127), 16B chunk c (0..3)
__device__ __forceinline__ uint32_t swz(uint32_t r, uint32_t c) {
    return r * 64 + ((c ^ ((r >> 1) & 3)) << 4);
}

// pack 4 floats into bf16 hi/lo pairs (8B each)
__device__ __forceinline__ void split4(float o0, float o1, float o2, float o3,
                                       uint2& hv, uint2& lv) {
    __nv_bfloat162 h01 = __floats2bfloat162_rn(o0, o1);
    __nv_bfloat162 h23 = __floats2bfloat162_rn(o2, o3);
    float e0 = o0 - __bfloat162float(h01.x), e1 = o1 - __bfloat162float(h01.y);
    float e2 = o2 - __bfloat162float(h23.x), e3 = o3 - __bfloat162float(h23.y);
    __nv_bfloat162 l01 = __floats2bfloat162_rn(e0, e1);
    __nv_bfloat162 l23 = __floats2bfloat162_rn(e2, e3);
    hv = make_uint2(*(uint32_t*)&h01, *(uint32_t*)&h23);
    lv = make_uint2(*(uint32_t*)&l01, *(uint32_t*)&l23);
}

// ---------------- HMMA GEMM (bf16x3 trunk) ----------------
// CTA 128x128, BK=32, 8 warps (2x4) of 64x32 warp tiles, 3-stage pipeline,
// swizzled 64B rows, 2 CTAs/SM.
#define T_AHI 0
#define T_ALO 8192
#define T_BHI 16384
#define T_BLO 24576
#define STAGE_BYTES 32768
#define GEMM_SMEM (3*STAGE_BYTES)

template<int ACT, int MODE>
__global__ __launch_bounds__(256, 2)
void gemm_hmma(const __nv_bfloat16* __restrict__ Ahi, const __nv_bfloat16* __restrict__ Alo,
               const __nv_bfloat16* __restrict__ Bhi, const __nv_bfloat16* __restrict__ Blo,
               const float* __restrict__ bias, float* __restrict__ C,
               __nv_bfloat16* __restrict__ Chi, __nv_bfloat16* __restrict__ Clo,
               int N, int K) {
    extern __shared__ char smem[];
    const uint32_t sb = smem_u32(smem);
    const int tid  = threadIdx.x;
    const int wid  = tid >> 5;
    const int lane = tid & 31;
    const int wrow = wid & 1;
    const int wcol = wid >> 1;
    const int bm = blockIdx.y << 7;
    const long bn = (long)blockIdx.x << 7;
    const int nc = K >> 5;

    const uint32_t r0t = tid >> 2, c0t = tid & 3;
    const uint32_t r1t = r0t + 64;
    const uint32_t so0 = swz(r0t, c0t);
    const uint32_t so1 = swz(r1t, c0t);

    #define LOAD_STAGE(kc, s) do {                                                     \
        uint32_t st_ = sb + (s) * STAGE_BYTES;                                          \
        {                                                                               \
            size_t ga = ((size_t)(bm + r0t) * K + (kc) * 32 + c0t * 8) * 2;             \
            size_t gb = ((size_t)(bn + r0t) * K + (kc) * 32 + c0t * 8) * 2;             \
            cp16(st_ + T_AHI + so0, (const char*)Ahi + ga);                             \
            cp16(st_ + T_ALO + so0, (const char*)Alo + ga);                             \
            cp16(st_ + T_BHI + so0, (const char*)Bhi + gb);                             \
            cp16(st_ + T_BLO + so0, (const char*)Blo + gb);                             \
        }                                                                               \
        {                                                                               \
            size_t ga = ((size_t)(bm + r1t) * K + (kc) * 32 + c0t * 8) * 2;             \
            size_t gb = ((size_t)(bn + r1t) * K + (kc) * 32 + c0t * 8) * 2;             \
            cp16(st_ + T_AHI + so1, (const char*)Ahi + ga);                             \
            cp16(st_ + T_ALO + so1, (const char*)Alo + ga);                             \
            cp16(st_ + T_BHI + so1, (const char*)Bhi + gb);                             \
            cp16(st_ + T_BLO + so1, (const char*)Blo + gb);                             \
        }                                                                               \
    } while (0)

    LOAD_STAGE(0, 0); cp_commit();
    LOAD_STAGE(1, 1); cp_commit();

    const int lane8 = lane & 7, sub = lane >> 3;
    // A: rows ra + mi*16 (swizzle invariant across mi: 16 rows = +0 mod 4 in (r>>1)&3)
    const uint32_t ra = wrow * 64 + (sub & 1) * 8 + lane8;
    const uint32_t aks0 = swz(ra, (sub >> 1));
    const uint32_t aks1 = swz(ra, (sub >> 1) + 2);
    // B: rows rb + nj*8 (swizzle invariant across nj)
    const uint32_t rb = wcol * 32 + lane8;
    const uint32_t boffs = swz(rb, sub);

    float acc[4][4][4];
    #pragma unroll
    for (int i = 0; i < 4; i++)
        #pragma unroll
        for (int j = 0; j < 4; j++)
            #pragma unroll
            for (int e = 0; e < 4; e++) acc[i][j][e] = 0.f;

    int slot = 0;
    for (int it = 0; it < nc; it++) {
        cp_wait<1>();
        __syncthreads();
        if (it + 2 < nc) {
            int ns = slot + 2; if (ns >= 3) ns -= 3;
            LOAD_STAGE(it + 2, ns);
        }
        cp_commit();
        const uint32_t st = sb + slot * STAGE_BYTES;

        uint32_t bh[4][4], bl[4][4];
        #pragma unroll
        for (int nj = 0; nj < 4; nj++) {
            ldsm4(bh[nj][0], bh[nj][1], bh[nj][2], bh[nj][3], st + T_BHI + boffs + nj * 512);
            ldsm4(bl[nj][0], bl[nj][1], bl[nj][2], bl[nj][3], st + T_BLO + boffs + nj * 512);
        }
        #pragma unroll
        for (int ks = 0; ks < 2; ks++) {
            const uint32_t ao = (ks == 0) ? aks0 : aks1;
            uint32_t a[4][4];
            #pragma unroll
            for (int mi = 0; mi < 4; mi++)
                ldsm4(a[mi][0], a[mi][1], a[mi][2], a[mi][3],
                      st + T_AHI + ao + mi * 1024);
            #pragma unroll
            for (int mi = 0; mi < 4; mi++)
                #pragma unroll
                for (int nj = 0; nj < 4; nj++)
                    mma16816(acc[mi][nj][0], acc[mi][nj][1], acc[mi][nj][2], acc[mi][nj][3],
                             a[mi][0], a[mi][1], a[mi][2], a[mi][3],
                             bh[nj][ks * 2], bh[nj][ks * 2 + 1]);
            #pragma unroll
            for (int mi = 0; mi < 4; mi++)
                #pragma unroll
                for (int nj = 0; nj < 4; nj++)
                    mma16816(acc[mi][nj][0], acc[mi][nj][1], acc[mi][nj][2], acc[mi][nj][3],
                             a[mi][0], a[mi][1], a[mi][2], a[mi][3],
                             bl[nj][ks * 2], bl[nj][ks * 2 + 1]);
            #pragma unroll
            for (int mi = 0; mi < 4; mi++)
                ldsm4(a[mi][0], a[mi][1], a[mi][2], a[mi][3],
                      st + T_ALO + ao + mi * 1024);
            #pragma unroll
            for (int mi = 0; mi < 4; mi++)
                #pragma unroll
                for (int nj = 0; nj < 4; nj++)
                    mma16816(acc[mi][nj][0], acc[mi][nj][1], acc[mi][nj][2], acc[mi][nj][3],
                             a[mi][0], a[mi][1], a[mi][2], a[mi][3],
                             bh[nj][ks * 2], bh[nj][ks * 2 + 1]);
        }
        if (++slot == 3) slot = 0;
    }

    // epilogue
    const int gr = lane >> 2;
    const int gc = (lane & 3) * 2;
    #pragma unroll
    for (int mi = 0; mi < 4; mi++) {
        size_t row0 = (size_t)(bm + wrow * 64 + mi * 16 + gr) * N;
        size_t row1 = row0 + (size_t)8 * N;
        #pragma unroll
        for (int nj = 0; nj < 4; nj++) {
            long c = bn + wcol * 32 + nj * 8 + gc;
            if (MODE == 0) {
                float bsv0 = bias[c], bsv1 = bias[c + 1];
                float v0 = acc[mi][nj][0] + bsv0;
                float v1 = acc[mi][nj][1] + bsv1;
                float v2 = acc[mi][nj][2] + bsv0;
                float v3 = acc[mi][nj][3] + bsv1;
                if (ACT == 1) {
                    v0 = gelu_exact(v0); v1 = gelu_exact(v1);
                    v2 = gelu_exact(v2); v3 = gelu_exact(v3);
                }
                C[row0 + c] = v0; C[row0 + c + 1] = v1;
                C[row1 + c] = v2; C[row1 + c + 1] = v3;
            } else {
                float b0 = bias[c], b1 = bias[c + 1];
                float v0 = acc[mi][nj][0] + b0, v1 = acc[mi][nj][1] + b1;
                float v2 = acc[mi][nj][2] + b0, v3 = acc[mi][nj][3] + b1;
                if (ACT == 1) {
                    v0 = gelu_exact(v0); v1 = gelu_exact(v1);
                    v2 = gelu_exact(v2); v3 = gelu_exact(v3);
                }
                __nv_bfloat162 hp0 = __floats2bfloat162_rn(v0, v1);
                __nv_bfloat162 hp1 = __floats2bfloat162_rn(v2, v3);
                float e0 = v0 - __bfloat162float(hp0.x), e1 = v1 - __bfloat162float(hp0.y);
                float e2 = v2 - __bfloat162float(hp1.x), e3 = v3 - __bfloat162float(hp1.y);
                __nv_bfloat162 lp0 = __floats2bfloat162_rn(e0, e1);
                __nv_bfloat162 lp1 = __floats2bfloat162_rn(e2, e3);
                *(uint32_t*)(Chi + row0 + c) = *(uint32_t*)&hp0;
                *(uint32_t*)(Clo + row0 + c) = *(uint32_t*)&lp0;
                *(uint32_t*)(Chi + row1 + c) = *(uint32_t*)&hp1;
                *(uint32_t*)(Clo + row1 + c) = *(uint32_t*)&lp1;
            }
        }
    }
    #undef LOAD_STAGE
}

// ---------------- fp16 single-term GEMM (LM head) ----------------
#define F_TA 0
#define F_TB 8192
#define F_STAGE 16384
#define F16_SMEM (3*F_STAGE)

__global__ __launch_bounds__(256, 2)
void gemm_f16(const __half* __restrict__ A, const __half* __restrict__ B,
              const float* __restrict__ bias, float* __restrict__ C, int N, int K) {
    extern __shared__ char smem[];
    const uint32_t sb = smem_u32(smem);
    const int tid  = threadIdx.x;
    const int wid  = tid >> 5;
    const int lane = tid & 31;
    const int wrow = wid & 1;
    const int wcol = wid >> 1;
    const int bm = blockIdx.x << 7;
    const long bn = (long)blockIdx.y << 7;
    const int nc = K >> 5;

    const uint32_t r0t = tid >> 2, c0t = tid & 3;
    const uint32_t r1t = r0t + 64;
    const uint32_t so0 = swz(r0t, c0t);
    const uint32_t so1 = swz(r1t, c0t);

    #define LOAD_STAGE_F(kc, s) do {                                                   \
        uint32_t st_ = sb + (s) * F_STAGE;                                              \
        {                                                                               \
            size_t ga = ((size_t)(bm + r0t) * K + (kc) * 32 + c0t * 8) * 2;             \
            size_t gb = ((size_t)(bn + r0t) * K + (kc) * 32 + c0t * 8) * 2;             \
            cp16(st_ + F_TA + so0, (const char*)A + ga);                                \
            cp16(st_ + F_TB + so0, (const char*)B + gb);                                \
        }                                                                               \
        {                                                                               \
            size_t ga = ((size_t)(bm + r1t) * K + (kc) * 32 + c0t * 8) * 2;             \
            size_t gb = ((size_t)(bn + r1t) * K + (kc) * 32 + c0t * 8) * 2;             \
            cp16(st_ + F_TA + so1, (const char*)A + ga);                                \
            cp16(st_ + F_TB + so1, (const char*)B + gb);                                \
        }                                                                               \
    } while (0)

    LOAD_STAGE_F(0, 0); cp_commit();
    LOAD_STAGE_F(1, 1); cp_commit();

    const int lane8 = lane & 7, sub = lane >> 3;
    const uint32_t ra = wrow * 64 + (sub & 1) * 8 + lane8;
    const uint32_t aks0 = swz(ra, (sub >> 1));
    const uint32_t aks1 = swz(ra, (sub >> 1) + 2);
    const uint32_t rb = wcol * 32 + lane8;
    const uint32_t boffs = swz(rb, sub);

    float acc[4][4][4];
    #pragma unroll
    for (int i = 0; i < 4; i++)
        #pragma unroll
        for (int j = 0; j < 4; j++)
            #pragma unroll
            for (int e = 0; e < 4; e++) acc[i][j][e] = 0.f;

    int slot = 0;
    for (int it = 0; it < nc; it++) {
        cp_wait<1>();
        __syncthreads();
        if (it + 2 < nc) {
            int ns = slot + 2; if (ns >= 3) ns -= 3;
            LOAD_STAGE_F(it + 2, ns);
        }
        cp_commit();
        const uint32_t st = sb + slot * F_STAGE;

        uint32_t bf[4][4];
        #pragma unroll
        for (int nj = 0; nj < 4; nj++)
            ldsm4(bf[nj][0], bf[nj][1], bf[nj][2], bf[nj][3], st + F_TB + boffs + nj * 512);
        #pragma unroll
        for (int ks = 0; ks < 2; ks++) {
            const uint32_t ao = (ks == 0) ? aks0 : aks1;
            uint32_t a[4][4];
            #pragma unroll
            for (int mi = 0; mi < 4; mi++)
                ldsm4(a[mi][0], a[mi][1], a[mi][2], a[mi][3], st + F_TA + ao + mi * 1024);
            #pragma unroll
            for (int mi = 0; mi < 4; mi++)
                #pragma unroll
                for (int nj = 0; nj < 4; nj++)
                    mma16816h(acc[mi][nj][0], acc[mi][nj][1], acc[mi][nj][2], acc[mi][nj][3],
                              a[mi][0], a[mi][1], a[mi][2], a[mi][3],
                              bf[nj][ks * 2], bf[nj][ks * 2 + 1]);
        }
        if (++slot == 3) slot = 0;
    }

    const int gr = lane >> 2;
    const int gc = (lane & 3) * 2;
    #pragma unroll
    for (int mi = 0; mi < 4; mi++) {
        size_t row0 = (size_t)(bm + wrow * 64 + mi * 16 + gr) * N;
        size_t row1 = row0 + (size_t)8 * N;
        #pragma unroll
        for (int nj = 0; nj < 4; nj++) {
            long c = bn + wcol * 32 + nj * 8 + gc;
            if (c < N) {
                C[row0 + c] = acc[mi][nj][0] + bias[c];
                C[row1 + c] = acc[mi][nj][2] + bias[c];
            }
            if (c + 1 < N) {
                C[row0 + c + 1] = acc[mi][nj][1] + bias[c + 1];
                C[row1 + c + 1] = acc[mi][nj][3] + bias[c + 1];
            }
        }
    }
    #undef LOAD_STAGE_F
}

// ---------------- weight transpose + split (bf16 hi/lo) ----------------
template<int QKV>
__global__ __launch_bounds__(256)
void transpose_split(const float* __restrict__ src0, const float* __restrict__ src1,
                     const float* __restrict__ src2,
                     __nv_bfloat16* __restrict__ hi, __nv_bfloat16* __restrict__ lo,
                     int R, int C) {
    __shared__ float t[128][33];
    int z = blockIdx.z;
    const float* src = src0;
    int sel = 0;
    if (QKV) {
        sel = z / (NLAYERS * NH);
        z   = z % (NLAYERS * NH);
        src = (sel == 0) ? src0 : (sel == 1) ? src1 : src2;
    }
    const size_t ib = (size_t)z * R * C;
    size_t ob;
    if (QKV) ob = (size_t)(z >> 4) * (3072 * 1024) + (size_t)sel * (1024 * 1024)
                + (size_t)(z & 15) * (64 * 1024);
    else     ob = ib;
    const int r0 = blockIdx.y * 128, c0 = blockIdx.x * 32;
    const int cc = threadIdx.x & 31, rb = threadIdx.x >> 5;
    const bool cok = (c0 + cc) < C;
    #pragma unroll
    for (int p = 0; p < 16; p++) {
        int rr = rb + p * 8;
        t[rr][cc] = cok ? src[ib + (size_t)(r0 + rr) * C + c0 + cc] : 0.f;
    }
    __syncthreads();
    const int oc = threadIdx.x >> 3, rq8 = threadIdx.x & 7;
    if (c0 + oc < C) {
        size_t obase = ob + (size_t)(c0 + oc) * R + r0;
        #pragma unroll
        for (int p = 0; p < 4; p++) {
            int r = (rq8 + p * 8) * 4;
            uint2 hv, lv;
            split4(t[r][oc], t[r + 1][oc], t[r + 2][oc], t[r + 3][oc], hv, lv);
            *(uint2*)(hi + obase + r) = hv;
            *(uint2*)(lo + obase + r) = lv;
        }
    }
}

// ---------------- fp16 weight transpose (LM head) ----------------
__global__ __launch_bounds__(256)
void transpose_f16(const float* __restrict__ src, __half* __restrict__ out, int R, int C) {
    __shared__ float t[128][33];
    const int r0 = blockIdx.y * 128, c0 = blockIdx.x * 32;
    const int cc = threadIdx.x & 31, rb = threadIdx.x >> 5;
    const bool cok = (c0 + cc) < C;
    #pragma unroll
    for (int p = 0; p < 16; p++) {
        int rr = rb + p * 8;
        t[rr][cc] = cok ? src[(size_t)(r0 + rr) * C + c0 + cc] : 0.f;
    }
    __syncthreads();
    const int oc = threadIdx.x >> 3, rq8 = threadIdx.x & 7;
    if (c0 + oc < C) {
        size_t obase = (size_t)(c0 + oc) * R + r0;
        #pragma unroll
        for (int p = 0; p < 4; p++) {
            int r = (rq8 + p * 8) * 4;
            __half2 h0 = __floats2half2_rn(t[r][oc], t[r + 1][oc]);
            __half2 h1 = __floats2half2_rn(t[r + 2][oc], t[r + 3][oc]);
            *(uint2*)(out + obase + r) = make_uint2(*(uint32_t*)&h0, *(uint32_t*)&h1);
        }
    }
}

// ---------------- embedding: x = emb[tok] + pos, + split ----------------
__global__ void embed_kernel(const int* __restrict__ tok, const float* __restrict__ emb,
                             const float* __restrict__ pos, float* __restrict__ x,
                             __nv_bfloat16* __restrict__ hi, __nv_bfloat16* __restrict__ lo) {
    int i4 = blockIdx.x * 256 + threadIdx.x;
    int e = i4 * 4;
    int s = e >> 10, h = e & 1023;
    float4 ev = *(const float4*)(emb + (size_t)tok[s] * H + h);
    float4 pv = *(const float4*)(pos + e);
    float o0 = ev.x + pv.x, o1 = ev.y + pv.y, o2 = ev.z + pv.z, o3 = ev.w + pv.w;
    *(float4*)(x + e) = make_float4(o0, o1, o2, o3);
    uint2 hv, lv;
    split4(o0, o1, o2, o3, hv, lv);
    *(uint2*)(hi + e) = hv;
    *(uint2*)(lo + e) = lv;
}

// ---------------- M_part = K^T V per (head, seg); qkv layout [S, 3072] ----------------
__global__ __launch_bounds__(256)
void ktv_kernel(const float* __restrict__ qkv, float* __restrict__ mp) {
    const int head = blockIdx.x & 15, seg = blockIdx.x >> 4;
    __shared__ float Ks[64][65];
    __shared__ float Vs[64][65];
    const int tid = threadIdx.x;
    const int tr = tid >> 4, tc = tid & 15;
    float acc[4][4] = {};
    for (int t0 = seg * 512; t0 < seg * 512 + 512; t0 += 64) {
        for (int i = tid; i < 4096; i += 256) {
            int r = i >> 6, c = i & 63;
            size_t base = (size_t)(t0 + r) * 3072 + head * DH + c;
            Ks[r][c] = qkv[base + 1024];
            Vs[r][c] = qkv[base + 2048];
        }
        __syncthreads();
        #pragma unroll 4
        for (int t = 0; t < 64; t++) {
            float a[4], b[4];
            #pragma unroll
            for (int i = 0; i < 4; i++) a[i] = Ks[t][tr * 4 + i];
            #pragma unroll
            for (int j = 0; j < 4; j++) b[j] = Vs[t][tc * 4 + j];
            #pragma unroll
            for (int i = 0; i < 4; i++)
                #pragma unroll
                for (int j = 0; j < 4; j++)
                    acc[i][j] = fmaf(a[i], b[j], acc[i][j]);
        }
        __syncthreads();
    }
    #pragma unroll
    for (int i = 0; i < 4; i++)
        #pragma unroll
        for (int j = 0; j < 4; j++)
            mp[(size_t)(seg * 16 + head) * 4096 + (tr * 4 + i) * 64 + tc * 4 + j] = acc[i][j];
}

// ---------------- parallel suffix sum of V over S ----------------
__global__ void suf_partial(const float* __restrict__ qkv, float* __restrict__ part) {
    int col = blockIdx.y * 256 + threadIdx.x;
    int seg = blockIdx.x;
    float s = 0.f;
    for (int t = seg * 128; t < seg * 128 + 128; t++)
        s += qkv[(size_t)t * 3072 + 2048 + col];
    part[seg * 1024 + col] = s;
}
__global__ void suf_apply(const float* __restrict__ qkv, const float* __restrict__ part,
                          float* __restrict__ suf) {
    int col = blockIdx.y * 256 + threadIdx.x;
    int seg = blockIdx.x;
    float run = 0.f;
    for (int s2 = seg + 1; s2 < 16; s2++) run += part[s2 * 1024 + col];
    for (int t = seg * 128 + 127; t >= seg * 128; t--) {
        suf[(size_t)t * 1024 + col] = run;
        run += qkv[(size_t)t * 3072 + 2048 + col];
    }
}

// ---------------- attn = scale*(Q@M) - 1e9*suf, emit hi/lo split ----------------
__global__ __launch_bounds__(256)
void attn_combine(const float* __restrict__ qkv, const float* __restrict__ mp,
                  const float* __restrict__ suf,
                  __nv_bfloat16* __restrict__ ahi, __nv_bfloat16* __restrict__ alo) {
    const int head = blockIdx.y;
    const int s0 = blockIdx.x * 64;
    __shared__ float Qs[64][65];
    __shared__ float Ms[64][65];
    const int tid = threadIdx.x;
    for (int i = tid; i < 4096; i += 256) {
        int r = i >> 6, c = i & 63;
        Qs[r][c] = qkv[(size_t)(s0 + r) * 3072 + head * DH + c];
        float mv = 0.f;
        #pragma unroll
        for (int sg = 0; sg < 4; sg++) mv += mp[(size_t)(sg * 16 + head) * 4096 + i];
        Ms[r][c] = mv;
    }
    __syncthreads();
    const int tr = tid >> 4, tc = tid & 15;
    float acc[4][4] = {};
    #pragma unroll 4
    for (int hp = 0; hp < 64; hp++) {
        float a[4], b[4];
        #pragma unroll
        for (int i = 0; i < 4; i++) a[i] = Qs[tr * 4 + i][hp];
        #pragma unroll
        for (int j = 0; j < 4; j++) b[j] = Ms[hp][tc * 4 + j];
        #pragma unroll
        for (int i = 0; i < 4; i++)
            #pragma unroll
            for (int j = 0; j < 4; j++)
                acc[i][j] = fmaf(a[i], b[j], acc[i][j]);
    }
    #pragma unroll
    for (int i = 0; i < 4; i++) {
        int s = s0 + tr * 4 + i;
        size_t sb = (size_t)s * 1024 + head * DH + tc * 4;
        float o[4];
        #pragma unroll
        for (int j = 0; j < 4; j++)
            o[j] = 0.125f * acc[i][j] - 1e9f * suf[sb + j];
        uint2 hv, lv;
        split4(o[0], o[1], o[2], o[3], hv, lv);
        *(uint2*)(ahi + sb) = hv;
        *(uint2*)(alo + sb) = lv;
    }
}

// ---------------- LayerNorm (+residual) + fused split ----------------
template<bool ADD, bool WF32, int OUTK>
__global__ __launch_bounds__(256)
void ln_kernel(const float* __restrict__ t, const float* __restrict__ xin,
               const float* __restrict__ g, const float* __restrict__ b,
               float* __restrict__ outf,
               __nv_bfloat16* __restrict__ hi, __nv_bfloat16* __restrict__ lo,
               __half* __restrict__ outh) {
    const int row = blockIdx.x;
    const int tid = threadIdx.x;
    float4 v = *(const float4*)(t + (size_t)row * H + tid * 4);
    __shared__ float red[256];
    __shared__ float stat[2];

    float s = v.x + v.y + v.z + v.w;
    red[tid] = s; __syncthreads();
    for (int o = 128; o > 0; o >>= 1) {
        if (tid < o) red[tid] += red[tid + o];
        __syncthreads();
    }
    if (tid == 0) stat[0] = red[0] * (1.0f / H);
    __syncthreads();
    float mean = stat[0];

    float dx = v.x - mean, dy = v.y - mean, dz = v.z - mean, dw = v.w - mean;
    red[tid] = dx * dx + dy * dy + dz * dz + dw * dw; __syncthreads();
    for (int o = 128; o > 0; o >>= 1) {
        if (tid < o) red[tid] += red[tid + o];
        __syncthreads();
    }
    if (tid == 0) stat[1] = rsqrtf(red[0] * (1.0f / H) + 1e-5f);
    __syncthreads();
    float rstd = stat[1];

    int h = tid * 4;
    float4 gv = *(const float4*)(g + h);
    float4 bv = *(const float4*)(b + h);
    float o0 = dx * rstd * gv.x + bv.x;
    float o1 = dy * rstd * gv.y + bv.y;
    float o2 = dz * rstd * gv.z + bv.z;
    float o3 = dw * rstd * gv.w + bv.w;
    if (ADD) {
        float4 xv = *(const float4*)(xin + (size_t)row * H + h);
        o0 += xv.x; o1 += xv.y; o2 += xv.z; o3 += xv.w;
    }
    if (WF32) *(float4*)(outf + (size_t)row * H + h) = make_float4(o0, o1, o2, o3);
    if (OUTK == 0) {
        uint2 hv, lv;
        split4(o0, o1, o2, o3, hv, lv);
        *(uint2*)(hi + (size_t)row * H + h) = hv;
        *(uint2*)(lo + (size_t)row * H + h) = lv;
    } else {
        __half2 h0 = __floats2half2_rn(o0, o1);
        __half2 h1 = __floats2half2_rn(o2, o3);
        *(uint2*)(outh + (size_t)row * H + h) = make_uint2(*(uint32_t*)&h0, *(uint32_t*)&h1);
    }
}

// ---------------- launch ----------------
extern "C" void kernel_launch(void* const* d_in, const int* in_sizes, int n_in,
                              void* d_out, int out_size) {
    const int*   tokens = (const int*)  d_in[0];
    const float* emb    = (const float*)d_in[1];
    const float* pos    = (const float*)d_in[2];
    const float* Wq     = (const float*)d_in[3];
    const float* Wk     = (const float*)d_in[4];
    const float* Wv     = (const float*)d_in[5];
    const float* Wp     = (const float*)d_in[6];
    const float* bp     = (const float*)d_in[7];
    const float* W1     = (const float*)d_in[8];
    const float* b1     = (const float*)d_in[9];
    const float* W2     = (const float*)d_in[10];
    const float* b2     = (const float*)d_in[11];
    const float* ln_g   = (const float*)d_in[12];
    const float* ln_b   = (const float*)d_in[13];
    const float* Wlm    = (const float*)d_in[14];
    const float* blm    = (const float*)d_in[15];
    float* out = (float*)d_out;
    const int Vv = in_sizes[15];

    float *x, *tmp, *res, *qkv, *suf, *m, *part, *zb;
    __nv_bfloat16 *ahi, *alo, *bhi, *blo;
    __nv_bfloat16 *btqkv_hi, *btqkv_lo, *btp_hi, *btp_lo;
    __nv_bfloat16 *bt1_hi, *bt1_lo, *bt2_hi, *bt2_lo;
    __half *wlm, *xf16;
    cudaGetSymbolAddress((void**)&x, g_x);       cudaGetSymbolAddress((void**)&tmp, g_tmp);
    cudaGetSymbolAddress((void**)&res, g_res);   cudaGetSymbolAddress((void**)&qkv, g_qkv);
    cudaGetSymbolAddress((void**)&suf, g_suf);   cudaGetSymbolAddress((void**)&m, g_m);
    cudaGetSymbolAddress((void**)&part, g_part); cudaGetSymbolAddress((void**)&zb, g_zb);
    cudaGetSymbolAddress((void**)&ahi, g_ahi);   cudaGetSymbolAddress((void**)&alo, g_alo);
    cudaGetSymbolAddress((void**)&bhi, g_bhi);   cudaGetSymbolAddress((void**)&blo, g_blo);
    cudaGetSymbolAddress((void**)&btqkv_hi, g_btqkv_hi);
    cudaGetSymbolAddress((void**)&btqkv_lo, g_btqkv_lo);
    cudaGetSymbolAddress((void**)&btp_hi, g_btp_hi); cudaGetSymbolAddress((void**)&btp_lo, g_btp_lo);
    cudaGetSymbolAddress((void**)&bt1_hi, g_bt1_hi); cudaGetSymbolAddress((void**)&bt1_lo, g_bt1_lo);
    cudaGetSymbolAddress((void**)&bt2_hi, g_bt2_hi); cudaGetSymbolAddress((void**)&bt2_lo, g_bt2_lo);
    cudaGetSymbolAddress((void**)&wlm, g_wlm_f16);   cudaGetSymbolAddress((void**)&xf16, g_xf_f16);

    cudaFuncSetAttribute(gemm_hmma<0,0>, cudaFuncAttributeMaxDynamicSharedMemorySize, GEMM_SMEM);
    cudaFuncSetAttribute(gemm_hmma<1,1>, cudaFuncAttributeMaxDynamicSharedMemorySize, GEMM_SMEM);
    cudaFuncSetAttribute(gemm_f16, cudaFuncAttributeMaxDynamicSharedMemorySize, F16_SMEM);

    dim3 tb(256);
    // idx0: embed
    embed_kernel<<<(S * H) / 1024, 256>>>(tokens, emb, pos, x, ahi, alo);
    // idx1: combined qkv weight transpose
    transpose_split<1><<<dim3(2, 8, 3 * NLAYERS * NH), tb>>>(Wq, Wk, Wv,
                                                             btqkv_hi, btqkv_lo, H, DH);
    // idx2: proj weights
    transpose_split<0><<<dim3(32, 8, NLAYERS), tb>>>(Wp, nullptr, nullptr,
                                                     btp_hi, btp_lo, H, H);
    // idx3: QKV GEMM layer 0 (profile target)
    gemm_hmma<0,0><<<dim3(24, 16), 256, GEMM_SMEM>>>(ahi, alo, btqkv_hi, btqkv_lo,
                                                     zb, qkv, nullptr, nullptr, 3072, H);
    // remaining weight transposes
    transpose_split<0><<<dim3(128, 8, NLAYERS), tb>>>(W1, nullptr, nullptr, bt1_hi, bt1_lo, H, FF);
    transpose_split<0><<<dim3(32, 32, NLAYERS), tb>>>(W2, nullptr, nullptr, bt2_hi, bt2_lo, FF, H);
    transpose_f16<<<dim3((Vv + 31) / 32, 8), tb>>>(Wlm, wlm, H, Vv);

    for (int l = 0; l < NLAYERS; l++) {
        size_t oQ = (size_t)l * 3072 * H;
        size_t oH = (size_t)l * H * H;
        size_t oF = (size_t)l * H * FF;

        if (l > 0)
            gemm_hmma<0,0><<<dim3(24, 16), 256, GEMM_SMEM>>>(ahi, alo, btqkv_hi + oQ, btqkv_lo + oQ,
                                                             zb, qkv, nullptr, nullptr, 3072, H);
        ktv_kernel<<<64, 256>>>(qkv, m);
        suf_partial<<<dim3(16, 4), 256>>>(qkv, part);
        suf_apply<<<dim3(16, 4), 256>>>(qkv, part, suf);
        attn_combine<<<dim3(S / 64, NH), 256>>>(qkv, m, suf, ahi, alo);

        gemm_hmma<0,0><<<dim3(8, 16), 256, GEMM_SMEM>>>(ahi, alo, btp_hi + oH, btp_lo + oH,
                                                        bp + (size_t)l * H, tmp, nullptr, nullptr, H, H);
        ln_kernel<true, true, 0><<<S, 256>>>(tmp, x, ln_g, ln_b, res, ahi, alo, nullptr);

        gemm_hmma<1,1><<<dim3(32, 16), 256, GEMM_SMEM>>>(ahi, alo, bt1_hi + oF, bt1_lo + oF,
                                                         b1 + (size_t)l * FF, nullptr, bhi, blo, FF, H);
        gemm_hmma<0,0><<<dim3(8, 16), 256, GEMM_SMEM>>>(bhi, blo, bt2_hi + oF, bt2_lo + oF,
                                                        b2 + (size_t)l * H, tmp, nullptr, nullptr, H, FF);
        ln_kernel<true, true, 0><<<S, 256>>>(tmp, res, ln_g, ln_b, x, ahi, alo, nullptr);
    }

    // final LN -> fp16, LM head in fp16 HMMA
    ln_kernel<false, false, 1><<<S, 256>>>(x, nullptr, ln_g, ln_b, nullptr, nullptr, nullptr, xf16);
    gemm_f16<<<dim3(16, VPAD / 128), 256, F16_SMEM>>>(xf16, wlm, blm, out, Vv, H);
}

// round 7
// speedup vs baseline: 4.6273x; 1.0472x over previous
#include <cuda_runtime.h>
#include <cuda_bf16.h>
#include <cuda_fp16.h>
#include <math.h>
#include <stdint.h>

#define S  2048
#define H  1024
#define NH 16
#define DH 64
#define FF 4096
#define NLAYERS 6
#define VPAD 50432     // 50257 padded to multiple of 128

#define SZ_SH (S*H)

// ---------------- device scratch ----------------
__device__ __align__(16) float g_x[SZ_SH];
__device__ __align__(16) float g_tmp[SZ_SH];
__device__ __align__(16) float g_res[SZ_SH];
__device__ __align__(16) float g_qkv[S*3072];
__device__ __align__(16) float g_suf[SZ_SH];
__device__ __align__(16) float g_m[8*NH*DH*DH];     // split-K partials
__device__ __align__(16) float g_part[16*1024];
__device__ __align__(16) float g_zb[8192];          // zero bias (never written)

// activation hi/lo
__device__ __align__(128) __nv_bfloat16 g_ahi[S*FF];
__device__ __align__(128) __nv_bfloat16 g_alo[S*FF];
__device__ __align__(128) __nv_bfloat16 g_bhi[S*FF];
__device__ __align__(128) __nv_bfloat16 g_blo[S*FF];

// weight hi/lo, K-major transposed [N,K]
__device__ __align__(128) __nv_bfloat16 g_btqkv_hi[NLAYERS*3072*H];
__device__ __align__(128) __nv_bfloat16 g_btqkv_lo[NLAYERS*3072*H];
__device__ __align__(128) __nv_bfloat16 g_btp_hi[NLAYERS*H*H];
__device__ __align__(128) __nv_bfloat16 g_btp_lo[NLAYERS*H*H];
__device__ __align__(128) __nv_bfloat16 g_bt1_hi[NLAYERS*H*FF];
__device__ __align__(128) __nv_bfloat16 g_bt1_lo[NLAYERS*H*FF];
__device__ __align__(128) __nv_bfloat16 g_bt2_hi[NLAYERS*H*FF];
__device__ __align__(128) __nv_bfloat16 g_bt2_lo[NLAYERS*H*FF];
__device__ __align__(128) __half g_wlm_f16[VPAD*H];  // fp16 LM weights, pad rows stay zero
__device__ __align__(128) __half g_xf_f16[SZ_SH];    // fp16 final-LN activations

// ---------------- PTX helpers ----------------
__device__ __forceinline__ uint32_t smem_u32(const void* p) {
    uint32_t a;
    asm("{ .reg .u64 t; cvta.to.shared.u64 t, %1; cvt.u32.u64 %0, t; }" : "=r"(a) : "l"(p));
    return a;
}
__device__ __forceinline__ void cp16(uint32_t dst, const void* src) {
    asm volatile("cp.async.cg.shared.global [%0], [%1], 16;" :: "r"(dst), "l"(src));
}
__device__ __forceinline__ void cp_commit() { asm volatile("cp.async.commit_group;" ::: "memory"); }
template<int N> __device__ __forceinline__ void cp_wait() {
    asm volatile("cp.async.wait_group %0;" :: "n"(N) : "memory");
}
__device__ __forceinline__ void ldsm4(uint32_t& r0, uint32_t& r1, uint32_t& r2, uint32_t& r3,
                                      uint32_t addr) {
    asm volatile("ldmatrix.sync.aligned.m8n8.x4.shared.b16 {%0,%1,%2,%3}, [%4];"
                 : "=r"(r0), "=r"(r1), "=r"(r2), "=r"(r3) : "r"(addr));
}
__device__ __forceinline__ void mma16816(float& d0, float& d1, float& d2, float& d3,
                                         uint32_t a0, uint32_t a1, uint32_t a2, uint32_t a3,
                                         uint32_t b0, uint32_t b1) {
    asm volatile("mma.sync.aligned.m16n8k16.row.col.f32.bf16.bf16.f32 "
                 "{%0,%1,%2,%3}, {%4,%5,%6,%7}, {%8,%9}, {%0,%1,%2,%3};"
                 : "+f"(d0), "+f"(d1), "+f"(d2), "+f"(d3)
                 : "r"(a0), "r"(a1), "r"(a2), "r"(a3), "r"(b0), "r"(b1));
}
__device__ __forceinline__ void mma16816h(float& d0, float& d1, float& d2, float& d3,
                                          uint32_t a0, uint32_t a1, uint32_t a2, uint32_t a3,
                                          uint32_t b0, uint32_t b1) {
    asm volatile("mma.sync.aligned.m16n8k16.row.col.f32.f16.f16.f32 "
                 "{%0,%1,%2,%3}, {%4,%5,%6,%7}, {%8,%9}, {%0,%1,%2,%3};"
                 : "+f"(d0), "+f"(d1), "+f"(d2), "+f"(d3)
                 : "r"(a0), "r"(a1), "r"(a2), "r"(a3), "r"(b0), "r"(b1));
}

__device__ __forceinline__ float gelu_exact(float x) {
    return 0.5f * x * (1.0f + erff(x * 0.70710678118654752f));
}

// swizzled 64B-row offset: row r, 16B chunk c (0..3)
__device__ __forceinline__ uint32_t swz(uint32_t r, uint32_t c) {
    return r * 64 + ((c ^ ((r >> 1) & 3)) << 4);
}

// pack 4 floats into bf16 hi/lo pairs (8B each)
__device__ __forceinline__ void split4(float o0, float o1, float o2, float o3,
                                       uint2& hv, uint2& lv) {
    __nv_bfloat162 h01 = __floats2bfloat162_rn(o0, o1);
    __nv_bfloat162 h23 = __floats2bfloat162_rn(o2, o3);
    float e0 = o0 - __bfloat162float(h01.x), e1 = o1 - __bfloat162float(h01.y);
    float e2 = o2 - __bfloat162float(h23.x), e3 = o3 - __bfloat162float(h23.y);
    __nv_bfloat162 l01 = __floats2bfloat162_rn(e0, e1);
    __nv_bfloat162 l23 = __floats2bfloat162_rn(e2, e3);
    hv = make_uint2(*(uint32_t*)&h01, *(uint32_t*)&h23);
    lv = make_uint2(*(uint32_t*)&l01, *(uint32_t*)&l23);
}

// ---------------- TM64 HMMA GEMM (bf16x3): CTA 64x128, BK=32 ----------------
// 8 warps (2x4) of 32x32 tiles. fp32 out + bias. N mult of 128, M mult of 64.
#define S64_AHI 0
#define S64_ALO 4096
#define S64_BHI 8192
#define S64_BLO 16384
#define STAGE64 24576
#define GEMM64_SMEM (3*STAGE64)

__global__ __launch_bounds__(256, 2)
void gemm_hmma64(const __nv_bfloat16* __restrict__ Ahi, const __nv_bfloat16* __restrict__ Alo,
                 const __nv_bfloat16* __restrict__ Bhi, const __nv_bfloat16* __restrict__ Blo,
                 const float* __restrict__ bias, float* __restrict__ C, int N, int K) {
    extern __shared__ char smem[];
    const uint32_t sb = smem_u32(smem);
    const int tid  = threadIdx.x;
    const int wid  = tid >> 5;
    const int lane = tid & 31;
    const int wrow = wid & 1;          // 32-row slab
    const int wcol = wid >> 1;         // 32-col slab
    const int bm = blockIdx.y << 6;
    const long bn = (long)blockIdx.x << 7;
    const int nc = K >> 5;

    const uint32_t rt = tid >> 2, ct = tid & 3;
    const uint32_t soA  = swz(rt, ct);
    const uint32_t soB0 = swz(rt, ct);
    const uint32_t soB1 = swz(rt + 64, ct);

    #define LOAD_STAGE64(kc, s) do {                                                   \
        uint32_t st_ = sb + (s) * STAGE64;                                              \
        size_t ga  = ((size_t)(bm + rt) * K + (kc) * 32 + ct * 8) * 2;                  \
        size_t gb0 = ((size_t)(bn + rt) * K + (kc) * 32 + ct * 8) * 2;                  \
        size_t gb1 = ((size_t)(bn + rt + 64) * K + (kc) * 32 + ct * 8) * 2;             \
        cp16(st_ + S64_AHI + soA,  (const char*)Ahi + ga);                              \
        cp16(st_ + S64_ALO + soA,  (const char*)Alo + ga);                              \
        cp16(st_ + S64_BHI + soB0, (const char*)Bhi + gb0);                             \
        cp16(st_ + S64_BLO + soB0, (const char*)Blo + gb0);                             \
        cp16(st_ + S64_BHI + soB1, (const char*)Bhi + gb1);                             \
        cp16(st_ + S64_BLO + soB1, (const char*)Blo + gb1);                             \
    } while (0)

    LOAD_STAGE64(0, 0); cp_commit();
    LOAD_STAGE64(1, 1); cp_commit();

    const int lane8 = lane & 7, sub = lane >> 3;
    const uint32_t ra = wrow * 32 + (sub & 1) * 8 + lane8;
    const uint32_t aks0 = swz(ra, (sub >> 1));
    const uint32_t aks1 = swz(ra, (sub >> 1) + 2);
    const uint32_t rb = wcol * 32 + lane8;
    const uint32_t boffs = swz(rb, sub);

    float acc[2][4][4];
    #pragma unroll
    for (int i = 0; i < 2; i++)
        #pragma unroll
        for (int j = 0; j < 4; j++)
            #pragma unroll
            for (int e = 0; e < 4; e++) acc[i][j][e] = 0.f;

    int slot = 0;
    for (int it = 0; it < nc; it++) {
        cp_wait<1>();
        __syncthreads();
        if (it + 2 < nc) {
            int ns = slot + 2; if (ns >= 3) ns -= 3;
            LOAD_STAGE64(it + 2, ns);
        }
        cp_commit();
        const uint32_t st = sb + slot * STAGE64;

        uint32_t bh[4][4], bl[4][4];
        #pragma unroll
        for (int nj = 0; nj < 4; nj++) {
            ldsm4(bh[nj][0], bh[nj][1], bh[nj][2], bh[nj][3], st + S64_BHI + boffs + nj * 512);
            ldsm4(bl[nj][0], bl[nj][1], bl[nj][2], bl[nj][3], st + S64_BLO + boffs + nj * 512);
        }
        #pragma unroll
        for (int ks = 0; ks < 2; ks++) {
            const uint32_t ao = (ks == 0) ? aks0 : aks1;
            uint32_t a[2][4];
            #pragma unroll
            for (int mi = 0; mi < 2; mi++)
                ldsm4(a[mi][0], a[mi][1], a[mi][2], a[mi][3], st + S64_AHI + ao + mi * 1024);
            #pragma unroll
            for (int mi = 0; mi < 2; mi++)
                #pragma unroll
                for (int nj = 0; nj < 4; nj++)
                    mma16816(acc[mi][nj][0], acc[mi][nj][1], acc[mi][nj][2], acc[mi][nj][3],
                             a[mi][0], a[mi][1], a[mi][2], a[mi][3],
                             bh[nj][ks * 2], bh[nj][ks * 2 + 1]);
            #pragma unroll
            for (int mi = 0; mi < 2; mi++)
                #pragma unroll
                for (int nj = 0; nj < 4; nj++)
                    mma16816(acc[mi][nj][0], acc[mi][nj][1], acc[mi][nj][2], acc[mi][nj][3],
                             a[mi][0], a[mi][1], a[mi][2], a[mi][3],
                             bl[nj][ks * 2], bl[nj][ks * 2 + 1]);
            #pragma unroll
            for (int mi = 0; mi < 2; mi++)
                ldsm4(a[mi][0], a[mi][1], a[mi][2], a[mi][3], st + S64_ALO + ao + mi * 1024);
            #pragma unroll
            for (int mi = 0; mi < 2; mi++)
                #pragma unroll
                for (int nj = 0; nj < 4; nj++)
                    mma16816(acc[mi][nj][0], acc[mi][nj][1], acc[mi][nj][2], acc[mi][nj][3],
                             a[mi][0], a[mi][1], a[mi][2], a[mi][3],
                             bh[nj][ks * 2], bh[nj][ks * 2 + 1]);
        }
        if (++slot == 3) slot = 0;
    }

    const int gr = lane >> 2;
    const int gc = (lane & 3) * 2;
    #pragma unroll
    for (int mi = 0; mi < 2; mi++) {
        size_t row0 = (size_t)(bm + wrow * 32 + mi * 16 + gr) * N;
        size_t row1 = row0 + (size_t)8 * N;
        #pragma unroll
        for (int nj = 0; nj < 4; nj++) {
            long c = bn + wcol * 32 + nj * 8 + gc;
            float b0 = bias[c], b1 = bias[c + 1];
            C[row0 + c]     = acc[mi][nj][0] + b0;
            C[row0 + c + 1] = acc[mi][nj][1] + b1;
            C[row1 + c]     = acc[mi][nj][2] + b0;
            C[row1 + c + 1] = acc[mi][nj][3] + b1;
        }
    }
    #undef LOAD_STAGE64
}

// ---------------- TM128 HMMA GEMM (bf16x3, MLP1: gelu + bf16 hi/lo out) ----------------
#define T_AHI 0
#define T_ALO 8192
#define T_BHI 16384
#define T_BLO 24576
#define STAGE_BYTES 32768
#define GEMM_SMEM (3*STAGE_BYTES)

__global__ __launch_bounds__(256, 2)
void gemm_hmma_mlp1(const __nv_bfloat16* __restrict__ Ahi, const __nv_bfloat16* __restrict__ Alo,
                    const __nv_bfloat16* __restrict__ Bhi, const __nv_bfloat16* __restrict__ Blo,
                    const float* __restrict__ bias,
                    __nv_bfloat16* __restrict__ Chi, __nv_bfloat16* __restrict__ Clo,
                    int N, int K) {
    extern __shared__ char smem[];
    const uint32_t sb = smem_u32(smem);
    const int tid  = threadIdx.x;
    const int wid  = tid >> 5;
    const int lane = tid & 31;
    const int wrow = wid & 1;
    const int wcol = wid >> 1;
    const int bm = blockIdx.y << 7;
    const long bn = (long)blockIdx.x << 7;
    const int nc = K >> 5;

    const uint32_t r0t = tid >> 2, c0t = tid & 3;
    const uint32_t r1t = r0t + 64;
    const uint32_t so0 = swz(r0t, c0t);
    const uint32_t so1 = swz(r1t, c0t);

    #define LOAD_STAGE(kc, s) do {                                                     \
        uint32_t st_ = sb + (s) * STAGE_BYTES;                                          \
        {                                                                               \
            size_t ga = ((size_t)(bm + r0t) * K + (kc) * 32 + c0t * 8) * 2;             \
            size_t gb = ((size_t)(bn + r0t) * K + (kc) * 32 + c0t * 8) * 2;             \
            cp16(st_ + T_AHI + so0, (const char*)Ahi + ga);                             \
            cp16(st_ + T_ALO + so0, (const char*)Alo + ga);                             \
            cp16(st_ + T_BHI + so0, (const char*)Bhi + gb);                             \
            cp16(st_ + T_BLO + so0, (const char*)Blo + gb);                             \
        }                                                                               \
        {                                                                               \
            size_t ga = ((size_t)(bm + r1t) * K + (kc) * 32 + c0t * 8) * 2;             \
            size_t gb = ((size_t)(bn + r1t) * K + (kc) * 32 + c0t * 8) * 2;             \
            cp16(st_ + T_AHI + so1, (const char*)Ahi + ga);                             \
            cp16(st_ + T_ALO + so1, (const char*)Alo + ga);                             \
            cp16(st_ + T_BHI + so1, (const char*)Bhi + gb);                             \
            cp16(st_ + T_BLO + so1, (const char*)Blo + gb);                             \
        }                                                                               \
    } while (0)

    LOAD_STAGE(0, 0); cp_commit();
    LOAD_STAGE(1, 1); cp_commit();

    const int lane8 = lane & 7, sub = lane >> 3;
    const uint32_t ra = wrow * 64 + (sub & 1) * 8 + lane8;
    const uint32_t aks0 = swz(ra, (sub >> 1));
    const uint32_t aks1 = swz(ra, (sub >> 1) + 2);
    const uint32_t rb = wcol * 32 + lane8;
    const uint32_t boffs = swz(rb, sub);

    float acc[4][4][4];
    #pragma unroll
    for (int i = 0; i < 4; i++)
        #pragma unroll
        for (int j = 0; j < 4; j++)
            #pragma unroll
            for (int e = 0; e < 4; e++) acc[i][j][e] = 0.f;

    int slot = 0;
    for (int it = 0; it < nc; it++) {
        cp_wait<1>();
        __syncthreads();
        if (it + 2 < nc) {
            int ns = slot + 2; if (ns >= 3) ns -= 3;
            LOAD_STAGE(it + 2, ns);
        }
        cp_commit();
        const uint32_t st = sb + slot * STAGE_BYTES;

        uint32_t bh[4][4], bl[4][4];
        #pragma unroll
        for (int nj = 0; nj < 4; nj++) {
            ldsm4(bh[nj][0], bh[nj][1], bh[nj][2], bh[nj][3], st + T_BHI + boffs + nj * 512);
            ldsm4(bl[nj][0], bl[nj][1], bl[nj][2], bl[nj][3], st + T_BLO + boffs + nj * 512);
        }
        #pragma unroll
        for (int ks = 0; ks < 2; ks++) {
            const uint32_t ao = (ks == 0) ? aks0 : aks1;
            uint32_t a[4][4];
            #pragma unroll
            for (int mi = 0; mi < 4; mi++)
                ldsm4(a[mi][0], a[mi][1], a[mi][2], a[mi][3], st + T_AHI + ao + mi * 1024);
            #pragma unroll
            for (int mi = 0; mi < 4; mi++)
                #pragma unroll
                for (int nj = 0; nj < 4; nj++)
                    mma16816(acc[mi][nj][0], acc[mi][nj][1], acc[mi][nj][2], acc[mi][nj][3],
                             a[mi][0], a[mi][1], a[mi][2], a[mi][3],
                             bh[nj][ks * 2], bh[nj][ks * 2 + 1]);
            #pragma unroll
            for (int mi = 0; mi < 4; mi++)
                #pragma unroll
                for (int nj = 0; nj < 4; nj++)
                    mma16816(acc[mi][nj][0], acc[mi][nj][1], acc[mi][nj][2], acc[mi][nj][3],
                             a[mi][0], a[mi][1], a[mi][2], a[mi][3],
                             bl[nj][ks * 2], bl[nj][ks * 2 + 1]);
            #pragma unroll
            for (int mi = 0; mi < 4; mi++)
                ldsm4(a[mi][0], a[mi][1], a[mi][2], a[mi][3], st + T_ALO + ao + mi * 1024);
            #pragma unroll
            for (int mi = 0; mi < 4; mi++)
                #pragma unroll
                for (int nj = 0; nj < 4; nj++)
                    mma16816(acc[mi][nj][0], acc[mi][nj][1], acc[mi][nj][2], acc[mi][nj][3],
                             a[mi][0], a[mi][1], a[mi][2], a[mi][3],
                             bh[nj][ks * 2], bh[nj][ks * 2 + 1]);
        }
        if (++slot == 3) slot = 0;
    }

    const int gr = lane >> 2;
    const int gc = (lane & 3) * 2;
    #pragma unroll
    for (int mi = 0; mi < 4; mi++) {
        size_t row0 = (size_t)(bm + wrow * 64 + mi * 16 + gr) * N;
        size_t row1 = row0 + (size_t)8 * N;
        #pragma unroll
        for (int nj = 0; nj < 4; nj++) {
            long c = bn + wcol * 32 + nj * 8 + gc;
            float b0 = bias[c], b1 = bias[c + 1];
            float v0 = gelu_exact(acc[mi][nj][0] + b0);
            float v1 = gelu_exact(acc[mi][nj][1] + b1);
            float v2 = gelu_exact(acc[mi][nj][2] + b0);
            float v3 = gelu_exact(acc[mi][nj][3] + b1);
            __nv_bfloat162 hp0 = __floats2bfloat162_rn(v0, v1);
            __nv_bfloat162 hp1 = __floats2bfloat162_rn(v2, v3);
            float e0 = v0 - __bfloat162float(hp0.x), e1 = v1 - __bfloat162float(hp0.y);
            float e2 = v2 - __bfloat162float(hp1.x), e3 = v3 - __bfloat162float(hp1.y);
            __nv_bfloat162 lp0 = __floats2bfloat162_rn(e0, e1);
            __nv_bfloat162 lp1 = __floats2bfloat162_rn(e2, e3);
            *(uint32_t*)(Chi + row0 + c) = *(uint32_t*)&hp0;
            *(uint32_t*)(Clo + row0 + c) = *(uint32_t*)&lp0;
            *(uint32_t*)(Chi + row1 + c) = *(uint32_t*)&hp1;
            *(uint32_t*)(Clo + row1 + c) = *(uint32_t*)&lp1;
        }
    }
    #undef LOAD_STAGE
}

// ---------------- fp16 single-term GEMM (LM head) ----------------
#define F_TA 0
#define F_TB 8192
#define F_STAGE 16384
#define F16_SMEM (3*F_STAGE)

__global__ __launch_bounds__(256, 2)
void gemm_f16(const __half* __restrict__ A, const __half* __restrict__ B,
              const float* __restrict__ bias, float* __restrict__ C, int N, int K) {
    extern __shared__ char smem[];
    const uint32_t sb = smem_u32(smem);
    const int tid  = threadIdx.x;
    const int wid  = tid >> 5;
    const int lane = tid & 31;
    const int wrow = wid & 1;
    const int wcol = wid >> 1;
    const int bm = blockIdx.x << 7;
    const long bn = (long)blockIdx.y << 7;
    const int nc = K >> 5;

    const uint32_t r0t = tid >> 2, c0t = tid & 3;
    const uint32_t r1t = r0t + 64;
    const uint32_t so0 = swz(r0t, c0t);
    const uint32_t so1 = swz(r1t, c0t);

    #define LOAD_STAGE_F(kc, s) do {                                                   \
        uint32_t st_ = sb + (s) * F_STAGE;                                              \
        {                                                                               \
            size_t ga = ((size_t)(bm + r0t) * K + (kc) * 32 + c0t * 8) * 2;             \
            size_t gb = ((size_t)(bn + r0t) * K + (kc) * 32 + c0t * 8) * 2;             \
            cp16(st_ + F_TA + so0, (const char*)A + ga);                                \
            cp16(st_ + F_TB + so0, (const char*)B + gb);                                \
        }                                                                               \
        {                                                                               \
            size_t ga = ((size_t)(bm + r1t) * K + (kc) * 32 + c0t * 8) * 2;             \
            size_t gb = ((size_t)(bn + r1t) * K + (kc) * 32 + c0t * 8) * 2;             \
            cp16(st_ + F_TA + so1, (const char*)A + ga);                                \
            cp16(st_ + F_TB + so1, (const char*)B + gb);                                \
        }                                                                               \
    } while (0)

    LOAD_STAGE_F(0, 0); cp_commit();
    LOAD_STAGE_F(1, 1); cp_commit();

    const int lane8 = lane & 7, sub = lane >> 3;
    const uint32_t ra = wrow * 64 + (sub & 1) * 8 + lane8;
    const uint32_t aks0 = swz(ra, (sub >> 1));
    const uint32_t aks1 = swz(ra, (sub >> 1) + 2);
    const uint32_t rb = wcol * 32 + lane8;
    const uint32_t boffs = swz(rb, sub);

    float acc[4][4][4];
    #pragma unroll
    for (int i = 0; i < 4; i++)
        #pragma unroll
        for (int j = 0; j < 4; j++)
            #pragma unroll
            for (int e = 0; e < 4; e++) acc[i][j][e] = 0.f;

    int slot = 0;
    for (int it = 0; it < nc; it++) {
        cp_wait<1>();
        __syncthreads();
        if (it + 2 < nc) {
            int ns = slot + 2; if (ns >= 3) ns -= 3;
            LOAD_STAGE_F(it + 2, ns);
        }
        cp_commit();
        const uint32_t st = sb + slot * F_STAGE;

        uint32_t bf[4][4];
        #pragma unroll
        for (int nj = 0; nj < 4; nj++)
            ldsm4(bf[nj][0], bf[nj][1], bf[nj][2], bf[nj][3], st + F_TB + boffs + nj * 512);
        #pragma unroll
        for (int ks = 0; ks < 2; ks++) {
            const uint32_t ao = (ks == 0) ? aks0 : aks1;
            uint32_t a[4][4];
            #pragma unroll
            for (int mi = 0; mi < 4; mi++)
                ldsm4(a[mi][0], a[mi][1], a[mi][2], a[mi][3], st + F_TA + ao + mi * 1024);
            #pragma unroll
            for (int mi = 0; mi < 4; mi++)
                #pragma unroll
                for (int nj = 0; nj < 4; nj++)
                    mma16816h(acc[mi][nj][0], acc[mi][nj][1], acc[mi][nj][2], acc[mi][nj][3],
                              a[mi][0], a[mi][1], a[mi][2], a[mi][3],
                              bf[nj][ks * 2], bf[nj][ks * 2 + 1]);
        }
        if (++slot == 3) slot = 0;
    }

    const int gr = lane >> 2;
    const int gc = (lane & 3) * 2;
    #pragma unroll
    for (int mi = 0; mi < 4; mi++) {
        size_t row0 = (size_t)(bm + wrow * 64 + mi * 16 + gr) * N;
        size_t row1 = row0 + (size_t)8 * N;
        #pragma unroll
        for (int nj = 0; nj < 4; nj++) {
            long c = bn + wcol * 32 + nj * 8 + gc;
            if (c < N) {
                C[row0 + c] = acc[mi][nj][0] + bias[c];
                C[row1 + c] = acc[mi][nj][2] + bias[c];
            }
            if (c + 1 < N) {
                C[row0 + c + 1] = acc[mi][nj][1] + bias[c + 1];
                C[row1 + c + 1] = acc[mi][nj][3] + bias[c + 1];
            }
        }
    }
    #undef LOAD_STAGE_F
}

// ---------------- weight transpose + split (bf16 hi/lo) ----------------
template<int QKV>
__global__ __launch_bounds__(256)
void transpose_split(const float* __restrict__ src0, const float* __restrict__ src1,
                     const float* __restrict__ src2,
                     __nv_bfloat16* __restrict__ hi, __nv_bfloat16* __restrict__ lo,
                     int R, int C) {
    __shared__ float t[128][33];
    int z = blockIdx.z;
    const float* src = src0;
    int sel = 0;
    if (QKV) {
        sel = z / (NLAYERS * NH);
        z   = z % (NLAYERS * NH);
        src = (sel == 0) ? src0 : (sel == 1) ? src1 : src2;
    }
    const size_t ib = (size_t)z * R * C;
    size_t ob;
    if (QKV) ob = (size_t)(z >> 4) * (3072 * 1024) + (size_t)sel * (1024 * 1024)
                + (size_t)(z & 15) * (64 * 1024);
    else     ob = ib;
    const int r0 = blockIdx.y * 128, c0 = blockIdx.x * 32;
    const int cc = threadIdx.x & 31, rb = threadIdx.x >> 5;
    const bool cok = (c0 + cc) < C;
    #pragma unroll
    for (int p = 0; p < 16; p++) {
        int rr = rb + p * 8;
        t[rr][cc] = cok ? src[ib + (size_t)(r0 + rr) * C + c0 + cc] : 0.f;
    }
    __syncthreads();
    const int oc = threadIdx.x >> 3, rq8 = threadIdx.x & 7;
    if (c0 + oc < C) {
        size_t obase = ob + (size_t)(c0 + oc) * R + r0;
        #pragma unroll
        for (int p = 0; p < 4; p++) {
            int r = (rq8 + p * 8) * 4;
            uint2 hv, lv;
            split4(t[r][oc], t[r + 1][oc], t[r + 2][oc], t[r + 3][oc], hv, lv);
            *(uint2*)(hi + obase + r) = hv;
            *(uint2*)(lo + obase + r) = lv;
        }
    }
}

// ---------------- fp16 weight transpose (LM head) ----------------
__global__ __launch_bounds__(256)
void transpose_f16(const float* __restrict__ src, __half* __restrict__ out, int R, int C) {
    __shared__ float t[128][33];
    const int r0 = blockIdx.y * 128, c0 = blockIdx.x * 32;
    const int cc = threadIdx.x & 31, rb = threadIdx.x >> 5;
    const bool cok = (c0 + cc) < C;
    #pragma unroll
    for (int p = 0; p < 16; p++) {
        int rr = rb + p * 8;
        t[rr][cc] = cok ? src[(size_t)(r0 + rr) * C + c0 + cc] : 0.f;
    }
    __syncthreads();
    const int oc = threadIdx.x >> 3, rq8 = threadIdx.x & 7;
    if (c0 + oc < C) {
        size_t obase = (size_t)(c0 + oc) * R + r0;
        #pragma unroll
        for (int p = 0; p < 4; p++) {
            int r = (rq8 + p * 8) * 4;
            __half2 h0 = __floats2half2_rn(t[r][oc], t[r + 1][oc]);
            __half2 h1 = __floats2half2_rn(t[r + 2][oc], t[r + 3][oc]);
            *(uint2*)(out + obase + r) = make_uint2(*(uint32_t*)&h0, *(uint32_t*)&h1);
        }
    }
}

// ---------------- embedding: x = emb[tok] + pos, + split ----------------
__global__ void embed_kernel(const int* __restrict__ tok, const float* __restrict__ emb,
                             const float* __restrict__ pos, float* __restrict__ x,
                             __nv_bfloat16* __restrict__ hi, __nv_bfloat16* __restrict__ lo) {
    int i4 = blockIdx.x * 256 + threadIdx.x;
    int e = i4 * 4;
    int s = e >> 10, h = e & 1023;
    float4 ev = *(const float4*)(emb + (size_t)tok[s] * H + h);
    float4 pv = *(const float4*)(pos + e);
    float o0 = ev.x + pv.x, o1 = ev.y + pv.y, o2 = ev.z + pv.z, o3 = ev.w + pv.w;
    *(float4*)(x + e) = make_float4(o0, o1, o2, o3);
    uint2 hv, lv;
    split4(o0, o1, o2, o3, hv, lv);
    *(uint2*)(hi + e) = hv;
    *(uint2*)(lo + e) = lv;
}

// ---------------- M_part = K^T V per (head, seg); 8 segs ----------------
__global__ __launch_bounds__(256)
void ktv_kernel(const float* __restrict__ qkv, float* __restrict__ mp) {
    const int head = blockIdx.x & 15, seg = blockIdx.x >> 4;   // seg 0..7
    __shared__ float Ks[64][65];
    __shared__ float Vs[64][65];
    const int tid = threadIdx.x;
    const int tr = tid >> 4, tc = tid & 15;
    float acc[4][4] = {};
    for (int t0 = seg * 256; t0 < seg * 256 + 256; t0 += 64) {
        for (int i = tid; i < 4096; i += 256) {
            int r = i >> 6, c = i & 63;
            size_t base = (size_t)(t0 + r) * 3072 + head * DH + c;
            Ks[r][c] = qkv[base + 1024];
            Vs[r][c] = qkv[base + 2048];
        }
        __syncthreads();
        #pragma unroll 4
        for (int t = 0; t < 64; t++) {
            float a[4], b[4];
            #pragma unroll
            for (int i = 0; i < 4; i++) a[i] = Ks[t][tr * 4 + i];
            #pragma unroll
            for (int j = 0; j < 4; j++) b[j] = Vs[t][tc * 4 + j];
            #pragma unroll
            for (int i = 0; i < 4; i++)
                #pragma unroll
                for (int j = 0; j < 4; j++)
                    acc[i][j] = fmaf(a[i], b[j], acc[i][j]);
        }
        __syncthreads();
    }
    #pragma unroll
    for (int i = 0; i < 4; i++)
        #pragma unroll
        for (int j = 0; j < 4; j++)
            mp[(size_t)(seg * 16 + head) * 4096 + (tr * 4 + i) * 64 + tc * 4 + j] = acc[i][j];
}

// ---------------- parallel suffix sum of V over S ----------------
__global__ void suf_partial(const float* __restrict__ qkv, float* __restrict__ part) {
    int col = blockIdx.y * 256 + threadIdx.x;
    int seg = blockIdx.x;
    float s = 0.f;
    for (int t = seg * 128; t < seg * 128 + 128; t++)
        s += qkv[(size_t)t * 3072 + 2048 + col];
    part[seg * 1024 + col] = s;
}
__global__ void suf_apply(const float* __restrict__ qkv, const float* __restrict__ part,
                          float* __restrict__ suf) {
    int col = blockIdx.y * 256 + threadIdx.x;
    int seg = blockIdx.x;
    float run = 0.f;
    for (int s2 = seg + 1; s2 < 16; s2++) run += part[s2 * 1024 + col];
    for (int t = seg * 128 + 127; t >= seg * 128; t--) {
        suf[(size_t)t * 1024 + col] = run;
        run += qkv[(size_t)t * 3072 + 2048 + col];
    }
}

// ---------------- attn = scale*(Q@M) - 1e9*suf, emit hi/lo split ----------------
__global__ __launch_bounds__(256)
void attn_combine(const float* __restrict__ qkv, const float* __restrict__ mp,
                  const float* __restrict__ suf,
                  __nv_bfloat16* __restrict__ ahi, __nv_bfloat16* __restrict__ alo) {
    const int head = blockIdx.y;
    const int s0 = blockIdx.x * 64;
    __shared__ float Qs[64][65];
    __shared__ float Ms[64][65];
    const int tid = threadIdx.x;
    for (int i = tid; i < 4096; i += 256) {
        int r = i >> 6, c = i & 63;
        Qs[r][c] = qkv[(size_t)(s0 + r) * 3072 + head * DH + c];
        float mv = 0.f;
        #pragma unroll
        for (int sg = 0; sg < 8; sg++) mv += mp[(size_t)(sg * 16 + head) * 4096 + i];
        Ms[r][c] = mv;
    }
    __syncthreads();
    const int tr = tid >> 4, tc = tid & 15;
    float acc[4][4] = {};
    #pragma unroll 4
    for (int hp = 0; hp < 64; hp++) {
        float a[4], b[4];
        #pragma unroll
        for (int i = 0; i < 4; i++) a[i] = Qs[tr * 4 + i][hp];
        #pragma unroll
        for (int j = 0; j < 4; j++) b[j] = Ms[hp][tc * 4 + j];
        #pragma unroll
        for (int i = 0; i < 4; i++)
            #pragma unroll
            for (int j = 0; j < 4; j++)
                acc[i][j] = fmaf(a[i], b[j], acc[i][j]);
    }
    #pragma unroll
    for (int i = 0; i < 4; i++) {
        int s = s0 + tr * 4 + i;
        size_t sb = (size_t)s * 1024 + head * DH + tc * 4;
        float o[4];
        #pragma unroll
        for (int j = 0; j < 4; j++)
            o[j] = 0.125f * acc[i][j] - 1e9f * suf[sb + j];
        uint2 hv, lv;
        split4(o[0], o[1], o[2], o[3], hv, lv);
        *(uint2*)(ahi + sb) = hv;
        *(uint2*)(alo + sb) = lv;
    }
}

// ---------------- LayerNorm (+residual) + fused split ----------------
template<bool ADD, bool WF32, int OUTK>
__global__ __launch_bounds__(256)
void ln_kernel(const float* __restrict__ t, const float* __restrict__ xin,
               const float* __restrict__ g, const float* __restrict__ b,
               float* __restrict__ outf,
               __nv_bfloat16* __restrict__ hi, __nv_bfloat16* __restrict__ lo,
               __half* __restrict__ outh) {
    const int row = blockIdx.x;
    const int tid = threadIdx.x;
    float4 v = *(const float4*)(t + (size_t)row * H + tid * 4);
    __shared__ float red[256];
    __shared__ float stat[2];

    float s = v.x + v.y + v.z + v.w;
    red[tid] = s; __syncthreads();
    for (int o = 128; o > 0; o >>= 1) {
        if (tid < o) red[tid] += red[tid + o];
        __syncthreads();
    }
    if (tid == 0) stat[0] = red[0] * (1.0f / H);
    __syncthreads();
    float mean = stat[0];

    float dx = v.x - mean, dy = v.y - mean, dz = v.z - mean, dw = v.w - mean;
    red[tid] = dx * dx + dy * dy + dz * dz + dw * dw; __syncthreads();
    for (int o = 128; o > 0; o >>= 1) {
        if (tid < o) red[tid] += red[tid + o];
        __syncthreads();
    }
    if (tid == 0) stat[1] = rsqrtf(red[0] * (1.0f / H) + 1e-5f);
    __syncthreads();
    float rstd = stat[1];

    int h = tid * 4;
    float4 gv = *(const float4*)(g + h);
    float4 bv = *(const float4*)(b + h);
    float o0 = dx * rstd * gv.x + bv.x;
    float o1 = dy * rstd * gv.y + bv.y;
    float o2 = dz * rstd * gv.z + bv.z;
    float o3 = dw * rstd * gv.w + bv.w;
    if (ADD) {
        float4 xv = *(const float4*)(xin + (size_t)row * H + h);
        o0 += xv.x; o1 += xv.y; o2 += xv.z; o3 += xv.w;
    }
    if (WF32) *(float4*)(outf + (size_t)row * H + h) = make_float4(o0, o1, o2, o3);
    if (OUTK == 0) {
        uint2 hv, lv;
        split4(o0, o1, o2, o3, hv, lv);
        *(uint2*)(hi + (size_t)row * H + h) = hv;
        *(uint2*)(lo + (size_t)row * H + h) = lv;
    } else {
        __half2 h0 = __floats2half2_rn(o0, o1);
        __half2 h1 = __floats2half2_rn(o2, o3);
        *(uint2*)(outh + (size_t)row * H + h) = make_uint2(*(uint32_t*)&h0, *(uint32_t*)&h1);
    }
}

// ---------------- launch ----------------
extern "C" void kernel_launch(void* const* d_in, const int* in_sizes, int n_in,
                              void* d_out, int out_size) {
    const int*   tokens = (const int*)  d_in[0];
    const float* emb    = (const float*)d_in[1];
    const float* pos    = (const float*)d_in[2];
    const float* Wq     = (const float*)d_in[3];
    const float* Wk     = (const float*)d_in[4];
    const float* Wv     = (const float*)d_in[5];
    const float* Wp     = (const float*)d_in[6];
    const float* bp     = (const float*)d_in[7];
    const float* W1     = (const float*)d_in[8];
    const float* b1     = (const float*)d_in[9];
    const float* W2     = (const float*)d_in[10];
    const float* b2     = (const float*)d_in[11];
    const float* ln_g   = (const float*)d_in[12];
    const float* ln_b   = (const float*)d_in[13];
    const float* Wlm    = (const float*)d_in[14];
    const float* blm    = (const float*)d_in[15];
    float* out = (float*)d_out;
    const int Vv = in_sizes[15];

    float *x, *tmp, *res, *qkv, *suf, *m, *part, *zb;
    __nv_bfloat16 *ahi, *alo, *bhi, *blo;
    __nv_bfloat16 *btqkv_hi, *btqkv_lo, *btp_hi, *btp_lo;
    __nv_bfloat16 *bt1_hi, *bt1_lo, *bt2_hi, *bt2_lo;
    __half *wlm, *xf16;
    cudaGetSymbolAddress((void**)&x, g_x);       cudaGetSymbolAddress((void**)&tmp, g_tmp);
    cudaGetSymbolAddress((void**)&res, g_res);   cudaGetSymbolAddress((void**)&qkv, g_qkv);
    cudaGetSymbolAddress((void**)&suf, g_suf);   cudaGetSymbolAddress((void**)&m, g_m);
    cudaGetSymbolAddress((void**)&part, g_part); cudaGetSymbolAddress((void**)&zb, g_zb);
    cudaGetSymbolAddress((void**)&ahi, g_ahi);   cudaGetSymbolAddress((void**)&alo, g_alo);
    cudaGetSymbolAddress((void**)&bhi, g_bhi);   cudaGetSymbolAddress((void**)&blo, g_blo);
    cudaGetSymbolAddress((void**)&btqkv_hi, g_btqkv_hi);
    cudaGetSymbolAddress((void**)&btqkv_lo, g_btqkv_lo);
    cudaGetSymbolAddress((void**)&btp_hi, g_btp_hi); cudaGetSymbolAddress((void**)&btp_lo, g_btp_lo);
    cudaGetSymbolAddress((void**)&bt1_hi, g_bt1_hi); cudaGetSymbolAddress((void**)&bt1_lo, g_bt1_lo);
    cudaGetSymbolAddress((void**)&bt2_hi, g_bt2_hi); cudaGetSymbolAddress((void**)&bt2_lo, g_bt2_lo);
    cudaGetSymbolAddress((void**)&wlm, g_wlm_f16);   cudaGetSymbolAddress((void**)&xf16, g_xf_f16);

    cudaFuncSetAttribute(gemm_hmma64, cudaFuncAttributeMaxDynamicSharedMemorySize, GEMM64_SMEM);
    cudaFuncSetAttribute(gemm_hmma_mlp1, cudaFuncAttributeMaxDynamicSharedMemorySize, GEMM_SMEM);
    cudaFuncSetAttribute(gemm_f16, cudaFuncAttributeMaxDynamicSharedMemorySize, F16_SMEM);

    dim3 tb(256);
    // idx0: embed
    embed_kernel<<<(S * H) / 1024, 256>>>(tokens, emb, pos, x, ahi, alo);
    // idx1: combined qkv weight transpose
    transpose_split<1><<<dim3(2, 8, 3 * NLAYERS * NH), tb>>>(Wq, Wk, Wv,
                                                             btqkv_hi, btqkv_lo, H, DH);
    // idx2: proj weights
    transpose_split<0><<<dim3(32, 8, NLAYERS), tb>>>(Wp, nullptr, nullptr,
                                                     btp_hi, btp_lo, H, H);
    // idx3: QKV GEMM layer 0 (profile target)
    gemm_hmma64<<<dim3(24, 32), 256, GEMM64_SMEM>>>(ahi, alo, btqkv_hi, btqkv_lo,
                                                    zb, qkv, 3072, H);
    // remaining weight transposes
    transpose_split<0><<<dim3(128, 8, NLAYERS), tb>>>(W1, nullptr, nullptr, bt1_hi, bt1_lo, H, FF);
    transpose_split<0><<<dim3(32, 32, NLAYERS), tb>>>(W2, nullptr, nullptr, bt2_hi, bt2_lo, FF, H);
    transpose_f16<<<dim3((Vv + 31) / 32, 8), tb>>>(Wlm, wlm, H, Vv);

    for (int l = 0; l < NLAYERS; l++) {
        size_t oQ = (size_t)l * 3072 * H;
        size_t oH = (size_t)l * H * H;
        size_t oF = (size_t)l * H * FF;

        if (l > 0)
            gemm_hmma64<<<dim3(24, 32), 256, GEMM64_SMEM>>>(ahi, alo, btqkv_hi + oQ, btqkv_lo + oQ,
                                                            zb, qkv, 3072, H);
        ktv_kernel<<<128, 256>>>(qkv, m);
        suf_partial<<<dim3(16, 4), 256>>>(qkv, part);
        suf_apply<<<dim3(16, 4), 256>>>(qkv, part, suf);
        attn_combine<<<dim3(S / 64, NH), 256>>>(qkv, m, suf, ahi, alo);

        gemm_hmma64<<<dim3(8, 32), 256, GEMM64_SMEM>>>(ahi, alo, btp_hi + oH, btp_lo + oH,
                                                       bp + (size_t)l * H, tmp, H, H);
        ln_kernel<true, true, 0><<<S, 256>>>(tmp, x, ln_g, ln_b, res, ahi, alo, nullptr);

        gemm_hmma_mlp1<<<dim3(32, 16), 256, GEMM_SMEM>>>(ahi, alo, bt1_hi + oF, bt1_lo + oF,
                                                         b1 + (size_t)l * FF, bhi, blo, FF, H);
        gemm_hmma64<<<dim3(8, 32), 256, GEMM64_SMEM>>>(bhi, blo, bt2_hi + oF, bt2_lo + oF,
                                                       b2 + (size_t)l * H, tmp, H, FF);
        ln_kernel<true, true, 0><<<S, 256>>>(tmp, res, ln_g, ln_b, x, ahi, alo, nullptr);
    }

    // final LN -> fp16, LM head in fp16 HMMA
    ln_kernel<false, false, 1><<<S, 256>>>(x, nullptr, ln_g, ln_b, nullptr, nullptr, nullptr, xf16);
    gemm_f16<<<dim3(16, VPAD / 128), 256, F16_SMEM>>>(xf16, wlm, blm, out, Vv, H);
}

// round 8
// speedup vs baseline: 4.7380x; 1.0239x over previous
#include <cuda_runtime.h>
#include <cuda_bf16.h>
#include <cuda_fp16.h>
#include <math.h>
#include <stdint.h>

#define S  2048
#define H  1024
#define NH 16
#define DH 64
#define FF 4096
#define NLAYERS 6
#define VPAD 50432     // 50257 padded to multiple of 128

#define SZ_SH (S*H)

// ---------------- device scratch ----------------
__device__ __align__(16) float g_x[SZ_SH];
__device__ __align__(16) float g_tmp[SZ_SH];
__device__ __align__(16) float g_res[SZ_SH];
__device__ __align__(16) float g_qkv[S*3072];
__device__ __align__(16) float g_suf[SZ_SH];
__device__ __align__(16) float g_m[8*NH*DH*DH];     // split-K partials
__device__ __align__(16) float g_part[16*1024];
__device__ __align__(16) float g_zb[8192];          // zero bias (never written)

// activation hi/lo
__device__ __align__(128) __nv_bfloat16 g_ahi[S*FF];
__device__ __align__(128) __nv_bfloat16 g_alo[S*FF];
__device__ __align__(128) __nv_bfloat16 g_bhi[S*FF];
__device__ __align__(128) __nv_bfloat16 g_blo[S*FF];

// weight hi/lo, K-major transposed [N,K]
__device__ __align__(128) __nv_bfloat16 g_btqkv_hi[NLAYERS*3072*H];
__device__ __align__(128) __nv_bfloat16 g_btqkv_lo[NLAYERS*3072*H];
__device__ __align__(128) __nv_bfloat16 g_btp_hi[NLAYERS*H*H];
__device__ __align__(128) __nv_bfloat16 g_btp_lo[NLAYERS*H*H];
__device__ __align__(128) __nv_bfloat16 g_bt1_hi[NLAYERS*H*FF];
__device__ __align__(128) __nv_bfloat16 g_bt1_lo[NLAYERS*H*FF];
__device__ __align__(128) __nv_bfloat16 g_bt2_hi[NLAYERS*H*FF];
__device__ __align__(128) __nv_bfloat16 g_bt2_lo[NLAYERS*H*FF];
__device__ __align__(128) __half g_wlm_f16[VPAD*H];  // fp16 LM weights, pad rows stay zero
__device__ __align__(128) __half g_xf_f16[SZ_SH];    // fp16 final-LN activations

// ---------------- PTX helpers ----------------
__device__ __forceinline__ uint32_t smem_u32(const void* p) {
    uint32_t a;
    asm("{ .reg .u64 t; cvta.to.shared.u64 t, %1; cvt.u32.u64 %0, t; }" : "=r"(a) : "l"(p));
    return a;
}
__device__ __forceinline__ void cp16(uint32_t dst, const void* src) {
    asm volatile("cp.async.cg.shared.global [%0], [%1], 16;" :: "r"(dst), "l"(src));
}
__device__ __forceinline__ void cp_commit() { asm volatile("cp.async.commit_group;" ::: "memory"); }
template<int N> __device__ __forceinline__ void cp_wait() {
    asm volatile("cp.async.wait_group %0;" :: "n"(N) : "memory");
}
__device__ __forceinline__ void ldsm4(uint32_t& r0, uint32_t& r1, uint32_t& r2, uint32_t& r3,
                                      uint32_t addr) {
    asm volatile("ldmatrix.sync.aligned.m8n8.x4.shared.b16 {%0,%1,%2,%3}, [%4];"
                 : "=r"(r0), "=r"(r1), "=r"(r2), "=r"(r3) : "r"(addr));
}
__device__ __forceinline__ void mma16816(float& d0, float& d1, float& d2, float& d3,
                                         uint32_t a0, uint32_t a1, uint32_t a2, uint32_t a3,
                                         uint32_t b0, uint32_t b1) {
    asm volatile("mma.sync.aligned.m16n8k16.row.col.f32.bf16.bf16.f32 "
                 "{%0,%1,%2,%3}, {%4,%5,%6,%7}, {%8,%9}, {%0,%1,%2,%3};"
                 : "+f"(d0), "+f"(d1), "+f"(d2), "+f"(d3)
                 : "r"(a0), "r"(a1), "r"(a2), "r"(a3), "r"(b0), "r"(b1));
}
__device__ __forceinline__ void mma16816h(float& d0, float& d1, float& d2, float& d3,
                                          uint32_t a0, uint32_t a1, uint32_t a2, uint32_t a3,
                                          uint32_t b0, uint32_t b1) {
    asm volatile("mma.sync.aligned.m16n8k16.row.col.f32.f16.f16.f32 "
                 "{%0,%1,%2,%3}, {%4,%5,%6,%7}, {%8,%9}, {%0,%1,%2,%3};"
                 : "+f"(d0), "+f"(d1), "+f"(d2), "+f"(d3)
                 : "r"(a0), "r"(a1), "r"(a2), "r"(a3), "r"(b0), "r"(b1));
}

__device__ __forceinline__ float gelu_exact(float x) {
    return 0.5f * x * (1.0f + erff(x * 0.70710678118654752f));
}

// swizzled 64B-row offset: row r, 16B chunk c (0..3)
__device__ __forceinline__ uint32_t swz(uint32_t r, uint32_t c) {
    return r * 64 + ((c ^ ((r >> 1) & 3)) << 4);
}

// pack 4 floats into bf16 hi/lo pairs (8B each)
__device__ __forceinline__ void split4(float o0, float o1, float o2, float o3,
                                       uint2& hv, uint2& lv) {
    __nv_bfloat162 h01 = __floats2bfloat162_rn(o0, o1);
    __nv_bfloat162 h23 = __floats2bfloat162_rn(o2, o3);
    float e0 = o0 - __bfloat162float(h01.x), e1 = o1 - __bfloat162float(h01.y);
    float e2 = o2 - __bfloat162float(h23.x), e3 = o3 - __bfloat162float(h23.y);
    __nv_bfloat162 l01 = __floats2bfloat162_rn(e0, e1);
    __nv_bfloat162 l23 = __floats2bfloat162_rn(e2, e3);
    hv = make_uint2(*(uint32_t*)&h01, *(uint32_t*)&h23);
    lv = make_uint2(*(uint32_t*)&l01, *(uint32_t*)&l23);
}

// ---------------- TM64 HMMA GEMM (bf16x3): CTA 64x128, BK=32, 4-stage ----------------
// 8 warps (2x4) of 32x32 tiles. MODE 0: fp32 + bias. MODE 1: gelu + bf16 hi/lo.
#define S64_AHI 0
#define S64_ALO 4096
#define S64_BHI 8192
#define S64_BLO 16384
#define STAGE64 24576
#define GEMM64_SMEM (4*STAGE64)

template<int MODE>
__global__ __launch_bounds__(256, 2)
void gemm_hmma64(const __nv_bfloat16* __restrict__ Ahi, const __nv_bfloat16* __restrict__ Alo,
                 const __nv_bfloat16* __restrict__ Bhi, const __nv_bfloat16* __restrict__ Blo,
                 const float* __restrict__ bias, float* __restrict__ C,
                 __nv_bfloat16* __restrict__ Chi, __nv_bfloat16* __restrict__ Clo,
                 int N, int K) {
    extern __shared__ char smem[];
    const uint32_t sb = smem_u32(smem);
    const int tid  = threadIdx.x;
    const int wid  = tid >> 5;
    const int lane = tid & 31;
    const int wrow = wid & 1;          // 32-row slab
    const int wcol = wid >> 1;         // 32-col slab
    const int bm = blockIdx.y << 6;
    const long bn = (long)blockIdx.x << 7;
    const int nc = K >> 5;

    const uint32_t rt = tid >> 2, ct = tid & 3;
    const uint32_t soA  = swz(rt, ct);
    const uint32_t soB1 = swz(rt + 64, ct);

    #define LOAD_STAGE64(kc, s) do {                                                   \
        uint32_t st_ = sb + (s) * STAGE64;                                              \
        size_t ga  = ((size_t)(bm + rt) * K + (kc) * 32 + ct * 8) * 2;                  \
        size_t gb0 = ((size_t)(bn + rt) * K + (kc) * 32 + ct * 8) * 2;                  \
        size_t gb1 = ((size_t)(bn + rt + 64) * K + (kc) * 32 + ct * 8) * 2;             \
        cp16(st_ + S64_AHI + soA,  (const char*)Ahi + ga);                              \
        cp16(st_ + S64_ALO + soA,  (const char*)Alo + ga);                              \
        cp16(st_ + S64_BHI + soA,  (const char*)Bhi + gb0);                             \
        cp16(st_ + S64_BLO + soA,  (const char*)Blo + gb0);                             \
        cp16(st_ + S64_BHI + soB1, (const char*)Bhi + gb1);                             \
        cp16(st_ + S64_BLO + soB1, (const char*)Blo + gb1);                             \
    } while (0)

    LOAD_STAGE64(0, 0); cp_commit();
    LOAD_STAGE64(1, 1); cp_commit();
    LOAD_STAGE64(2, 2); cp_commit();

    const int lane8 = lane & 7, sub = lane >> 3;
    const uint32_t ra = wrow * 32 + (sub & 1) * 8 + lane8;
    const uint32_t aks0 = swz(ra, (sub >> 1));
    const uint32_t aks1 = swz(ra, (sub >> 1) + 2);
    const uint32_t rb = wcol * 32 + lane8;
    const uint32_t boffs = swz(rb, sub);

    float acc[2][4][4];
    #pragma unroll
    for (int i = 0; i < 2; i++)
        #pragma unroll
        for (int j = 0; j < 4; j++)
            #pragma unroll
            for (int e = 0; e < 4; e++) acc[i][j][e] = 0.f;

    int slot = 0;
    for (int it = 0; it < nc; it++) {
        cp_wait<2>();
        __syncthreads();
        if (it + 3 < nc) {
            int ns = slot + 3; if (ns >= 4) ns -= 4;
            LOAD_STAGE64(it + 3, ns);
        }
        cp_commit();
        const uint32_t st = sb + slot * STAGE64;

        // front-load ALL fragments for this k-chunk
        uint32_t bh[4][4], bl[4][4], ah[2][2][4], al[2][2][4];
        #pragma unroll
        for (int nj = 0; nj < 4; nj++) {
            ldsm4(bh[nj][0], bh[nj][1], bh[nj][2], bh[nj][3], st + S64_BHI + boffs + nj * 512);
            ldsm4(bl[nj][0], bl[nj][1], bl[nj][2], bl[nj][3], st + S64_BLO + boffs + nj * 512);
        }
        #pragma unroll
        for (int mi = 0; mi < 2; mi++) {
            ldsm4(ah[0][mi][0], ah[0][mi][1], ah[0][mi][2], ah[0][mi][3],
                  st + S64_AHI + aks0 + mi * 1024);
            ldsm4(ah[1][mi][0], ah[1][mi][1], ah[1][mi][2], ah[1][mi][3],
                  st + S64_AHI + aks1 + mi * 1024);
            ldsm4(al[0][mi][0], al[0][mi][1], al[0][mi][2], al[0][mi][3],
                  st + S64_ALO + aks0 + mi * 1024);
            ldsm4(al[1][mi][0], al[1][mi][1], al[1][mi][2], al[1][mi][3],
                  st + S64_ALO + aks1 + mi * 1024);
        }
        #pragma unroll
        for (int ks = 0; ks < 2; ks++) {
            #pragma unroll
            for (int mi = 0; mi < 2; mi++)
                #pragma unroll
                for (int nj = 0; nj < 4; nj++)
                    mma16816(acc[mi][nj][0], acc[mi][nj][1], acc[mi][nj][2], acc[mi][nj][3],
                             ah[ks][mi][0], ah[ks][mi][1], ah[ks][mi][2], ah[ks][mi][3],
                             bh[nj][ks * 2], bh[nj][ks * 2 + 1]);
            #pragma unroll
            for (int mi = 0; mi < 2; mi++)
                #pragma unroll
                for (int nj = 0; nj < 4; nj++)
                    mma16816(acc[mi][nj][0], acc[mi][nj][1], acc[mi][nj][2], acc[mi][nj][3],
                             ah[ks][mi][0], ah[ks][mi][1], ah[ks][mi][2], ah[ks][mi][3],
                             bl[nj][ks * 2], bl[nj][ks * 2 + 1]);
            #pragma unroll
            for (int mi = 0; mi < 2; mi++)
                #pragma unroll
                for (int nj = 0; nj < 4; nj++)
                    mma16816(acc[mi][nj][0], acc[mi][nj][1], acc[mi][nj][2], acc[mi][nj][3],
                             al[ks][mi][0], al[ks][mi][1], al[ks][mi][2], al[ks][mi][3],
                             bh[nj][ks * 2], bh[nj][ks * 2 + 1]);
        }
        if (++slot == 4) slot = 0;
    }

    const int gr = lane >> 2;
    const int gc = (lane & 3) * 2;
    #pragma unroll
    for (int mi = 0; mi < 2; mi++) {
        size_t row0 = (size_t)(bm + wrow * 32 + mi * 16 + gr) * N;
        size_t row1 = row0 + (size_t)8 * N;
        #pragma unroll
        for (int nj = 0; nj < 4; nj++) {
            long c = bn + wcol * 32 + nj * 8 + gc;
            float b0 = bias[c], b1 = bias[c + 1];
            if (MODE == 0) {
                C[row0 + c]     = acc[mi][nj][0] + b0;
                C[row0 + c + 1] = acc[mi][nj][1] + b1;
                C[row1 + c]     = acc[mi][nj][2] + b0;
                C[row1 + c + 1] = acc[mi][nj][3] + b1;
            } else {
                float v0 = gelu_exact(acc[mi][nj][0] + b0);
                float v1 = gelu_exact(acc[mi][nj][1] + b1);
                float v2 = gelu_exact(acc[mi][nj][2] + b0);
                float v3 = gelu_exact(acc[mi][nj][3] + b1);
                __nv_bfloat162 hp0 = __floats2bfloat162_rn(v0, v1);
                __nv_bfloat162 hp1 = __floats2bfloat162_rn(v2, v3);
                float e0 = v0 - __bfloat162float(hp0.x), e1 = v1 - __bfloat162float(hp0.y);
                float e2 = v2 - __bfloat162float(hp1.x), e3 = v3 - __bfloat162float(hp1.y);
                __nv_bfloat162 lp0 = __floats2bfloat162_rn(e0, e1);
                __nv_bfloat162 lp1 = __floats2bfloat162_rn(e2, e3);
                *(uint32_t*)(Chi + row0 + c) = *(uint32_t*)&hp0;
                *(uint32_t*)(Clo + row0 + c) = *(uint32_t*)&lp0;
                *(uint32_t*)(Chi + row1 + c) = *(uint32_t*)&hp1;
                *(uint32_t*)(Clo + row1 + c) = *(uint32_t*)&lp1;
            }
        }
    }
    #undef LOAD_STAGE64
}

// ---------------- fp16 single-term GEMM (LM head), 4-stage ----------------
#define F_TA 0
#define F_TB 8192
#define F_STAGE 16384
#define F16_SMEM (4*F_STAGE)

__global__ __launch_bounds__(256, 2)
void gemm_f16(const __half* __restrict__ A, const __half* __restrict__ B,
              const float* __restrict__ bias, float* __restrict__ C, int N, int K) {
    extern __shared__ char smem[];
    const uint32_t sb = smem_u32(smem);
    const int tid  = threadIdx.x;
    const int wid  = tid >> 5;
    const int lane = tid & 31;
    const int wrow = wid & 1;
    const int wcol = wid >> 1;
    const int bm = blockIdx.x << 7;
    const long bn = (long)blockIdx.y << 7;
    const int nc = K >> 5;

    const uint32_t r0t = tid >> 2, c0t = tid & 3;
    const uint32_t r1t = r0t + 64;
    const uint32_t so0 = swz(r0t, c0t);
    const uint32_t so1 = swz(r1t, c0t);

    #define LOAD_STAGE_F(kc, s) do {                                                   \
        uint32_t st_ = sb + (s) * F_STAGE;                                              \
        {                                                                               \
            size_t ga = ((size_t)(bm + r0t) * K + (kc) * 32 + c0t * 8) * 2;             \
            size_t gb = ((size_t)(bn + r0t) * K + (kc) * 32 + c0t * 8) * 2;             \
            cp16(st_ + F_TA + so0, (const char*)A + ga);                                \
            cp16(st_ + F_TB + so0, (const char*)B + gb);                                \
        }                                                                               \
        {                                                                               \
            size_t ga = ((size_t)(bm + r1t) * K + (kc) * 32 + c0t * 8) * 2;             \
            size_t gb = ((size_t)(bn + r1t) * K + (kc) * 32 + c0t * 8) * 2;             \
            cp16(st_ + F_TA + so1, (const char*)A + ga);                                \
            cp16(st_ + F_TB + so1, (const char*)B + gb);                                \
        }                                                                               \
    } while (0)

    LOAD_STAGE_F(0, 0); cp_commit();
    LOAD_STAGE_F(1, 1); cp_commit();
    LOAD_STAGE_F(2, 2); cp_commit();

    const int lane8 = lane & 7, sub = lane >> 3;
    const uint32_t ra = wrow * 64 + (sub & 1) * 8 + lane8;
    const uint32_t aks0 = swz(ra, (sub >> 1));
    const uint32_t aks1 = swz(ra, (sub >> 1) + 2);
    const uint32_t rb = wcol * 32 + lane8;
    const uint32_t boffs = swz(rb, sub);

    float acc[4][4][4];
    #pragma unroll
    for (int i = 0; i < 4; i++)
        #pragma unroll
        for (int j = 0; j < 4; j++)
            #pragma unroll
            for (int e = 0; e < 4; e++) acc[i][j][e] = 0.f;

    int slot = 0;
    for (int it = 0; it < nc; it++) {
        cp_wait<2>();
        __syncthreads();
        if (it + 3 < nc) {
            int ns = slot + 3; if (ns >= 4) ns -= 4;
            LOAD_STAGE_F(it + 3, ns);
        }
        cp_commit();
        const uint32_t st = sb + slot * F_STAGE;

        uint32_t bf[4][4];
        #pragma unroll
        for (int nj = 0; nj < 4; nj++)
            ldsm4(bf[nj][0], bf[nj][1], bf[nj][2], bf[nj][3], st + F_TB + boffs + nj * 512);
        #pragma unroll
        for (int ks = 0; ks < 2; ks++) {
            const uint32_t ao = (ks == 0) ? aks0 : aks1;
            uint32_t a[4][4];
            #pragma unroll
            for (int mi = 0; mi < 4; mi++)
                ldsm4(a[mi][0], a[mi][1], a[mi][2], a[mi][3], st + F_TA + ao + mi * 1024);
            #pragma unroll
            for (int mi = 0; mi < 4; mi++)
                #pragma unroll
                for (int nj = 0; nj < 4; nj++)
                    mma16816h(acc[mi][nj][0], acc[mi][nj][1], acc[mi][nj][2], acc[mi][nj][3],
                              a[mi][0], a[mi][1], a[mi][2], a[mi][3],
                              bf[nj][ks * 2], bf[nj][ks * 2 + 1]);
        }
        if (++slot == 4) slot = 0;
    }

    const int gr = lane >> 2;
    const int gc = (lane & 3) * 2;
    #pragma unroll
    for (int mi = 0; mi < 4; mi++) {
        size_t row0 = (size_t)(bm + wrow * 64 + mi * 16 + gr) * N;
        size_t row1 = row0 + (size_t)8 * N;
        #pragma unroll
        for (int nj = 0; nj < 4; nj++) {
            long c = bn + wcol * 32 + nj * 8 + gc;
            if (c < N) {
                C[row0 + c] = acc[mi][nj][0] + bias[c];
                C[row1 + c] = acc[mi][nj][2] + bias[c];
            }
            if (c + 1 < N) {
                C[row0 + c + 1] = acc[mi][nj][1] + bias[c + 1];
                C[row1 + c + 1] = acc[mi][nj][3] + bias[c + 1];
            }
        }
    }
    #undef LOAD_STAGE_F
}

// ---------------- weight transpose + split (bf16 hi/lo) ----------------
template<int QKV>
__global__ __launch_bounds__(256)
void transpose_split(const float* __restrict__ src0, const float* __restrict__ src1,
                     const float* __restrict__ src2,
                     __nv_bfloat16* __restrict__ hi, __nv_bfloat16* __restrict__ lo,
                     int R, int C) {
    __shared__ float t[128][33];
    int z = blockIdx.z;
    const float* src = src0;
    int sel = 0;
    if (QKV) {
        sel = z / (NLAYERS * NH);
        z   = z % (NLAYERS * NH);
        src = (sel == 0) ? src0 : (sel == 1) ? src1 : src2;
    }
    const size_t ib = (size_t)z * R * C;
    size_t ob;
    if (QKV) ob = (size_t)(z >> 4) * (3072 * 1024) + (size_t)sel * (1024 * 1024)
                + (size_t)(z & 15) * (64 * 1024);
    else     ob = ib;
    const int r0 = blockIdx.y * 128, c0 = blockIdx.x * 32;
    const int cc = threadIdx.x & 31, rb = threadIdx.x >> 5;
    const bool cok = (c0 + cc) < C;
    #pragma unroll
    for (int p = 0; p < 16; p++) {
        int rr = rb + p * 8;
        t[rr][cc] = cok ? src[ib + (size_t)(r0 + rr) * C + c0 + cc] : 0.f;
    }
    __syncthreads();
    const int oc = threadIdx.x >> 3, rq8 = threadIdx.x & 7;
    if (c0 + oc < C) {
        size_t obase = ob + (size_t)(c0 + oc) * R + r0;
        #pragma unroll
        for (int p = 0; p < 4; p++) {
            int r = (rq8 + p * 8) * 4;
            uint2 hv, lv;
            split4(t[r][oc], t[r + 1][oc], t[r + 2][oc], t[r + 3][oc], hv, lv);
            *(uint2*)(hi + obase + r) = hv;
            *(uint2*)(lo + obase + r) = lv;
        }
    }
}

// ---------------- fp16 weight transpose (LM head) ----------------
__global__ __launch_bounds__(256)
void transpose_f16(const float* __restrict__ src, __half* __restrict__ out, int R, int C) {
    __shared__ float t[128][33];
    const int r0 = blockIdx.y * 128, c0 = blockIdx.x * 32;
    const int cc = threadIdx.x & 31, rb = threadIdx.x >> 5;
    const bool cok = (c0 + cc) < C;
    #pragma unroll
    for (int p = 0; p < 16; p++) {
        int rr = rb + p * 8;
        t[rr][cc] = cok ? src[(size_t)(r0 + rr) * C + c0 + cc] : 0.f;
    }
    __syncthreads();
    const int oc = threadIdx.x >> 3, rq8 = threadIdx.x & 7;
    if (c0 + oc < C) {
        size_t obase = (size_t)(c0 + oc) * R + r0;
        #pragma unroll
        for (int p = 0; p < 4; p++) {
            int r = (rq8 + p * 8) * 4;
            __half2 h0 = __floats2half2_rn(t[r][oc], t[r + 1][oc]);
            __half2 h1 = __floats2half2_rn(t[r + 2][oc], t[r + 3][oc]);
            *(uint2*)(out + obase + r) = make_uint2(*(uint32_t*)&h0, *(uint32_t*)&h1);
        }
    }
}

// ---------------- embedding: x = emb[tok] + pos, + split ----------------
__global__ void embed_kernel(const int* __restrict__ tok, const float* __restrict__ emb,
                             const float* __restrict__ pos, float* __restrict__ x,
                             __nv_bfloat16* __restrict__ hi, __nv_bfloat16* __restrict__ lo) {
    int i4 = blockIdx.x * 256 + threadIdx.x;
    int e = i4 * 4;
    int s = e >> 10, h = e & 1023;
    float4 ev = *(const float4*)(emb + (size_t)tok[s] * H + h);
    float4 pv = *(const float4*)(pos + e);
    float o0 = ev.x + pv.x, o1 = ev.y + pv.y, o2 = ev.z + pv.z, o3 = ev.w + pv.w;
    *(float4*)(x + e) = make_float4(o0, o1, o2, o3);
    uint2 hv, lv;
    split4(o0, o1, o2, o3, hv, lv);
    *(uint2*)(hi + e) = hv;
    *(uint2*)(lo + e) = lv;
}

// ---------------- M_part = K^T V per (head, seg); 8 segs ----------------
__global__ __launch_bounds__(256)
void ktv_kernel(const float* __restrict__ qkv, float* __restrict__ mp) {
    const int head = blockIdx.x & 15, seg = blockIdx.x >> 4;   // seg 0..7
    __shared__ float Ks[64][65];
    __shared__ float Vs[64][65];
    const int tid = threadIdx.x;
    const int tr = tid >> 4, tc = tid & 15;
    float acc[4][4] = {};
    for (int t0 = seg * 256; t0 < seg * 256 + 256; t0 += 64) {
        for (int i = tid; i < 4096; i += 256) {
            int r = i >> 6, c = i & 63;
            size_t base = (size_t)(t0 + r) * 3072 + head * DH + c;
            Ks[r][c] = qkv[base + 1024];
            Vs[r][c] = qkv[base + 2048];
        }
        __syncthreads();
        #pragma unroll 4
        for (int t = 0; t < 64; t++) {
            float a[4], b[4];
            #pragma unroll
            for (int i = 0; i < 4; i++) a[i] = Ks[t][tr * 4 + i];
            #pragma unroll
            for (int j = 0; j < 4; j++) b[j] = Vs[t][tc * 4 + j];
            #pragma unroll
            for (int i = 0; i < 4; i++)
                #pragma unroll
                for (int j = 0; j < 4; j++)
                    acc[i][j] = fmaf(a[i], b[j], acc[i][j]);
        }
        __syncthreads();
    }
    #pragma unroll
    for (int i = 0; i < 4; i++)
        #pragma unroll
        for (int j = 0; j < 4; j++)
            mp[(size_t)(seg * 16 + head) * 4096 + (tr * 4 + i) * 64 + tc * 4 + j] = acc[i][j];
}

// ---------------- parallel suffix sum of V over S ----------------
__global__ void suf_partial(const float* __restrict__ qkv, float* __restrict__ part) {
    int col = blockIdx.y * 256 + threadIdx.x;
    int seg = blockIdx.x;
    float s = 0.f;
    for (int t = seg * 128; t < seg * 128 + 128; t++)
        s += qkv[(size_t)t * 3072 + 2048 + col];
    part[seg * 1024 + col] = s;
}
__global__ void suf_apply(const float* __restrict__ qkv, const float* __restrict__ part,
                          float* __restrict__ suf) {
    int col = blockIdx.y * 256 + threadIdx.x;
    int seg = blockIdx.x;
    float run = 0.f;
    for (int s2 = seg + 1; s2 < 16; s2++) run += part[s2 * 1024 + col];
    for (int t = seg * 128 + 127; t >= seg * 128; t--) {
        suf[(size_t)t * 1024 + col] = run;
        run += qkv[(size_t)t * 3072 + 2048 + col];
    }
}

// ---------------- attn = scale*(Q@M) - 1e9*suf, emit hi/lo split ----------------
__global__ __launch_bounds__(256)
void attn_combine(const float* __restrict__ qkv, const float* __restrict__ mp,
                  const float* __restrict__ suf,
                  __nv_bfloat16* __restrict__ ahi, __nv_bfloat16* __restrict__ alo) {
    const int head = blockIdx.y;
    const int s0 = blockIdx.x * 64;
    __shared__ float Qs[64][65];
    __shared__ float Ms[64][65];
    const int tid = threadIdx.x;
    for (int i = tid; i < 4096; i += 256) {
        int r = i >> 6, c = i & 63;
        Qs[r][c] = qkv[(size_t)(s0 + r) * 3072 + head * DH + c];
        float mv = 0.f;
        #pragma unroll
        for (int sg = 0; sg < 8; sg++) mv += mp[(size_t)(sg * 16 + head) * 4096 + i];
        Ms[r][c] = mv;
    }
    __syncthreads();
    const int tr = tid >> 4, tc = tid & 15;
    float acc[4][4] = {};
    #pragma unroll 4
    for (int hp = 0; hp < 64; hp++) {
        float a[4], b[4];
        #pragma unroll
        for (int i = 0; i < 4; i++) a[i] = Qs[tr * 4 + i][hp];
        #pragma unroll
        for (int j = 0; j < 4; j++) b[j] = Ms[hp][tc * 4 + j];
        #pragma unroll
        for (int i = 0; i < 4; i++)
            #pragma unroll
            for (int j = 0; j < 4; j++)
                acc[i][j] = fmaf(a[i], b[j], acc[i][j]);
    }
    #pragma unroll
    for (int i = 0; i < 4; i++) {
        int s = s0 + tr * 4 + i;
        size_t sb = (size_t)s * 1024 + head * DH + tc * 4;
        float o[4];
        #pragma unroll
        for (int j = 0; j < 4; j++)
            o[j] = 0.125f * acc[i][j] - 1e9f * suf[sb + j];
        uint2 hv, lv;
        split4(o[0], o[1], o[2], o[3], hv, lv);
        *(uint2*)(ahi + sb) = hv;
        *(uint2*)(alo + sb) = lv;
    }
}

// ---------------- LayerNorm (+residual) + fused split ----------------
template<bool ADD, bool WF32, int OUTK>
__global__ __launch_bounds__(256)
void ln_kernel(const float* __restrict__ t, const float* __restrict__ xin,
               const float* __restrict__ g, const float* __restrict__ b,
               float* __restrict__ outf,
               __nv_bfloat16* __restrict__ hi, __nv_bfloat16* __restrict__ lo,
               __half* __restrict__ outh) {
    const int row = blockIdx.x;
    const int tid = threadIdx.x;
    float4 v = *(const float4*)(t + (size_t)row * H + tid * 4);
    __shared__ float red[256];
    __shared__ float stat[2];

    float s = v.x + v.y + v.z + v.w;
    red[tid] = s; __syncthreads();
    for (int o = 128; o > 0; o >>= 1) {
        if (tid < o) red[tid] += red[tid + o];
        __syncthreads();
    }
    if (tid == 0) stat[0] = red[0] * (1.0f / H);
    __syncthreads();
    float mean = stat[0];

    float dx = v.x - mean, dy = v.y - mean, dz = v.z - mean, dw = v.w - mean;
    red[tid] = dx * dx + dy * dy + dz * dz + dw * dw; __syncthreads();
    for (int o = 128; o > 0; o >>= 1) {
        if (tid < o) red[tid] += red[tid + o];
        __syncthreads();
    }
    if (tid == 0) stat[1] = rsqrtf(red[0] * (1.0f / H) + 1e-5f);
    __syncthreads();
    float rstd = stat[1];

    int h = tid * 4;
    float4 gv = *(const float4*)(g + h);
    float4 bv = *(const float4*)(b + h);
    float o0 = dx * rstd * gv.x + bv.x;
    float o1 = dy * rstd * gv.y + bv.y;
    float o2 = dz * rstd * gv.z + bv.z;
    float o3 = dw * rstd * gv.w + bv.w;
    if (ADD) {
        float4 xv = *(const float4*)(xin + (size_t)row * H + h);
        o0 += xv.x; o1 += xv.y; o2 += xv.z; o3 += xv.w;
    }
    if (WF32) *(float4*)(outf + (size_t)row * H + h) = make_float4(o0, o1, o2, o3);
    if (OUTK == 0) {
        uint2 hv, lv;
        split4(o0, o1, o2, o3, hv, lv);
        *(uint2*)(hi + (size_t)row * H + h) = hv;
        *(uint2*)(lo + (size_t)row * H + h) = lv;
    } else {
        __half2 h0 = __floats2half2_rn(o0, o1);
        __half2 h1 = __floats2half2_rn(o2, o3);
        *(uint2*)(outh + (size_t)row * H + h) = make_uint2(*(uint32_t*)&h0, *(uint32_t*)&h1);
    }
}

// ---------------- launch ----------------
extern "C" void kernel_launch(void* const* d_in, const int* in_sizes, int n_in,
                              void* d_out, int out_size) {
    const int*   tokens = (const int*)  d_in[0];
    const float* emb    = (const float*)d_in[1];
    const float* pos    = (const float*)d_in[2];
    const float* Wq     = (const float*)d_in[3];
    const float* Wk     = (const float*)d_in[4];
    const float* Wv     = (const float*)d_in[5];
    const float* Wp     = (const float*)d_in[6];
    const float* bp     = (const float*)d_in[7];
    const float* W1     = (const float*)d_in[8];
    const float* b1     = (const float*)d_in[9];
    const float* W2     = (const float*)d_in[10];
    const float* b2     = (const float*)d_in[11];
    const float* ln_g   = (const float*)d_in[12];
    const float* ln_b   = (const float*)d_in[13];
    const float* Wlm    = (const float*)d_in[14];
    const float* blm    = (const float*)d_in[15];
    float* out = (float*)d_out;
    const int Vv = in_sizes[15];

    float *x, *tmp, *res, *qkv, *suf, *m, *part, *zb;
    __nv_bfloat16 *ahi, *alo, *bhi, *blo;
    __nv_bfloat16 *btqkv_hi, *btqkv_lo, *btp_hi, *btp_lo;
    __nv_bfloat16 *bt1_hi, *bt1_lo, *bt2_hi, *bt2_lo;
    __half *wlm, *xf16;
    cudaGetSymbolAddress((void**)&x, g_x);       cudaGetSymbolAddress((void**)&tmp, g_tmp);
    cudaGetSymbolAddress((void**)&res, g_res);   cudaGetSymbolAddress((void**)&qkv, g_qkv);
    cudaGetSymbolAddress((void**)&suf, g_suf);   cudaGetSymbolAddress((void**)&m, g_m);
    cudaGetSymbolAddress((void**)&part, g_part); cudaGetSymbolAddress((void**)&zb, g_zb);
    cudaGetSymbolAddress((void**)&ahi, g_ahi);   cudaGetSymbolAddress((void**)&alo, g_alo);
    cudaGetSymbolAddress((void**)&bhi, g_bhi);   cudaGetSymbolAddress((void**)&blo, g_blo);
    cudaGetSymbolAddress((void**)&btqkv_hi, g_btqkv_hi);
    cudaGetSymbolAddress((void**)&btqkv_lo, g_btqkv_lo);
    cudaGetSymbolAddress((void**)&btp_hi, g_btp_hi); cudaGetSymbolAddress((void**)&btp_lo, g_btp_lo);
    cudaGetSymbolAddress((void**)&bt1_hi, g_bt1_hi); cudaGetSymbolAddress((void**)&bt1_lo, g_bt1_lo);
    cudaGetSymbolAddress((void**)&bt2_hi, g_bt2_hi); cudaGetSymbolAddress((void**)&bt2_lo, g_bt2_lo);
    cudaGetSymbolAddress((void**)&wlm, g_wlm_f16);   cudaGetSymbolAddress((void**)&xf16, g_xf_f16);

    cudaFuncSetAttribute(gemm_hmma64<0>, cudaFuncAttributeMaxDynamicSharedMemorySize, GEMM64_SMEM);
    cudaFuncSetAttribute(gemm_hmma64<1>, cudaFuncAttributeMaxDynamicSharedMemorySize, GEMM64_SMEM);
    cudaFuncSetAttribute(gemm_f16, cudaFuncAttributeMaxDynamicSharedMemorySize, F16_SMEM);

    dim3 tb(256);
    // idx0: embed
    embed_kernel<<<(S * H) / 1024, 256>>>(tokens, emb, pos, x, ahi, alo);
    // idx1: combined qkv weight transpose
    transpose_split<1><<<dim3(2, 8, 3 * NLAYERS * NH), tb>>>(Wq, Wk, Wv,
                                                             btqkv_hi, btqkv_lo, H, DH);
    // idx2: proj weights
    transpose_split<0><<<dim3(32, 8, NLAYERS), tb>>>(Wp, nullptr, nullptr,
                                                     btp_hi, btp_lo, H, H);
    // idx3: QKV GEMM layer 0 (profile target)
    gemm_hmma64<0><<<dim3(24, 32), 256, GEMM64_SMEM>>>(ahi, alo, btqkv_hi, btqkv_lo,
                                                       zb, qkv, nullptr, nullptr, 3072, H);
    // remaining weight transposes
    transpose_split<0><<<dim3(128, 8, NLAYERS), tb>>>(W1, nullptr, nullptr, bt1_hi, bt1_lo, H, FF);
    transpose_split<0><<<dim3(32, 32, NLAYERS), tb>>>(W2, nullptr, nullptr, bt2_hi, bt2_lo, FF, H);
    transpose_f16<<<dim3((Vv + 31) / 32, 8), tb>>>(Wlm, wlm, H, Vv);

    for (int l = 0; l < NLAYERS; l++) {
        size_t oQ = (size_t)l * 3072 * H;
        size_t oH = (size_t)l * H * H;
        size_t oF = (size_t)l * H * FF;

        if (l > 0)
            gemm_hmma64<0><<<dim3(24, 32), 256, GEMM64_SMEM>>>(ahi, alo, btqkv_hi + oQ, btqkv_lo + oQ,
                                                               zb, qkv, nullptr, nullptr, 3072, H);
        ktv_kernel<<<128, 256>>>(qkv, m);
        suf_partial<<<dim3(16, 4), 256>>>(qkv, part);
        suf_apply<<<dim3(16, 4), 256>>>(qkv, part, suf);
        attn_combine<<<dim3(S / 64, NH), 256>>>(qkv, m, suf, ahi, alo);

        gemm_hmma64<0><<<dim3(8, 32), 256, GEMM64_SMEM>>>(ahi, alo, btp_hi + oH, btp_lo + oH,
                                                          bp + (size_t)l * H, tmp, nullptr, nullptr, H, H);
        ln_kernel<true, true, 0><<<S, 256>>>(tmp, x, ln_g, ln_b, res, ahi, alo, nullptr);

        gemm_hmma64<1><<<dim3(32, 32), 256, GEMM64_SMEM>>>(ahi, alo, bt1_hi + oF, bt1_lo + oF,
                                                           b1 + (size_t)l * FF, nullptr, bhi, blo, FF, H);
        gemm_hmma64<0><<<dim3(8, 32), 256, GEMM64_SMEM>>>(bhi, blo, bt2_hi + oF, bt2_lo + oF,
                                                          b2 + (size_t)l * H, tmp, nullptr, nullptr, H, FF);
        ln_kernel<true, true, 0><<<S, 256>>>(tmp, res, ln_g, ln_b, x, ahi, alo, nullptr);
    }

    // final LN -> fp16, LM head in fp16 HMMA
    ln_kernel<false, false, 1><<<S, 256>>>(x, nullptr, ln_g, ln_b, nullptr, nullptr, nullptr, xf16);
    gemm_f16<<<dim3(16, VPAD / 128), 256, F16_SMEM>>>(xf16, wlm, blm, out, Vv, H);
}